// round 2
// baseline (speedup 1.0000x reference)
#include <cuda_runtime.h>
#include <cuda_bf16.h>
#include <math.h>

// Problem constants
#define B_  16
#define C_  64
#define H_  192
#define W_  192
#define H2_ 64
#define W2_ 64
#define S_  5

// ---------------------------------------------------------------------------
// Scratch buffers (static device globals; no allocation allowed)
// ---------------------------------------------------------------------------
__device__ float g_q[B_ * C_ * H2_ * W2_];        // (16,64,64,64)
__device__ float g_k[B_ * C_ * H2_ * W2_];        // (16,64,64,64)
__device__ float g_attn[B_ * C_ * C_ * S_ * S_];  // (16,64,64,5,5) [b][co(k-ch)][ci(q-ch)][i][j]
__device__ float g_ak[B_ * C_ * C_ * 9];          // (16,64,64,3,3) transposed ak (pre-norm)
__device__ float g_kern[B_ * C_ * C_ * 9];        // final dynamic kernels

union F2U {
    float2 f;
    unsigned long long u;
};

// ---------------------------------------------------------------------------
// Kernel A: qk conv, stride 3, VALID. Non-overlapping 3x3 patches.
// grid (16 tiles, 8 oc-groups, 16 b), block 64 threads (8x8), each thread 2x2 px,
// 16 output channels per block, ci chunked by 4.
// q/k are NOT normalized (scale cancels after ak normalization).
// ---------------------------------------------------------------------------
__global__ void __launch_bounds__(64) qk_conv_kernel(const float* __restrict__ x,
                                                     const float* __restrict__ w_qk) {
    const int tileI = blockIdx.x >> 2;
    const int tileJ = blockIdx.x & 3;
    const int ocg   = blockIdx.y;   // 0..7, 16 oc each (128 total)
    const int b     = blockIdx.z;

    const int tid = threadIdx.x;
    const int thx = tid & 7;
    const int thy = tid >> 3;

    __shared__ float xs[4][48][48];     // 36.9 KB
    __shared__ float ws[16][4][9];      // 2.3 KB

    float acc[16][4];
#pragma unroll
    for (int oc = 0; oc < 16; ++oc)
#pragma unroll
        for (int p = 0; p < 4; ++p) acc[oc][p] = 0.f;

    const int row0 = tileI * 48;  // = 3 * tileI*16
    const int col0 = tileJ * 48;

    for (int cic = 0; cic < 16; ++cic) {
        const int ci0 = cic * 4;
        __syncthreads();
        // load weights: 16oc x 4ci x 9 = 576
        for (int t = tid; t < 576; t += 64) {
            int oc = t / 36;
            int rr = t % 36;
            int ci = rr / 9;
            int tp = rr % 9;
            ws[oc][ci][tp] = w_qk[((ocg * 16 + oc) * C_ + ci0 + ci) * 9 + tp];
        }
        // load x region: 4ci x 48 x 48
        for (int t = tid; t < 4 * 48 * 48; t += 64) {
            int ci = t / 2304;
            int rr = t % 2304;
            int r = rr / 48;
            int c = rr % 48;
            xs[ci][r][c] = x[((b * C_ + ci0 + ci) * H_ + row0 + r) * W_ + col0 + c];
        }
        __syncthreads();

#pragma unroll
        for (int ci = 0; ci < 4; ++ci) {
            float xv[4][9];
#pragma unroll
            for (int py = 0; py < 2; ++py)
#pragma unroll
                for (int px = 0; px < 2; ++px)
#pragma unroll
                    for (int dy = 0; dy < 3; ++dy)
#pragma unroll
                        for (int dx = 0; dx < 3; ++dx)
                            xv[py * 2 + px][dy * 3 + dx] =
                                xs[ci][thy * 6 + py * 3 + dy][thx * 6 + px * 3 + dx];
#pragma unroll
            for (int oc = 0; oc < 16; ++oc) {
#pragma unroll
                for (int t9 = 0; t9 < 9; ++t9) {
                    float wv = ws[oc][ci][t9];
                    acc[oc][0] = fmaf(xv[0][t9], wv, acc[oc][0]);
                    acc[oc][1] = fmaf(xv[1][t9], wv, acc[oc][1]);
                    acc[oc][2] = fmaf(xv[2][t9], wv, acc[oc][2]);
                    acc[oc][3] = fmaf(xv[3][t9], wv, acc[oc][3]);
                }
            }
        }
    }

    // write out
#pragma unroll
    for (int oc = 0; oc < 16; ++oc) {
        int ocglob = ocg * 16 + oc;
        float* dst = (ocglob < 64) ? g_q : g_k;
        int c = ocglob & 63;
#pragma unroll
        for (int py = 0; py < 2; ++py)
#pragma unroll
            for (int px = 0; px < 2; ++px) {
                int i = tileI * 16 + thy * 2 + py;
                int j = tileJ * 16 + thx * 2 + px;
                dst[((b * C_ + c) * H2_ + i) * W2_ + j] = acc[oc][py * 2 + px];
            }
    }
}

// ---------------------------------------------------------------------------
// Kernel B: attn[b,co,ci,i,j] = sum_{h,w valid} q[b,ci,h+i-2,w+j-2] * k[b,co,h,w]
// grid (5,5,16), block 128. Thread tile 4co x 8ci. SMEM transposed [w][ch].
// ---------------------------------------------------------------------------
__global__ void __launch_bounds__(128) attn_kernel() {
    const int j = blockIdx.x;
    const int i = blockIdx.y;
    const int b = blockIdx.z;
    const int di = i - 2;
    const int dj = j - 2;

    const int tid = threadIdx.x;
    const int tco = tid & 15;  // co base = tco*4
    const int tci = tid >> 4;  // ci base = tci*8

    __shared__ float qs[64][68];
    __shared__ float ks[64][68];

    float acc[4][8];
#pragma unroll
    for (int a = 0; a < 4; ++a)
#pragma unroll
        for (int c = 0; c < 8; ++c) acc[a][c] = 0.f;

    const int h0 = max(0, -di), h1 = min(64, 64 - di);
    const float* __restrict__ qb = g_q + b * C_ * 4096;
    const float* __restrict__ kb = g_k + b * C_ * 4096;

    for (int h = h0; h < h1; ++h) {
        __syncthreads();
        for (int t = tid; t < 4096; t += 128) {
            int ch = t >> 6;
            int w  = t & 63;
            int wq = w + dj;
            float qv = 0.f;
            if ((unsigned)wq < 64u) qv = qb[ch * 4096 + (h + di) * 64 + wq];
            qs[w][ch] = qv;
            ks[w][ch] = kb[ch * 4096 + h * 64 + w];
        }
        __syncthreads();

#pragma unroll 4
        for (int w = 0; w < 64; ++w) {
            float4 kv  = *(const float4*)&ks[w][tco * 4];
            float4 qa  = *(const float4*)&qs[w][tci * 8];
            float4 qb4 = *(const float4*)&qs[w][tci * 8 + 4];
            float kr[4] = {kv.x, kv.y, kv.z, kv.w};
            float qr[8] = {qa.x, qa.y, qa.z, qa.w, qb4.x, qb4.y, qb4.z, qb4.w};
#pragma unroll
            for (int a = 0; a < 4; ++a)
#pragma unroll
                for (int c = 0; c < 8; ++c)
                    acc[a][c] = fmaf(kr[a], qr[c], acc[a][c]);
        }
    }

#pragma unroll
    for (int a = 0; a < 4; ++a)
#pragma unroll
        for (int c = 0; c < 8; ++c) {
            int co = tco * 4 + a;
            int ci = tci * 8 + c;
            g_attn[((b * 64 + co) * 64 + ci) * 25 + i * 5 + j] = acc[a][c];
        }
}

// ---------------------------------------------------------------------------
// Kernel C1: ak conv (VALID 3x3 over 5x5 attn maps), already transposed:
//   g_ak[b][cB][cA][ky*3+kx] = sum_{ci,dy,dx} attn[b][cA][ci][ky+dy][kx+dx] * weight[cB][ci][dy][dx]
// grid (64 cA, 16 b), block 64 (thread = cB).
// ---------------------------------------------------------------------------
__global__ void __launch_bounds__(64) akconv_kernel(const float* __restrict__ weight) {
    const int cA = blockIdx.x;
    const int b  = blockIdx.y;
    const int cB = threadIdx.x;

    __shared__ float as_[64][25];
    __shared__ float ws[64][73];

    for (int t = cB; t < 1600; t += 64)
        as_[t / 25][t % 25] = g_attn[(b * 64 + cA) * 1600 + t];

    float acc[9];
#pragma unroll
    for (int t9 = 0; t9 < 9; ++t9) acc[t9] = 0.f;

    for (int cic = 0; cic < 8; ++cic) {
        __syncthreads();
        for (int t = cB; t < 4608; t += 64) {
            int c2 = t / 72;
            int rr = t % 72;
            ws[c2][rr] = weight[c2 * 576 + (cic * 8 + rr / 9) * 9 + (rr % 9)];
        }
        __syncthreads();
#pragma unroll
        for (int ci = 0; ci < 8; ++ci) {
            float av[25];
#pragma unroll
            for (int p = 0; p < 25; ++p) av[p] = as_[cic * 8 + ci][p];
#pragma unroll
            for (int dy = 0; dy < 3; ++dy)
#pragma unroll
                for (int dx = 0; dx < 3; ++dx) {
                    float wv = ws[cB][ci * 9 + dy * 3 + dx];
#pragma unroll
                    for (int ky = 0; ky < 3; ++ky)
#pragma unroll
                        for (int kx = 0; kx < 3; ++kx)
                            acc[ky * 3 + kx] =
                                fmaf(av[(ky + dy) * 5 + (kx + dx)], wv, acc[ky * 3 + kx]);
                }
        }
    }
#pragma unroll
    for (int t9 = 0; t9 < 9; ++t9)
        g_ak[((b * 64 + cB) * 64 + cA) * 9 + t9] = acc[t9];
}

// ---------------------------------------------------------------------------
// Kernel C2: per-(b,cB) L2 normalize ak over (cA,3,3), then
//   kern[b,cB,cA,t] = weight[cB,cA,t] + ak_n * temperature
// grid (64 cB, 16 b), block 64 (thread = cA).
// ---------------------------------------------------------------------------
__global__ void __launch_bounds__(64) kern_kernel(const float* __restrict__ weight,
                                                  const float* __restrict__ temperature) {
    const int cB  = blockIdx.x;
    const int b   = blockIdx.y;
    const int tid = threadIdx.x;  // = cA

    const float* ak = g_ak + (b * 64 + cB) * 64 * 9;
    float v[9];
    float ss = 0.f;
#pragma unroll
    for (int t9 = 0; t9 < 9; ++t9) {
        v[t9] = ak[tid * 9 + t9];
        ss = fmaf(v[t9], v[t9], ss);
    }

    __shared__ float red[64];
    red[tid] = ss;
    __syncthreads();
#pragma unroll
    for (int s = 32; s >= 1; s >>= 1) {
        if (tid < s) red[tid] += red[tid + s];
        __syncthreads();
    }
    float nrm = sqrtf(red[0]);
    float scale = temperature[0] / fmaxf(nrm, 1e-12f);

#pragma unroll
    for (int t9 = 0; t9 < 9; ++t9)
        g_kern[((b * 64 + cB) * 64 + tid) * 9 + t9] =
            weight[(cB * 64 + tid) * 9 + t9] + v[t9] * scale;
}

// ---------------------------------------------------------------------------
// Kernel D: final per-sample 3x3 conv (pad 1) + ReLU, packed f32x2 FMA.
// grid (36 tiles, 8 oc-groups, 16 b), block 128 (16x x 8y), thread 2x-pair x 4y
// x 8oc. ci chunked by 8; kernel values duplicated into float2 at smem fill.
// ---------------------------------------------------------------------------
__global__ void __launch_bounds__(128) final_conv_kernel(const float* __restrict__ x,
                                                         float* __restrict__ out) {
    const int tY  = blockIdx.x / 6;
    const int tX  = blockIdx.x % 6;
    const int ocg = blockIdx.y;  // 8 groups of 8 oc
    const int b   = blockIdx.z;

    const int tid = threadIdx.x;
    const int tx = tid & 15;   // 0..15 -> x pair base tx*2
    const int ty = tid >> 4;   // 0..7  -> y base ty*4

    __shared__ float  xs[8][34][34];   // 37.0 KB
    __shared__ float2 ks2[8][8][9];    //  4.6 KB

    F2U acc[4][8];
#pragma unroll
    for (int yy = 0; yy < 4; ++yy)
#pragma unroll
        for (int oc = 0; oc < 8; ++oc) acc[yy][oc].u = 0ull;

    for (int cic = 0; cic < 8; ++cic) {
        __syncthreads();
        // dynamic kernel chunk, duplicated into both f32x2 lanes
        for (int t = tid; t < 576; t += 128) {
            int oc = t / 72;
            int rr = t % 72;
            float v = g_kern[((b * 64 + ocg * 8 + oc) * 64 + cic * 8 + rr / 9) * 9 + (rr % 9)];
            ks2[oc][rr / 9][rr % 9] = make_float2(v, v);
        }
        // x tile with halo
        for (int t = tid; t < 8 * 34 * 34; t += 128) {
            int ci = t / 1156;
            int rr = t % 1156;
            int r = rr / 34;
            int c = rr % 34;
            int gy = tY * 32 - 1 + r;
            int gx = tX * 32 - 1 + c;
            float v = 0.f;
            if ((unsigned)gy < (unsigned)H_ && (unsigned)gx < (unsigned)W_)
                v = x[((b * C_ + cic * 8 + ci) * H_ + gy) * W_ + gx];
            xs[ci][r][c] = v;
        }
        __syncthreads();

#pragma unroll
        for (int ci = 0; ci < 8; ++ci) {
            F2U pr[6][3];
#pragma unroll
            for (int r = 0; r < 6; ++r) {
                float2 a  = *(const float2*)&xs[ci][ty * 4 + r][tx * 2];
                float2 c2 = *(const float2*)&xs[ci][ty * 4 + r][tx * 2 + 2];
                pr[r][0].f = a;
                pr[r][1].f = make_float2(a.y, c2.x);
                pr[r][2].f = c2;
            }
#pragma unroll
            for (int oc = 0; oc < 8; ++oc) {
#pragma unroll
                for (int dy = 0; dy < 3; ++dy)
#pragma unroll
                    for (int dx = 0; dx < 3; ++dx) {
                        F2U kv;
                        kv.f = ks2[oc][ci][dy * 3 + dx];
#pragma unroll
                        for (int yy = 0; yy < 4; ++yy)
                            asm("fma.rn.f32x2 %0, %1, %2, %0;"
                                : "+l"(acc[yy][oc].u)
                                : "l"(pr[yy + dy][dx].u), "l"(kv.u));
                    }
            }
        }
    }

#pragma unroll
    for (int yy = 0; yy < 4; ++yy) {
        int gy = tY * 32 + ty * 4 + yy;
        int gx = tX * 32 + tx * 2;
#pragma unroll
        for (int oc = 0; oc < 8; ++oc) {
            float2 v = acc[yy][oc].f;
            v.x = fmaxf(v.x, 0.f);
            v.y = fmaxf(v.y, 0.f);
            *(float2*)&out[((b * C_ + ocg * 8 + oc) * H_ + gy) * W_ + gx] = v;
        }
    }
}

// ---------------------------------------------------------------------------
// Launch
// ---------------------------------------------------------------------------
extern "C" void kernel_launch(void* const* d_in, const int* in_sizes, int n_in,
                              void* d_out, int out_size) {
    const float* x    = (const float*)d_in[0];  // (16,64,192,192)
    const float* w_qk = (const float*)d_in[1];  // (128,64,3,3)
    const float* wgt  = (const float*)d_in[2];  // (64,64,3,3)
    const float* temp = (const float*)d_in[3];  // (1,1,1)
    float* out = (float*)d_out;                 // (16,64,192,192)

    qk_conv_kernel<<<dim3(16, 8, 16), 64>>>(x, w_qk);
    attn_kernel<<<dim3(5, 5, 16), 128>>>();
    akconv_kernel<<<dim3(64, 16), 64>>>(wgt);
    kern_kernel<<<dim3(64, 16), 64>>>(wgt, temp);
    final_conv_kernel<<<dim3(36, 8, 16), 128>>>(x, out);
}

// round 3
// speedup vs baseline: 1.0985x; 1.0985x over previous
#include <cuda_runtime.h>
#include <cuda_bf16.h>
#include <math.h>

// Problem constants
#define B_  16
#define C_  64
#define H_  192
#define W_  192
#define H2_ 64
#define W2_ 64
#define S_  5

// ---------------------------------------------------------------------------
// Scratch buffers (static device globals; no allocation allowed)
// ---------------------------------------------------------------------------
// q/k now CHANNEL-LAST: g_q[b][h][w][c]
__device__ float g_q[B_ * H2_ * W2_ * C_];
__device__ float g_k[B_ * H2_ * W2_ * C_];
__device__ float g_attn[B_ * C_ * C_ * S_ * S_];  // [b][co(k-ch)][ci(q-ch)][i][j]
__device__ float g_ak[B_ * C_ * C_ * 9];          // transposed ak (pre-norm)
__device__ float g_kern[B_ * C_ * C_ * 9];        // final dynamic kernels

union F2U {
    float2 f;
    unsigned long long u;
};

// ---------------------------------------------------------------------------
// Kernel A: qk conv, stride 3, VALID. Non-overlapping 3x3 patches.
// f32x2 over output-channel PAIRS (weights pre-paired in smem, x duplicated).
// grid (16 tiles, 8 oc-groups, 16 b), block 64 threads (8x8), thread = 2x2 px,
// 16 oc per block (8 pairs). Output written channel-last.
// q/k are NOT normalized (scale cancels after ak normalization).
// ---------------------------------------------------------------------------
__global__ void __launch_bounds__(64) qk_conv_kernel(const float* __restrict__ x,
                                                     const float* __restrict__ w_qk) {
    const int tileI = blockIdx.x >> 2;
    const int tileJ = blockIdx.x & 3;
    const int ocg   = blockIdx.y;   // 0..7, 16 oc each (128 total)
    const int b     = blockIdx.z;

    const int tid = threadIdx.x;
    const int thx = tid & 7;
    const int thy = tid >> 3;

    __shared__ float  xs[4][48][48];    // 36.9 KB
    __shared__ float2 ws2[4][9][8];     // oc-pairs: 2.3 KB

    F2U acc2[8][4];
#pragma unroll
    for (int ocp = 0; ocp < 8; ++ocp)
#pragma unroll
        for (int p = 0; p < 4; ++p) acc2[ocp][p].u = 0ull;

    const int row0 = tileI * 48;
    const int col0 = tileJ * 48;

    for (int cic = 0; cic < 16; ++cic) {
        const int ci0 = cic * 4;
        __syncthreads();
        // weights: 4ci x 9tap x 8 oc-pairs
        for (int t = tid; t < 288; t += 64) {
            int ocp = t & 7;
            int r   = t >> 3;
            int tap = r % 9;
            int ci  = r / 9;
            int oc0 = ocg * 16 + ocp * 2;
            ws2[ci][tap][ocp] = make_float2(
                w_qk[((oc0    ) * C_ + ci0 + ci) * 9 + tap],
                w_qk[((oc0 + 1) * C_ + ci0 + ci) * 9 + tap]);
        }
        // x region: 4ci x 48 x 48
        for (int t = tid; t < 4 * 48 * 48; t += 64) {
            int ci = t / 2304;
            int rr = t % 2304;
            int r = rr / 48;
            int c = rr % 48;
            xs[ci][r][c] = x[((b * C_ + ci0 + ci) * H_ + row0 + r) * W_ + col0 + c];
        }
        __syncthreads();

#pragma unroll
        for (int ci = 0; ci < 4; ++ci) {
            F2U xd[4][9];
#pragma unroll
            for (int py = 0; py < 2; ++py)
#pragma unroll
                for (int px = 0; px < 2; ++px)
#pragma unroll
                    for (int dy = 0; dy < 3; ++dy)
#pragma unroll
                        for (int dx = 0; dx < 3; ++dx) {
                            float v = xs[ci][thy * 6 + py * 3 + dy][thx * 6 + px * 3 + dx];
                            xd[py * 2 + px][dy * 3 + dx].f = make_float2(v, v);
                        }
#pragma unroll
            for (int ocp = 0; ocp < 8; ++ocp) {
#pragma unroll
                for (int t9 = 0; t9 < 9; ++t9) {
                    F2U kv;
                    kv.f = ws2[ci][t9][ocp];
#pragma unroll
                    for (int p = 0; p < 4; ++p)
                        asm("fma.rn.f32x2 %0, %1, %2, %0;"
                            : "+l"(acc2[ocp][p].u)
                            : "l"(xd[p][t9].u), "l"(kv.u));
                }
            }
        }
    }

    // write channel-last
    float* dst = (ocg < 4) ? g_q : g_k;
    const int cbase = (ocg & 3) * 16;
#pragma unroll
    for (int py = 0; py < 2; ++py)
#pragma unroll
        for (int px = 0; px < 2; ++px) {
            int i = tileI * 16 + thy * 2 + py;
            int j = tileJ * 16 + thx * 2 + px;
            float* p = dst + ((b * H2_ + i) * W2_ + j) * C_ + cbase;
#pragma unroll
            for (int ocp = 0; ocp < 8; ++ocp)
                *(float2*)&p[ocp * 2] = acc2[ocp][py * 2 + px].f;
        }
}

// ---------------------------------------------------------------------------
// Kernel B: attn[b,co,ci,i,j] = sum_{h,w valid} q[b,ci,h+i-2,w+j-2] * k[b,co,h,w]
// All 25 shifts computed per thread in a 5x5 f32x2 register file.
// Block 128 threads: tco 0..15 (co), tcip 0..7 (ci pair). Tile co=16, ci=16.
// grid (16 = 4cog x 4cig, 16 b). Rolling 5-row q smem buffer, mod-5 column
// window in registers: 5 LDS.64 per 25 FFMA2.
// ---------------------------------------------------------------------------
__global__ void __launch_bounds__(128) attn_kernel() {
    const int cog = blockIdx.x >> 2;
    const int cig = blockIdx.x & 3;
    const int b   = blockIdx.y;

    const int tid  = threadIdx.x;
    const int tco  = tid & 15;
    const int tcip = tid >> 4;  // 0..7

    __shared__ __align__(16) float qs[5][68 * 16];  // 21.8 KB, rows mod 5, cols padded +-2
    __shared__ float ks[64 * 16];                   // 4 KB

    const float* __restrict__ qg = g_q + (b * H2_ * W2_) * C_ + cig * 16;
    const float* __restrict__ kg = g_k + (b * H2_ * W2_) * C_ + cog * 16;

    F2U acc[5][5];
#pragma unroll
    for (int i = 0; i < 5; ++i)
#pragma unroll
        for (int j = 0; j < 5; ++j) acc[i][j].u = 0ull;

    // prologue: rows -2,-1 -> slots 3,4 (zero); rows 0,1 -> slots 0,1
    for (int t = tid; t < 1088; t += 128) {
        qs[3][t] = 0.f;
        qs[4][t] = 0.f;
    }
#pragma unroll
    for (int r = 0; r < 2; ++r)
        for (int t = tid; t < 1088; t += 128) {
            int col = t >> 4, c = t & 15, gw = col - 2;
            float v = 0.f;
            if ((unsigned)gw < 64u) v = qg[(r * W2_ + gw) * C_ + c];
            qs[r][t] = v;
        }

    for (int h = 0; h < 64; ++h) {
        __syncthreads();
        // k row h
        for (int t = tid; t < 1024; t += 128) {
            int w = t >> 4, c = t & 15;
            ks[t] = kg[(h * W2_ + w) * C_ + c];
        }
        // q row h+2 into slot (h+2)%5
        {
            int row = h + 2;
            float* dstp = qs[row % 5];
            if (row < 64) {
                for (int t = tid; t < 1088; t += 128) {
                    int col = t >> 4, c = t & 15, gw = col - 2;
                    float v = 0.f;
                    if ((unsigned)gw < 64u) v = qg[(row * W2_ + gw) * C_ + c];
                    dstp[t] = v;
                }
            } else {
                for (int t = tid; t < 1088; t += 128) dstp[t] = 0.f;
            }
        }
        __syncthreads();

        const float* qr[5];
#pragma unroll
        for (int di = 0; di < 5; ++di) qr[di] = qs[(h + di + 8) % 5];

        // init column window: padded cols 0..3
        F2U win[5][5];
#pragma unroll
        for (int s = 0; s < 4; ++s)
#pragma unroll
            for (int di = 0; di < 5; ++di)
                win[di][s].f = *(const float2*)&qr[di][s * 16 + tcip * 2];

        for (int wq = 0; wq < 64; wq += 5) {
#pragma unroll
            for (int u = 0; u < 5; ++u) {
                int w = wq + u;
                if (w < 64) {
                    const int sN = (u + 4) % 5;  // slot for padded col w+4
#pragma unroll
                    for (int di = 0; di < 5; ++di)
                        win[di][sN].f = *(const float2*)&qr[di][(w + 4) * 16 + tcip * 2];
                    F2U kd;
                    float kv = ks[w * 16 + tco];
                    kd.f = make_float2(kv, kv);
#pragma unroll
                    for (int i = 0; i < 5; ++i)
#pragma unroll
                        for (int j = 0; j < 5; ++j)
                            asm("fma.rn.f32x2 %0, %1, %2, %0;"
                                : "+l"(acc[i][j].u)
                                : "l"(win[i][(u + j) % 5].u), "l"(kd.u));
                }
            }
        }
    }

    const int co  = cog * 16 + tco;
    const int ci0 = cig * 16 + tcip * 2;
#pragma unroll
    for (int i = 0; i < 5; ++i)
#pragma unroll
        for (int j = 0; j < 5; ++j) {
            g_attn[((b * 64 + co) * 64 + ci0    ) * 25 + i * 5 + j] = acc[i][j].f.x;
            g_attn[((b * 64 + co) * 64 + ci0 + 1) * 25 + i * 5 + j] = acc[i][j].f.y;
        }
}

// ---------------------------------------------------------------------------
// Kernel C1: ak conv (VALID 3x3 over 5x5 attn maps), already transposed:
//   g_ak[b][cB][cA][ky*3+kx] = sum_{ci,dy,dx} attn[b][cA][ci][ky+dy][kx+dx] * weight[cB][ci][dy][dx]
// grid (64 cA, 16 b), block 64 (thread = cB).
// ---------------------------------------------------------------------------
__global__ void __launch_bounds__(64) akconv_kernel(const float* __restrict__ weight) {
    const int cA = blockIdx.x;
    const int b  = blockIdx.y;
    const int cB = threadIdx.x;

    __shared__ float as_[64][25];
    __shared__ float ws[64][73];

    for (int t = cB; t < 1600; t += 64)
        as_[t / 25][t % 25] = g_attn[(b * 64 + cA) * 1600 + t];

    float acc[9];
#pragma unroll
    for (int t9 = 0; t9 < 9; ++t9) acc[t9] = 0.f;

    for (int cic = 0; cic < 8; ++cic) {
        __syncthreads();
        for (int t = cB; t < 4608; t += 64) {
            int c2 = t / 72;
            int rr = t % 72;
            ws[c2][rr] = weight[c2 * 576 + (cic * 8 + rr / 9) * 9 + (rr % 9)];
        }
        __syncthreads();
#pragma unroll
        for (int ci = 0; ci < 8; ++ci) {
            float av[25];
#pragma unroll
            for (int p = 0; p < 25; ++p) av[p] = as_[cic * 8 + ci][p];
#pragma unroll
            for (int dy = 0; dy < 3; ++dy)
#pragma unroll
                for (int dx = 0; dx < 3; ++dx) {
                    float wv = ws[cB][ci * 9 + dy * 3 + dx];
#pragma unroll
                    for (int ky = 0; ky < 3; ++ky)
#pragma unroll
                        for (int kx = 0; kx < 3; ++kx)
                            acc[ky * 3 + kx] =
                                fmaf(av[(ky + dy) * 5 + (kx + dx)], wv, acc[ky * 3 + kx]);
                }
        }
    }
#pragma unroll
    for (int t9 = 0; t9 < 9; ++t9)
        g_ak[((b * 64 + cB) * 64 + cA) * 9 + t9] = acc[t9];
}

// ---------------------------------------------------------------------------
// Kernel C2: per-(b,cB) L2 normalize ak over (cA,3,3), then
//   kern[b,cB,cA,t] = weight[cB,cA,t] + ak_n * temperature
// ---------------------------------------------------------------------------
__global__ void __launch_bounds__(64) kern_kernel(const float* __restrict__ weight,
                                                  const float* __restrict__ temperature) {
    const int cB  = blockIdx.x;
    const int b   = blockIdx.y;
    const int tid = threadIdx.x;  // = cA

    const float* ak = g_ak + (b * 64 + cB) * 64 * 9;
    float v[9];
    float ss = 0.f;
#pragma unroll
    for (int t9 = 0; t9 < 9; ++t9) {
        v[t9] = ak[tid * 9 + t9];
        ss = fmaf(v[t9], v[t9], ss);
    }

    __shared__ float red[64];
    red[tid] = ss;
    __syncthreads();
#pragma unroll
    for (int s = 32; s >= 1; s >>= 1) {
        if (tid < s) red[tid] += red[tid + s];
        __syncthreads();
    }
    float nrm = sqrtf(red[0]);
    float scale = temperature[0] / fmaxf(nrm, 1e-12f);

#pragma unroll
    for (int t9 = 0; t9 < 9; ++t9)
        g_kern[((b * 64 + cB) * 64 + tid) * 9 + t9] =
            weight[(cB * 64 + tid) * 9 + t9] + v[t9] * scale;
}

// ---------------------------------------------------------------------------
// Kernel D: final per-sample 3x3 conv (pad 1) + ReLU, packed f32x2 FMA.
// ---------------------------------------------------------------------------
__global__ void __launch_bounds__(128) final_conv_kernel(const float* __restrict__ x,
                                                         float* __restrict__ out) {
    const int tY  = blockIdx.x / 6;
    const int tX  = blockIdx.x % 6;
    const int ocg = blockIdx.y;
    const int b   = blockIdx.z;

    const int tid = threadIdx.x;
    const int tx = tid & 15;
    const int ty = tid >> 4;

    __shared__ float  xs[8][34][34];
    __shared__ float2 ks2[8][8][9];

    F2U acc[4][8];
#pragma unroll
    for (int yy = 0; yy < 4; ++yy)
#pragma unroll
        for (int oc = 0; oc < 8; ++oc) acc[yy][oc].u = 0ull;

    for (int cic = 0; cic < 8; ++cic) {
        __syncthreads();
        for (int t = tid; t < 576; t += 128) {
            int oc = t / 72;
            int rr = t % 72;
            float v = g_kern[((b * 64 + ocg * 8 + oc) * 64 + cic * 8 + rr / 9) * 9 + (rr % 9)];
            ks2[oc][rr / 9][rr % 9] = make_float2(v, v);
        }
        for (int t = tid; t < 8 * 34 * 34; t += 128) {
            int ci = t / 1156;
            int rr = t % 1156;
            int r = rr / 34;
            int c = rr % 34;
            int gy = tY * 32 - 1 + r;
            int gx = tX * 32 - 1 + c;
            float v = 0.f;
            if ((unsigned)gy < (unsigned)H_ && (unsigned)gx < (unsigned)W_)
                v = x[((b * C_ + cic * 8 + ci) * H_ + gy) * W_ + gx];
            xs[ci][r][c] = v;
        }
        __syncthreads();

#pragma unroll
        for (int ci = 0; ci < 8; ++ci) {
            F2U pr[6][3];
#pragma unroll
            for (int r = 0; r < 6; ++r) {
                float2 a  = *(const float2*)&xs[ci][ty * 4 + r][tx * 2];
                float2 c2 = *(const float2*)&xs[ci][ty * 4 + r][tx * 2 + 2];
                pr[r][0].f = a;
                pr[r][1].f = make_float2(a.y, c2.x);
                pr[r][2].f = c2;
            }
#pragma unroll
            for (int oc = 0; oc < 8; ++oc) {
#pragma unroll
                for (int dy = 0; dy < 3; ++dy)
#pragma unroll
                    for (int dx = 0; dx < 3; ++dx) {
                        F2U kv;
                        kv.f = ks2[oc][ci][dy * 3 + dx];
#pragma unroll
                        for (int yy = 0; yy < 4; ++yy)
                            asm("fma.rn.f32x2 %0, %1, %2, %0;"
                                : "+l"(acc[yy][oc].u)
                                : "l"(pr[yy + dy][dx].u), "l"(kv.u));
                    }
            }
        }
    }

#pragma unroll
    for (int yy = 0; yy < 4; ++yy) {
        int gy = tY * 32 + ty * 4 + yy;
        int gx = tX * 32 + tx * 2;
#pragma unroll
        for (int oc = 0; oc < 8; ++oc) {
            float2 v = acc[yy][oc].f;
            v.x = fmaxf(v.x, 0.f);
            v.y = fmaxf(v.y, 0.f);
            *(float2*)&out[((b * C_ + ocg * 8 + oc) * H_ + gy) * W_ + gx] = v;
        }
    }
}

// ---------------------------------------------------------------------------
// Launch
// ---------------------------------------------------------------------------
extern "C" void kernel_launch(void* const* d_in, const int* in_sizes, int n_in,
                              void* d_out, int out_size) {
    const float* x    = (const float*)d_in[0];  // (16,64,192,192)
    const float* w_qk = (const float*)d_in[1];  // (128,64,3,3)
    const float* wgt  = (const float*)d_in[2];  // (64,64,3,3)
    const float* temp = (const float*)d_in[3];  // (1,1,1)
    float* out = (float*)d_out;                 // (16,64,192,192)

    qk_conv_kernel<<<dim3(16, 8, 16), 64>>>(x, w_qk);
    attn_kernel<<<dim3(16, 16), 128>>>();
    akconv_kernel<<<dim3(64, 16), 64>>>(wgt);
    kern_kernel<<<dim3(64, 16), 64>>>(wgt, temp);
    final_conv_kernel<<<dim3(36, 8, 16), 128>>>(x, out);
}

// round 6
// speedup vs baseline: 1.6077x; 1.4635x over previous
#include <cuda_runtime.h>
#include <cuda_bf16.h>
#include <cstdint>
#include <math.h>

// Problem constants
#define B_  16
#define C_  64
#define H_  192
#define W_  192
#define H2_ 64
#define W2_ 64
#define S_  5

// ---------------------------------------------------------------------------
// Scratch buffers (static device globals; no allocation allowed)
// ---------------------------------------------------------------------------
__device__ float g_q[B_ * H2_ * W2_ * C_];        // channel-last (b,h,w,c)
__device__ float g_k[B_ * H2_ * W2_ * C_];
__device__ float g_attn[B_ * C_ * C_ * S_ * S_];  // [b][co(k-ch)][ci(q-ch)][i][j]
__device__ float g_ak[B_ * C_ * C_ * 9];          // transposed ak (pre-norm)

// bf16 split operands for the tensor-core final conv
__device__ __align__(16) __nv_bfloat16 g_x_hi[B_ * H_ * W_ * C_];  // channel-last
__device__ __align__(16) __nv_bfloat16 g_x_lo[B_ * H_ * W_ * C_];
__device__ __align__(16) __nv_bfloat16 g_kt_hi[B_ * 9 * C_ * C_];  // [b][tap][oc][ci]
__device__ __align__(16) __nv_bfloat16 g_kt_lo[B_ * 9 * C_ * C_];

union F2U {
    float2 f;
    unsigned long long u;
};

__device__ __forceinline__ uint32_t smem_u32(const void* p) {
    uint32_t a;
    asm("{ .reg .u64 t; cvta.to.shared.u64 t, %1; cvt.u32.u64 %0, t; }" : "=r"(a) : "l"(p));
    return a;
}

// ldmatrix x4 (b16, no-trans)
__device__ __forceinline__ void ldsm_x4(uint32_t* r, uint32_t addr) {
    asm volatile("ldmatrix.sync.aligned.m8n8.x4.shared.b16 {%0,%1,%2,%3}, [%4];"
                 : "=r"(r[0]), "=r"(r[1]), "=r"(r[2]), "=r"(r[3])
                 : "r"(addr));
}

// mma.sync m16n8k16 bf16 -> fp32 accum (in-place)
__device__ __forceinline__ void mma_bf16(float* d, const uint32_t* a, const uint32_t* b) {
    asm volatile(
        "mma.sync.aligned.m16n8k16.row.col.f32.bf16.bf16.f32 "
        "{%0,%1,%2,%3}, {%4,%5,%6,%7}, {%8,%9}, {%0,%1,%2,%3};"
        : "+f"(d[0]), "+f"(d[1]), "+f"(d[2]), "+f"(d[3])
        : "r"(a[0]), "r"(a[1]), "r"(a[2]), "r"(a[3]), "r"(b[0]), "r"(b[1]));
}

// ---------------------------------------------------------------------------
// Kernel E0: x (fp32 NCHW) -> channel-last bf16 hi/lo
// ---------------------------------------------------------------------------
__global__ void __launch_bounds__(256) xcl_kernel(const float* __restrict__ x) {
    const int seg = blockIdx.x;
    const int b = blockIdx.y;
    const int y = seg / 3;
    const int x0 = (seg % 3) * 64;
    __shared__ float s[64][65];
    const int tid = threadIdx.x;

#pragma unroll
    for (int i = 0; i < 16; ++i) {
        int idx = tid + i * 256;
        int c = idx >> 6, p = idx & 63;
        s[p][c] = x[((b * 64 + c) * 192 + y) * 192 + x0 + p];
    }
    __syncthreads();
#pragma unroll
    for (int i = 0; i < 16; ++i) {
        int idx = tid + i * 256;
        int p = idx >> 6, c = idx & 63;
        float v = s[p][c];
        __nv_bfloat16 h = __float2bfloat16(v);
        float hf = __bfloat162float(h);
        __nv_bfloat16 l = __float2bfloat16(v - hf);
        int o = ((b * 192 + y) * 192 + x0 + p) * 64 + c;
        g_x_hi[o] = h;
        g_x_lo[o] = l;
    }
}

// ---------------------------------------------------------------------------
// Kernel A: qk conv, stride 3, VALID (f32x2 oc-pairs). Output channel-last.
// q/k NOT normalized (scale cancels after ak normalization).
// ---------------------------------------------------------------------------
__global__ void __launch_bounds__(64) qk_conv_kernel(const float* __restrict__ x,
                                                     const float* __restrict__ w_qk) {
    const int tileI = blockIdx.x >> 2;
    const int tileJ = blockIdx.x & 3;
    const int ocg   = blockIdx.y;
    const int b     = blockIdx.z;

    const int tid = threadIdx.x;
    const int thx = tid & 7;
    const int thy = tid >> 3;

    __shared__ float  xs[4][48][48];
    __shared__ float2 ws2[4][9][8];

    F2U acc2[8][4];
#pragma unroll
    for (int ocp = 0; ocp < 8; ++ocp)
#pragma unroll
        for (int p = 0; p < 4; ++p) acc2[ocp][p].u = 0ull;

    const int row0 = tileI * 48;
    const int col0 = tileJ * 48;

    for (int cic = 0; cic < 16; ++cic) {
        const int ci0 = cic * 4;
        __syncthreads();
        for (int t = tid; t < 288; t += 64) {
            int ocp = t & 7;
            int r   = t >> 3;
            int tap = r % 9;
            int ci  = r / 9;
            int oc0 = ocg * 16 + ocp * 2;
            ws2[ci][tap][ocp] = make_float2(
                w_qk[((oc0    ) * C_ + ci0 + ci) * 9 + tap],
                w_qk[((oc0 + 1) * C_ + ci0 + ci) * 9 + tap]);
        }
        for (int t = tid; t < 4 * 48 * 48; t += 64) {
            int ci = t / 2304;
            int rr = t % 2304;
            int r = rr / 48;
            int c = rr % 48;
            xs[ci][r][c] = x[((b * C_ + ci0 + ci) * H_ + row0 + r) * W_ + col0 + c];
        }
        __syncthreads();

#pragma unroll
        for (int ci = 0; ci < 4; ++ci) {
            F2U xd[4][9];
#pragma unroll
            for (int py = 0; py < 2; ++py)
#pragma unroll
                for (int px = 0; px < 2; ++px)
#pragma unroll
                    for (int dy = 0; dy < 3; ++dy)
#pragma unroll
                        for (int dx = 0; dx < 3; ++dx) {
                            float v = xs[ci][thy * 6 + py * 3 + dy][thx * 6 + px * 3 + dx];
                            xd[py * 2 + px][dy * 3 + dx].f = make_float2(v, v);
                        }
#pragma unroll
            for (int ocp = 0; ocp < 8; ++ocp) {
#pragma unroll
                for (int t9 = 0; t9 < 9; ++t9) {
                    F2U kv;
                    kv.f = ws2[ci][t9][ocp];
#pragma unroll
                    for (int p = 0; p < 4; ++p)
                        asm("fma.rn.f32x2 %0, %1, %2, %0;"
                            : "+l"(acc2[ocp][p].u)
                            : "l"(xd[p][t9].u), "l"(kv.u));
                }
            }
        }
    }

    float* dst = (ocg < 4) ? g_q : g_k;
    const int cbase = (ocg & 3) * 16;
#pragma unroll
    for (int py = 0; py < 2; ++py)
#pragma unroll
        for (int px = 0; px < 2; ++px) {
            int i = tileI * 16 + thy * 2 + py;
            int j = tileJ * 16 + thx * 2 + px;
            float* p = dst + ((b * H2_ + i) * W2_ + j) * C_ + cbase;
#pragma unroll
            for (int ocp = 0; ocp < 8; ++ocp)
                *(float2*)&p[ocp * 2] = acc2[ocp][py * 2 + px].f;
        }
}

// ---------------------------------------------------------------------------
// Kernel B: attn via 25-shift register-blocked cross-correlation (f32x2)
// ---------------------------------------------------------------------------
__global__ void __launch_bounds__(128) attn_kernel() {
    const int cog = blockIdx.x >> 2;
    const int cig = blockIdx.x & 3;
    const int b   = blockIdx.y;

    const int tid  = threadIdx.x;
    const int tco  = tid & 15;
    const int tcip = tid >> 4;

    __shared__ __align__(16) float qs[5][68 * 16];
    __shared__ float ks[64 * 16];

    const float* __restrict__ qg = g_q + (b * H2_ * W2_) * C_ + cig * 16;
    const float* __restrict__ kg = g_k + (b * H2_ * W2_) * C_ + cog * 16;

    F2U acc[5][5];
#pragma unroll
    for (int i = 0; i < 5; ++i)
#pragma unroll
        for (int j = 0; j < 5; ++j) acc[i][j].u = 0ull;

    for (int t = tid; t < 1088; t += 128) {
        qs[3][t] = 0.f;
        qs[4][t] = 0.f;
    }
#pragma unroll
    for (int r = 0; r < 2; ++r)
        for (int t = tid; t < 1088; t += 128) {
            int col = t >> 4, c = t & 15, gw = col - 2;
            float v = 0.f;
            if ((unsigned)gw < 64u) v = qg[(r * W2_ + gw) * C_ + c];
            qs[r][t] = v;
        }

    for (int h = 0; h < 64; ++h) {
        __syncthreads();
        for (int t = tid; t < 1024; t += 128) {
            int w = t >> 4, c = t & 15;
            ks[t] = kg[(h * W2_ + w) * C_ + c];
        }
        {
            int row = h + 2;
            float* dstp = qs[row % 5];
            if (row < 64) {
                for (int t = tid; t < 1088; t += 128) {
                    int col = t >> 4, c = t & 15, gw = col - 2;
                    float v = 0.f;
                    if ((unsigned)gw < 64u) v = qg[(row * W2_ + gw) * C_ + c];
                    dstp[t] = v;
                }
            } else {
                for (int t = tid; t < 1088; t += 128) dstp[t] = 0.f;
            }
        }
        __syncthreads();

        const float* qr[5];
#pragma unroll
        for (int di = 0; di < 5; ++di) qr[di] = qs[(h + di + 8) % 5];

        F2U win[5][5];
#pragma unroll
        for (int s = 0; s < 4; ++s)
#pragma unroll
            for (int di = 0; di < 5; ++di)
                win[di][s].f = *(const float2*)&qr[di][s * 16 + tcip * 2];

        for (int wq = 0; wq < 64; wq += 5) {
#pragma unroll
            for (int u = 0; u < 5; ++u) {
                int w = wq + u;
                if (w < 64) {
                    const int sN = (u + 4) % 5;
#pragma unroll
                    for (int di = 0; di < 5; ++di)
                        win[di][sN].f = *(const float2*)&qr[di][(w + 4) * 16 + tcip * 2];
                    F2U kd;
                    float kv = ks[w * 16 + tco];
                    kd.f = make_float2(kv, kv);
#pragma unroll
                    for (int i = 0; i < 5; ++i)
#pragma unroll
                        for (int j = 0; j < 5; ++j)
                            asm("fma.rn.f32x2 %0, %1, %2, %0;"
                                : "+l"(acc[i][j].u)
                                : "l"(win[i][(u + j) % 5].u), "l"(kd.u));
                }
            }
        }
    }

    const int co  = cog * 16 + tco;
    const int ci0 = cig * 16 + tcip * 2;
#pragma unroll
    for (int i = 0; i < 5; ++i)
#pragma unroll
        for (int j = 0; j < 5; ++j) {
            g_attn[((b * 64 + co) * 64 + ci0    ) * 25 + i * 5 + j] = acc[i][j].f.x;
            g_attn[((b * 64 + co) * 64 + ci0 + 1) * 25 + i * 5 + j] = acc[i][j].f.y;
        }
}

// ---------------------------------------------------------------------------
// Kernel C1: ak conv (VALID 3x3 over 5x5 attn), transposed output
// ---------------------------------------------------------------------------
__global__ void __launch_bounds__(64) akconv_kernel(const float* __restrict__ weight) {
    const int cA = blockIdx.x;
    const int b  = blockIdx.y;
    const int cB = threadIdx.x;

    __shared__ float as_[64][25];
    __shared__ float ws[64][73];

    for (int t = cB; t < 1600; t += 64)
        as_[t / 25][t % 25] = g_attn[(b * 64 + cA) * 1600 + t];

    float acc[9];
#pragma unroll
    for (int t9 = 0; t9 < 9; ++t9) acc[t9] = 0.f;

    for (int cic = 0; cic < 8; ++cic) {
        __syncthreads();
        for (int t = cB; t < 4608; t += 64) {
            int c2 = t / 72;
            int rr = t % 72;
            ws[c2][rr] = weight[c2 * 576 + (cic * 8 + rr / 9) * 9 + (rr % 9)];
        }
        __syncthreads();
#pragma unroll
        for (int ci = 0; ci < 8; ++ci) {
            float av[25];
#pragma unroll
            for (int p = 0; p < 25; ++p) av[p] = as_[cic * 8 + ci][p];
#pragma unroll
            for (int dy = 0; dy < 3; ++dy)
#pragma unroll
                for (int dx = 0; dx < 3; ++dx) {
                    float wv = ws[cB][ci * 9 + dy * 3 + dx];
#pragma unroll
                    for (int ky = 0; ky < 3; ++ky)
#pragma unroll
                        for (int kx = 0; kx < 3; ++kx)
                            acc[ky * 3 + kx] =
                                fmaf(av[(ky + dy) * 5 + (kx + dx)], wv, acc[ky * 3 + kx]);
                }
        }
    }
#pragma unroll
    for (int t9 = 0; t9 < 9; ++t9)
        g_ak[((b * 64 + cB) * 64 + cA) * 9 + t9] = acc[t9];
}

// ---------------------------------------------------------------------------
// Kernel C2: normalize ak, build dynamic kernels -> bf16 hi/lo B-operand tiles
// g_kt_*[b][tap][oc=cB][ci=cA]
// ---------------------------------------------------------------------------
__global__ void __launch_bounds__(64) kern_kernel(const float* __restrict__ weight,
                                                  const float* __restrict__ temperature) {
    const int cB  = blockIdx.x;
    const int b   = blockIdx.y;
    const int tid = threadIdx.x;  // = cA

    const float* ak = g_ak + (b * 64 + cB) * 64 * 9;
    float v[9];
    float ss = 0.f;
#pragma unroll
    for (int t9 = 0; t9 < 9; ++t9) {
        v[t9] = ak[tid * 9 + t9];
        ss = fmaf(v[t9], v[t9], ss);
    }

    __shared__ float red[64];
    red[tid] = ss;
    __syncthreads();
#pragma unroll
    for (int s = 32; s >= 1; s >>= 1) {
        if (tid < s) red[tid] += red[tid + s];
        __syncthreads();
    }
    float nrm = sqrtf(red[0]);
    float scale = temperature[0] / fmaxf(nrm, 1e-12f);

#pragma unroll
    for (int t9 = 0; t9 < 9; ++t9) {
        float vv = weight[(cB * 64 + tid) * 9 + t9] + v[t9] * scale;
        __nv_bfloat16 h = __float2bfloat16(vv);
        float hf = __bfloat162float(h);
        __nv_bfloat16 l = __float2bfloat16(vv - hf);
        int o = ((b * 9 + t9) * 64 + cB) * 64 + tid;
        g_kt_hi[o] = h;
        g_kt_lo[o] = l;
    }
}

// ---------------------------------------------------------------------------
// Kernel D: final conv via mma.sync m16n8k16 bf16 (3-term split, fp32 accum)
// Per block: b, y-pair, x-tile(64). M=128 pixels, N=64 oc, K=9 taps x 64 ci.
// 4 warps; warp w owns m rows [w*32, w*32+32), all 64 oc.
// Dynamic smem = 49152 B (default cap): Ahi 16K | Alo 16K | Bhi 8K | Blo 8K.
// ---------------------------------------------------------------------------
#define SM_AHI  0
#define SM_ALO  16384
#define SM_BHI  32768
#define SM_BLO  40960
#define SM_TOT  49152

__global__ void __launch_bounds__(128) final_mma_kernel(float* __restrict__ out) {
    extern __shared__ char smem[];
    const int xt = blockIdx.x, yp = blockIdx.y, b = blockIdx.z;
    const int x0 = xt * 64, y0 = yp * 2;
    const int tid = threadIdx.x, wid = tid >> 5, lid = tid & 31;
    const uint32_t sbase = smem_u32(smem);

    const int r = tid;  // A row filled by this thread (pixel index m)
    const int yy = r >> 6, xx = r & 63;

    float acc[2][8][4];
#pragma unroll
    for (int mt = 0; mt < 2; ++mt)
#pragma unroll
        for (int j = 0; j < 8; ++j)
#pragma unroll
            for (int e = 0; e < 4; ++e) acc[mt][j][e] = 0.f;

    // ldmatrix per-lane address components (hoisted)
    // A: row = wid*32 + mt*16 + (lid & 15), col16 = kc*2 + (lid >> 4)
    const int arow0 = wid * 32 + (lid & 15);
    const int apart = lid >> 4;
    // B: n = (lid & 7) + ((lid >> 4) << 3) + nt*16, col16 = kc*2 + ((lid >> 3) & 1)
    const int brow0 = (lid & 7) + ((lid >> 4) << 3);
    const int bpart = (lid >> 3) & 1;

    for (int tap = 0; tap < 9; ++tap) {
        const int dy = tap / 3 - 1, dx = tap % 3 - 1;
        __syncthreads();
        // ---- fill A hi/lo: row r = 64 bf16 = 128B, XOR-swizzled 16B chunks ----
        {
            int y = y0 + yy + dy, xc = x0 + xx + dx;
            bool ok = ((unsigned)y < (unsigned)H_) && ((unsigned)xc < (unsigned)W_);
            long base = ((long)(b * 192 + y) * 192 + xc) * 8;  // uint4 index
            const uint4* sh = (const uint4*)g_x_hi + base;
            const uint4* sl = (const uint4*)g_x_lo + base;
            const uint4 z = make_uint4(0, 0, 0, 0);
#pragma unroll
            for (int c = 0; c < 8; ++c) {
                uint4 vh = ok ? sh[c] : z;
                uint4 vl = ok ? sl[c] : z;
                uint32_t off = (uint32_t)r * 128u + (uint32_t)((c ^ (r & 7)) * 16);
                *(uint4*)(smem + SM_AHI + off) = vh;
                *(uint4*)(smem + SM_ALO + off) = vl;
            }
        }
        // ---- fill B hi/lo: 64 rows x 8 chunks = 512 uint4 per half ----
        {
            const uint4* kh = (const uint4*)g_kt_hi + (b * 9 + tap) * 512;
            const uint4* kl = (const uint4*)g_kt_lo + (b * 9 + tap) * 512;
#pragma unroll
            for (int i = 0; i < 4; ++i) {
                int idx = tid + i * 128;
                int row = idx >> 3, c = idx & 7;
                uint32_t off = (uint32_t)row * 128u + (uint32_t)((c ^ (row & 7)) * 16);
                *(uint4*)(smem + SM_BHI + off) = kh[idx];
                *(uint4*)(smem + SM_BLO + off) = kl[idx];
            }
        }
        __syncthreads();

#pragma unroll
        for (int kc = 0; kc < 4; ++kc) {
            const int acol = kc * 2 + apart;
            const int bcol = kc * 2 + bpart;
            uint32_t bf[4][4];  // 4 n16 groups (reused for Blo)
            uint32_t ah[2][4], al[2][4];
            // B hi
#pragma unroll
            for (int nt = 0; nt < 4; ++nt) {
                int row = brow0 + nt * 16;
                ldsm_x4(bf[nt], sbase + SM_BHI + row * 128 + ((bcol ^ (row & 7)) << 4));
            }
            // A hi
#pragma unroll
            for (int mt = 0; mt < 2; ++mt) {
                int row = arow0 + mt * 16;
                ldsm_x4(ah[mt], sbase + SM_AHI + row * 128 + ((acol ^ (row & 7)) << 4));
            }
#pragma unroll
            for (int mt = 0; mt < 2; ++mt)
#pragma unroll
                for (int j = 0; j < 8; ++j)
                    mma_bf16(acc[mt][j], ah[mt], &bf[j >> 1][2 * (j & 1)]);
            // A lo x B hi
#pragma unroll
            for (int mt = 0; mt < 2; ++mt) {
                int row = arow0 + mt * 16;
                ldsm_x4(al[mt], sbase + SM_ALO + row * 128 + ((acol ^ (row & 7)) << 4));
            }
#pragma unroll
            for (int mt = 0; mt < 2; ++mt)
#pragma unroll
                for (int j = 0; j < 8; ++j)
                    mma_bf16(acc[mt][j], al[mt], &bf[j >> 1][2 * (j & 1)]);
            // A hi x B lo (reuse bf regs)
#pragma unroll
            for (int nt = 0; nt < 4; ++nt) {
                int row = brow0 + nt * 16;
                ldsm_x4(bf[nt], sbase + SM_BLO + row * 128 + ((bcol ^ (row & 7)) << 4));
            }
#pragma unroll
            for (int mt = 0; mt < 2; ++mt)
#pragma unroll
                for (int j = 0; j < 8; ++j)
                    mma_bf16(acc[mt][j], ah[mt], &bf[j >> 1][2 * (j & 1)]);
        }
    }

    // ---- epilogue: stage fp32 [m][oc] in smem (stride 66), coalesced store ----
    __syncthreads();
    float* st = (float*)smem;
#pragma unroll
    for (int mt = 0; mt < 2; ++mt)
#pragma unroll
        for (int j = 0; j < 8; ++j)
#pragma unroll
            for (int e = 0; e < 4; ++e) {
                int row = wid * 32 + mt * 16 + (lid >> 2) + ((e >> 1) << 3);
                int col = j * 8 + (lid & 3) * 2 + (e & 1);
                st[row * 66 + col] = acc[mt][j][e];
            }
    __syncthreads();

    for (int t = tid; t < 8192; t += 128) {
        int oc = t >> 7, m = t & 127;
        float v = fmaxf(st[m * 66 + oc], 0.f);
        out[((long)(b * 64 + oc) * 192 + (y0 + (m >> 6))) * 192 + x0 + (m & 63)] = v;
    }
}

// ---------------------------------------------------------------------------
// Launch
// ---------------------------------------------------------------------------
extern "C" void kernel_launch(void* const* d_in, const int* in_sizes, int n_in,
                              void* d_out, int out_size) {
    const float* x    = (const float*)d_in[0];  // (16,64,192,192)
    const float* w_qk = (const float*)d_in[1];  // (128,64,3,3)
    const float* wgt  = (const float*)d_in[2];  // (64,64,3,3)
    const float* temp = (const float*)d_in[3];  // (1,1,1)
    float* out = (float*)d_out;                 // (16,64,192,192)

    xcl_kernel<<<dim3(576, 16), 256>>>(x);                       // launch 0
    qk_conv_kernel<<<dim3(16, 8, 16), 64>>>(x, w_qk);            // launch 1
    attn_kernel<<<dim3(16, 16), 128>>>();                        // launch 2
    akconv_kernel<<<dim3(64, 16), 64>>>(wgt);                    // launch 3
    kern_kernel<<<dim3(64, 16), 64>>>(wgt, temp);                // launch 4
    final_mma_kernel<<<dim3(3, 96, 16), 128, SM_TOT>>>(out);     // launch 5 (ncu slot)
}

// round 7
// speedup vs baseline: 1.8286x; 1.1374x over previous
#include <cuda_runtime.h>
#include <cuda_bf16.h>
#include <cstdint>
#include <math.h>

// Problem constants
#define B_  16
#define C_  64
#define H_  192
#define W_  192
#define H2_ 64
#define W2_ 64
#define S_  5

// ---------------------------------------------------------------------------
// Scratch buffers (static device globals; zero-initialized at load)
// ---------------------------------------------------------------------------
__device__ float g_q[B_ * H2_ * W2_ * C_];        // channel-last (b,h,w,c)
__device__ float g_k[B_ * H2_ * W2_ * C_];
__device__ float g_attn[B_ * C_ * C_ * S_ * S_];  // [b][co(k-ch)][ci(q-ch)][i][j]
__device__ float g_ak[B_ * C_ * C_ * 9];          // transposed ak (pre-norm)

// bf16 split operands for the tensor-core final conv
__device__ __align__(16) __nv_bfloat16 g_x_hi[B_ * H_ * W_ * C_];  // channel-last
__device__ __align__(16) __nv_bfloat16 g_x_lo[B_ * H_ * W_ * C_];
__device__ __align__(16) __nv_bfloat16 g_kt_hi[B_ * 9 * C_ * C_];  // [b][tap][oc][ci]
__device__ __align__(16) __nv_bfloat16 g_kt_lo[B_ * 9 * C_ * C_];

// bf16 split operands for the tensor-core attn GEMMs
// k channel-major: [b][co][4096]
__device__ __align__(16) __nv_bfloat16 g_kh[B_ * C_ * 4096];
__device__ __align__(16) __nv_bfloat16 g_kl[B_ * C_ * 4096];
// q shifted copies: [dj(5)][b][ci][68 rows (2 zero-pad top/bottom)][64]
__device__ __align__(16) __nv_bfloat16 g_qh[5 * B_ * C_ * 68 * 64];
__device__ __align__(16) __nv_bfloat16 g_ql[5 * B_ * C_ * 68 * 64];

union F2U {
    float2 f;
    unsigned long long u;
};

__device__ __forceinline__ uint32_t smem_u32(const void* p) {
    uint32_t a;
    asm("{ .reg .u64 t; cvta.to.shared.u64 t, %1; cvt.u32.u64 %0, t; }" : "=r"(a) : "l"(p));
    return a;
}

// ldmatrix x4 (b16, no-trans)
__device__ __forceinline__ void ldsm_x4(uint32_t* r, uint32_t addr) {
    asm volatile("ldmatrix.sync.aligned.m8n8.x4.shared.b16 {%0,%1,%2,%3}, [%4];"
                 : "=r"(r[0]), "=r"(r[1]), "=r"(r[2]), "=r"(r[3])
                 : "r"(addr));
}

// mma.sync m16n8k16 bf16 -> fp32 accum (in-place)
__device__ __forceinline__ void mma_bf16(float* d, const uint32_t* a, const uint32_t* b) {
    asm volatile(
        "mma.sync.aligned.m16n8k16.row.col.f32.bf16.bf16.f32 "
        "{%0,%1,%2,%3}, {%4,%5,%6,%7}, {%8,%9}, {%0,%1,%2,%3};"
        : "+f"(d[0]), "+f"(d[1]), "+f"(d[2]), "+f"(d[3])
        : "r"(a[0]), "r"(a[1]), "r"(a[2]), "r"(a[3]), "r"(b[0]), "r"(b[1]));
}

__device__ __forceinline__ void split_bf16(float v, __nv_bfloat16& h, __nv_bfloat16& l) {
    h = __float2bfloat16(v);
    l = __float2bfloat16(v - __bfloat162float(h));
}

// ---------------------------------------------------------------------------
// Kernel E0: x (fp32 NCHW) -> channel-last bf16 hi/lo
// ---------------------------------------------------------------------------
__global__ void __launch_bounds__(256) xcl_kernel(const float* __restrict__ x) {
    const int seg = blockIdx.x;
    const int b = blockIdx.y;
    const int y = seg / 3;
    const int x0 = (seg % 3) * 64;
    __shared__ float s[64][65];
    const int tid = threadIdx.x;

#pragma unroll
    for (int i = 0; i < 16; ++i) {
        int idx = tid + i * 256;
        int c = idx >> 6, p = idx & 63;
        s[p][c] = x[((b * 64 + c) * 192 + y) * 192 + x0 + p];
    }
    __syncthreads();
#pragma unroll
    for (int i = 0; i < 16; ++i) {
        int idx = tid + i * 256;
        int p = idx >> 6, c = idx & 63;
        __nv_bfloat16 h, l;
        split_bf16(s[p][c], h, l);
        int o = ((b * 192 + y) * 192 + x0 + p) * 64 + c;
        g_x_hi[o] = h;
        g_x_lo[o] = l;
    }
}

// ---------------------------------------------------------------------------
// Kernel A: qk conv, stride 3, VALID (f32x2 oc-pairs). Output channel-last.
// q/k NOT normalized (scale cancels after ak normalization).
// ---------------------------------------------------------------------------
__global__ void __launch_bounds__(64) qk_conv_kernel(const float* __restrict__ x,
                                                     const float* __restrict__ w_qk) {
    const int tileI = blockIdx.x >> 2;
    const int tileJ = blockIdx.x & 3;
    const int ocg   = blockIdx.y;
    const int b     = blockIdx.z;

    const int tid = threadIdx.x;
    const int thx = tid & 7;
    const int thy = tid >> 3;

    __shared__ float  xs[4][48][48];
    __shared__ float2 ws2[4][9][8];

    F2U acc2[8][4];
#pragma unroll
    for (int ocp = 0; ocp < 8; ++ocp)
#pragma unroll
        for (int p = 0; p < 4; ++p) acc2[ocp][p].u = 0ull;

    const int row0 = tileI * 48;
    const int col0 = tileJ * 48;

    for (int cic = 0; cic < 16; ++cic) {
        const int ci0 = cic * 4;
        __syncthreads();
        for (int t = tid; t < 288; t += 64) {
            int ocp = t & 7;
            int r   = t >> 3;
            int tap = r % 9;
            int ci  = r / 9;
            int oc0 = ocg * 16 + ocp * 2;
            ws2[ci][tap][ocp] = make_float2(
                w_qk[((oc0    ) * C_ + ci0 + ci) * 9 + tap],
                w_qk[((oc0 + 1) * C_ + ci0 + ci) * 9 + tap]);
        }
        for (int t = tid; t < 4 * 48 * 48; t += 64) {
            int ci = t / 2304;
            int rr = t % 2304;
            int r = rr / 48;
            int c = rr % 48;
            xs[ci][r][c] = x[((b * C_ + ci0 + ci) * H_ + row0 + r) * W_ + col0 + c];
        }
        __syncthreads();

#pragma unroll
        for (int ci = 0; ci < 4; ++ci) {
            F2U xd[4][9];
#pragma unroll
            for (int py = 0; py < 2; ++py)
#pragma unroll
                for (int px = 0; px < 2; ++px)
#pragma unroll
                    for (int dy = 0; dy < 3; ++dy)
#pragma unroll
                        for (int dx = 0; dx < 3; ++dx) {
                            float v = xs[ci][thy * 6 + py * 3 + dy][thx * 6 + px * 3 + dx];
                            xd[py * 2 + px][dy * 3 + dx].f = make_float2(v, v);
                        }
#pragma unroll
            for (int ocp = 0; ocp < 8; ++ocp) {
#pragma unroll
                for (int t9 = 0; t9 < 9; ++t9) {
                    F2U kv;
                    kv.f = ws2[ci][t9][ocp];
#pragma unroll
                    for (int p = 0; p < 4; ++p)
                        asm("fma.rn.f32x2 %0, %1, %2, %0;"
                            : "+l"(acc2[ocp][p].u)
                            : "l"(xd[p][t9].u), "l"(kv.u));
                }
            }
        }
    }

    float* dst = (ocg < 4) ? g_q : g_k;
    const int cbase = (ocg & 3) * 16;
#pragma unroll
    for (int py = 0; py < 2; ++py)
#pragma unroll
        for (int px = 0; px < 2; ++px) {
            int i = tileI * 16 + thy * 2 + py;
            int j = tileJ * 16 + thx * 2 + px;
            float* p = dst + ((b * H2_ + i) * W2_ + j) * C_ + cbase;
#pragma unroll
            for (int ocp = 0; ocp < 8; ++ocp)
                *(float2*)&p[ocp * 2] = acc2[ocp][py * 2 + px].f;
        }
}

// ---------------------------------------------------------------------------
// Kernel Bprep: g_q/g_k (fp32 channel-last) -> bf16 hi/lo channel-major.
// k: [b][co][4096]. q: 5 dj-shifted padded copies [dj][b][ci][68][64]
// (rows 0,1,66,67 never written -> stay zero). grid (64 h, 16 b), block 256.
// ---------------------------------------------------------------------------
__global__ void __launch_bounds__(256) bprep_kernel() {
    const int h = blockIdx.x, b = blockIdx.y;
    __shared__ float sq[64][65], sk[64][65];
    const int tid = threadIdx.x;

#pragma unroll
    for (int i = 0; i < 16; ++i) {
        int idx = tid + i * 256;
        int w = idx >> 6, c = idx & 63;
        sq[w][c] = g_q[((b * H2_ + h) * W2_ + w) * C_ + c];
        sk[w][c] = g_k[((b * H2_ + h) * W2_ + w) * C_ + c];
    }
    __syncthreads();

    // k out (channel-major)
#pragma unroll
    for (int i = 0; i < 16; ++i) {
        int idx = tid + i * 256;
        int c = idx >> 6, w = idx & 63;
        __nv_bfloat16 hh, ll;
        split_bf16(sk[w][c], hh, ll);
        long o = (long)(b * 64 + c) * 4096 + h * 64 + w;
        g_kh[o] = hh;
        g_kl[o] = ll;
    }
    // q out: 5 dj shifts, interior row p = h+2
#pragma unroll
    for (int djx = 0; djx < 5; ++djx) {
        const int sft = djx - 2;
#pragma unroll
        for (int i = 0; i < 16; ++i) {
            int idx = tid + i * 256;
            int c = idx >> 6, w = idx & 63;
            int wsrc = w + sft;
            float v = ((unsigned)wsrc < 64u) ? sq[wsrc][c] : 0.f;
            __nv_bfloat16 hh, ll;
            split_bf16(v, hh, ll);
            long o = (((long)(djx * 16 + b) * 64 + c) * 68 + (h + 2)) * 64 + w;
            g_qh[o] = hh;
            g_ql[o] = ll;
        }
    }
}

// ---------------------------------------------------------------------------
// Kernel B: attn via mma.sync. grid (25 = di*5+dj, 16 b), block 128 (4 warps).
// GEMM M=64(co) x N=64(ci) x K=4096, 3-term bf16 split, K-chunk 128.
// The di shift is a 64-element-aligned offset into the padded q plane.
// smem 64KB: Ah|Al|Bh|Bl 16KB each, 256B rows, XOR-swizzled.
// ---------------------------------------------------------------------------
#define AT_AH 0
#define AT_AL 16384
#define AT_BH 32768
#define AT_BL 49152
#define AT_TOT 65536

__global__ void __launch_bounds__(128) attn_mma_kernel() {
    extern __shared__ char smem[];
    const int dj = blockIdx.x % 5, di = blockIdx.x / 5, b = blockIdx.y;
    const int tid = threadIdx.x, wid = tid >> 5, lid = tid & 31;
    const uint32_t sbase = smem_u32(smem);
    const int mrow = (wid & 1) * 32, ncol = (wid >> 1) * 32;

    float acc[2][4][4];
#pragma unroll
    for (int mt = 0; mt < 2; ++mt)
#pragma unroll
        for (int j = 0; j < 4; ++j)
#pragma unroll
            for (int e = 0; e < 4; ++e) acc[mt][j][e] = 0.f;

    const uint4* __restrict__ kh = (const uint4*)g_kh + (long)b * 64 * 512;
    const uint4* __restrict__ kl = (const uint4*)g_kl + (long)b * 64 * 512;
    const uint4* __restrict__ qh = (const uint4*)g_qh + (long)(dj * 16 + b) * 64 * 544 + di * 8;
    const uint4* __restrict__ ql = (const uint4*)g_ql + (long)(dj * 16 + b) * 64 * 544 + di * 8;

    // hoisted ldmatrix lane components
    const int apart = lid >> 4;                               // A col16 sub
    const int brow_l = (lid & 7) + ((lid >> 4) << 3);         // B row sub
    const int bpart = (lid >> 3) & 1;                         // B col16 sub

    for (int kc = 0; kc < 32; ++kc) {
        __syncthreads();
#pragma unroll
        for (int u = 0; u < 8; ++u) {
            int idx = tid + u * 128;          // 0..1023
            int row = idx >> 4, c16 = idx & 15;
            uint32_t soff = (uint32_t)row * 256u + (uint32_t)((c16 ^ (row & 7)) << 4);
            int gA = row * 512 + kc * 16 + c16;
            int gB = row * 544 + kc * 16 + c16;
            *(uint4*)(smem + AT_AH + soff) = kh[gA];
            *(uint4*)(smem + AT_AL + soff) = kl[gA];
            *(uint4*)(smem + AT_BH + soff) = qh[gB];
            *(uint4*)(smem + AT_BL + soff) = ql[gB];
        }
        __syncthreads();

#pragma unroll
        for (int kk = 0; kk < 8; ++kk) {
            uint32_t ah[2][4], al[2][4], bh[2][4], bl[2][4];
            const int acol = kk * 2 + apart;
            const int bcol = kk * 2 + bpart;
#pragma unroll
            for (int mt = 0; mt < 2; ++mt) {
                int row = mrow + mt * 16 + (lid & 15);
                uint32_t off = (uint32_t)row * 256u + (uint32_t)((acol ^ (row & 7)) << 4);
                ldsm_x4(ah[mt], sbase + AT_AH + off);
                ldsm_x4(al[mt], sbase + AT_AL + off);
            }
#pragma unroll
            for (int nt = 0; nt < 2; ++nt) {
                int row = ncol + nt * 16 + brow_l;
                uint32_t off = (uint32_t)row * 256u + (uint32_t)((bcol ^ (row & 7)) << 4);
                ldsm_x4(bh[nt], sbase + AT_BH + off);
                ldsm_x4(bl[nt], sbase + AT_BL + off);
            }
#pragma unroll
            for (int mt = 0; mt < 2; ++mt)
#pragma unroll
                for (int j = 0; j < 4; ++j) {
                    const uint32_t* bhp = &bh[j >> 1][2 * (j & 1)];
                    mma_bf16(acc[mt][j], ah[mt], bhp);
                    mma_bf16(acc[mt][j], al[mt], bhp);
                    mma_bf16(acc[mt][j], ah[mt], &bl[j >> 1][2 * (j & 1)]);
                }
        }
    }

#pragma unroll
    for (int mt = 0; mt < 2; ++mt)
#pragma unroll
        for (int j = 0; j < 4; ++j)
#pragma unroll
            for (int e = 0; e < 4; ++e) {
                int co = mrow + mt * 16 + (lid >> 2) + ((e >> 1) << 3);
                int ci = ncol + j * 8 + (lid & 3) * 2 + (e & 1);
                g_attn[((b * 64 + co) * 64 + ci) * 25 + di * 5 + dj] = acc[mt][j][e];
            }
}

// ---------------------------------------------------------------------------
// Kernel C1: ak conv (VALID 3x3 over 5x5 attn), transposed output.
// grid (16 cAg, 16 b), block 256 = 4 cA x 64 cB.
// ---------------------------------------------------------------------------
__global__ void __launch_bounds__(256) akconv_kernel(const float* __restrict__ weight) {
    const int cAg = blockIdx.x;
    const int b   = blockIdx.y;
    const int tid = threadIdx.x;
    const int s  = tid >> 6;   // cA sub 0..3
    const int cB = tid & 63;
    const int cA = cAg * 4 + s;

    __shared__ float as4[4][64][25];
    __shared__ float ws[64][73];

    for (int t = tid; t < 6400; t += 256) {
        int a = t / 1600, r = t % 1600;
        as4[a][r / 25][r % 25] = g_attn[(b * 64 + cAg * 4 + a) * 1600 + r];
    }

    float acc[9];
#pragma unroll
    for (int t9 = 0; t9 < 9; ++t9) acc[t9] = 0.f;

    for (int cic = 0; cic < 8; ++cic) {
        __syncthreads();
        for (int t = tid; t < 4608; t += 256) {
            int c2 = t / 72;
            int rr = t % 72;
            ws[c2][rr] = weight[c2 * 576 + (cic * 8 + rr / 9) * 9 + (rr % 9)];
        }
        __syncthreads();
#pragma unroll
        for (int ci = 0; ci < 8; ++ci) {
            float av[25];
#pragma unroll
            for (int p = 0; p < 25; ++p) av[p] = as4[s][cic * 8 + ci][p];
#pragma unroll
            for (int dy = 0; dy < 3; ++dy)
#pragma unroll
                for (int dx = 0; dx < 3; ++dx) {
                    float wv = ws[cB][ci * 9 + dy * 3 + dx];
#pragma unroll
                    for (int ky = 0; ky < 3; ++ky)
#pragma unroll
                        for (int kx = 0; kx < 3; ++kx)
                            acc[ky * 3 + kx] =
                                fmaf(av[(ky + dy) * 5 + (kx + dx)], wv, acc[ky * 3 + kx]);
                }
        }
    }
#pragma unroll
    for (int t9 = 0; t9 < 9; ++t9)
        g_ak[((b * 64 + cB) * 64 + cA) * 9 + t9] = acc[t9];
}

// ---------------------------------------------------------------------------
// Kernel C2: normalize ak, build dynamic kernels -> bf16 hi/lo B-operand tiles
// g_kt_*[b][tap][oc=cB][ci=cA]
// ---------------------------------------------------------------------------
__global__ void __launch_bounds__(64) kern_kernel(const float* __restrict__ weight,
                                                  const float* __restrict__ temperature) {
    const int cB  = blockIdx.x;
    const int b   = blockIdx.y;
    const int tid = threadIdx.x;  // = cA

    const float* ak = g_ak + (b * 64 + cB) * 64 * 9;
    float v[9];
    float ss = 0.f;
#pragma unroll
    for (int t9 = 0; t9 < 9; ++t9) {
        v[t9] = ak[tid * 9 + t9];
        ss = fmaf(v[t9], v[t9], ss);
    }

    __shared__ float red[64];
    red[tid] = ss;
    __syncthreads();
#pragma unroll
    for (int s = 32; s >= 1; s >>= 1) {
        if (tid < s) red[tid] += red[tid + s];
        __syncthreads();
    }
    float nrm = sqrtf(red[0]);
    float scale = temperature[0] / fmaxf(nrm, 1e-12f);

#pragma unroll
    for (int t9 = 0; t9 < 9; ++t9) {
        float vv = weight[(cB * 64 + tid) * 9 + t9] + v[t9] * scale;
        __nv_bfloat16 h, l;
        split_bf16(vv, h, l);
        int o = ((b * 9 + t9) * 64 + cB) * 64 + tid;
        g_kt_hi[o] = h;
        g_kt_lo[o] = l;
    }
}

// ---------------------------------------------------------------------------
// Kernel D: final conv via mma.sync m16n8k16 bf16 (3-term split, fp32 accum)
// ---------------------------------------------------------------------------
#define SM_AHI  0
#define SM_ALO  16384
#define SM_BHI  32768
#define SM_BLO  40960
#define SM_TOT  49152

__global__ void __launch_bounds__(128) final_mma_kernel(float* __restrict__ out) {
    extern __shared__ char smem[];
    const int xt = blockIdx.x, yp = blockIdx.y, b = blockIdx.z;
    const int x0 = xt * 64, y0 = yp * 2;
    const int tid = threadIdx.x, wid = tid >> 5, lid = tid & 31;
    const uint32_t sbase = smem_u32(smem);

    const int r = tid;  // A row filled by this thread (pixel index m)
    const int yy = r >> 6, xx = r & 63;

    float acc[2][8][4];
#pragma unroll
    for (int mt = 0; mt < 2; ++mt)
#pragma unroll
        for (int j = 0; j < 8; ++j)
#pragma unroll
            for (int e = 0; e < 4; ++e) acc[mt][j][e] = 0.f;

    const int arow0 = wid * 32 + (lid & 15);
    const int apart = lid >> 4;
    const int brow0 = (lid & 7) + ((lid >> 4) << 3);
    const int bpart = (lid >> 3) & 1;

    for (int tap = 0; tap < 9; ++tap) {
        const int dy = tap / 3 - 1, dx = tap % 3 - 1;
        __syncthreads();
        {
            int y = y0 + yy + dy, xc = x0 + xx + dx;
            bool ok = ((unsigned)y < (unsigned)H_) && ((unsigned)xc < (unsigned)W_);
            long base = ((long)(b * 192 + y) * 192 + xc) * 8;  // uint4 index
            const uint4* sh = (const uint4*)g_x_hi + base;
            const uint4* sl = (const uint4*)g_x_lo + base;
            const uint4 z = make_uint4(0, 0, 0, 0);
#pragma unroll
            for (int c = 0; c < 8; ++c) {
                uint4 vh = ok ? sh[c] : z;
                uint4 vl = ok ? sl[c] : z;
                uint32_t off = (uint32_t)r * 128u + (uint32_t)((c ^ (r & 7)) * 16);
                *(uint4*)(smem + SM_AHI + off) = vh;
                *(uint4*)(smem + SM_ALO + off) = vl;
            }
        }
        {
            const uint4* kh = (const uint4*)g_kt_hi + (b * 9 + tap) * 512;
            const uint4* kl = (const uint4*)g_kt_lo + (b * 9 + tap) * 512;
#pragma unroll
            for (int i = 0; i < 4; ++i) {
                int idx = tid + i * 128;
                int row = idx >> 3, c = idx & 7;
                uint32_t off = (uint32_t)row * 128u + (uint32_t)((c ^ (row & 7)) * 16);
                *(uint4*)(smem + SM_BHI + off) = kh[idx];
                *(uint4*)(smem + SM_BLO + off) = kl[idx];
            }
        }
        __syncthreads();

#pragma unroll
        for (int kc = 0; kc < 4; ++kc) {
            const int acol = kc * 2 + apart;
            const int bcol = kc * 2 + bpart;
            uint32_t bf[4][4];
            uint32_t ah[2][4], al[2][4];
#pragma unroll
            for (int nt = 0; nt < 4; ++nt) {
                int row = brow0 + nt * 16;
                ldsm_x4(bf[nt], sbase + SM_BHI + row * 128 + ((bcol ^ (row & 7)) << 4));
            }
#pragma unroll
            for (int mt = 0; mt < 2; ++mt) {
                int row = arow0 + mt * 16;
                ldsm_x4(ah[mt], sbase + SM_AHI + row * 128 + ((acol ^ (row & 7)) << 4));
            }
#pragma unroll
            for (int mt = 0; mt < 2; ++mt)
#pragma unroll
                for (int j = 0; j < 8; ++j)
                    mma_bf16(acc[mt][j], ah[mt], &bf[j >> 1][2 * (j & 1)]);
#pragma unroll
            for (int mt = 0; mt < 2; ++mt) {
                int row = arow0 + mt * 16;
                ldsm_x4(al[mt], sbase + SM_ALO + row * 128 + ((acol ^ (row & 7)) << 4));
            }
#pragma unroll
            for (int mt = 0; mt < 2; ++mt)
#pragma unroll
                for (int j = 0; j < 8; ++j)
                    mma_bf16(acc[mt][j], al[mt], &bf[j >> 1][2 * (j & 1)]);
#pragma unroll
            for (int nt = 0; nt < 4; ++nt) {
                int row = brow0 + nt * 16;
                ldsm_x4(bf[nt], sbase + SM_BLO + row * 128 + ((bcol ^ (row & 7)) << 4));
            }
#pragma unroll
            for (int mt = 0; mt < 2; ++mt)
#pragma unroll
                for (int j = 0; j < 8; ++j)
                    mma_bf16(acc[mt][j], ah[mt], &bf[j >> 1][2 * (j & 1)]);
        }
    }

    // epilogue: stage fp32 [m][oc] in smem (stride 66), coalesced store
    __syncthreads();
    float* st = (float*)smem;
#pragma unroll
    for (int mt = 0; mt < 2; ++mt)
#pragma unroll
        for (int j = 0; j < 8; ++j)
#pragma unroll
            for (int e = 0; e < 4; ++e) {
                int row = wid * 32 + mt * 16 + (lid >> 2) + ((e >> 1) << 3);
                int col = j * 8 + (lid & 3) * 2 + (e & 1);
                st[row * 66 + col] = acc[mt][j][e];
            }
    __syncthreads();

    for (int t = tid; t < 8192; t += 128) {
        int oc = t >> 7, m = t & 127;
        float v = fmaxf(st[m * 66 + oc], 0.f);
        out[((long)(b * 64 + oc) * 192 + (y0 + (m >> 6))) * 192 + x0 + (m & 63)] = v;
    }
}

// ---------------------------------------------------------------------------
// Launch
// ---------------------------------------------------------------------------
extern "C" void kernel_launch(void* const* d_in, const int* in_sizes, int n_in,
                              void* d_out, int out_size) {
    const float* x    = (const float*)d_in[0];  // (16,64,192,192)
    const float* w_qk = (const float*)d_in[1];  // (128,64,3,3)
    const float* wgt  = (const float*)d_in[2];  // (64,64,3,3)
    const float* temp = (const float*)d_in[3];  // (1,1,1)
    float* out = (float*)d_out;                 // (16,64,192,192)

    cudaFuncSetAttribute(attn_mma_kernel, cudaFuncAttributeMaxDynamicSharedMemorySize, AT_TOT);

    xcl_kernel<<<dim3(576, 16), 256>>>(x);
    qk_conv_kernel<<<dim3(16, 8, 16), 64>>>(x, w_qk);
    bprep_kernel<<<dim3(64, 16), 256>>>();
    attn_mma_kernel<<<dim3(25, 16), 128, AT_TOT>>>();
    akconv_kernel<<<dim3(16, 16), 256>>>(wgt);
    kern_kernel<<<dim3(64, 16), 64>>>(wgt, temp);
    final_mma_kernel<<<dim3(3, 96, 16), 128, SM_TOT>>>(out);
}

// round 8
// speedup vs baseline: 3.9815x; 2.1774x over previous
#include <cuda_runtime.h>
#include <cuda_bf16.h>
#include <cstdint>
#include <math.h>

// Problem constants
#define B_  16
#define C_  64
#define H_  192
#define W_  192
#define H2_ 64
#define W2_ 64
#define S_  5

// ---------------------------------------------------------------------------
// Scratch buffers (static device globals; zero-initialized at load)
// ---------------------------------------------------------------------------
__device__ float g_q[B_ * H2_ * W2_ * C_];        // channel-last (b,h,w,c)
__device__ float g_k[B_ * H2_ * W2_ * C_];
__device__ float g_attn[B_ * C_ * C_ * S_ * S_];  // [b][co(k-ch)][ci(q-ch)][i][j]
__device__ float g_ak[B_ * C_ * C_ * 9];          // transposed ak (pre-norm)

// bf16 split operands
__device__ __align__(16) __nv_bfloat16 g_x_hi[B_ * H_ * W_ * C_];  // channel-last
__device__ __align__(16) __nv_bfloat16 g_x_lo[B_ * H_ * W_ * C_];
__device__ __align__(16) __nv_bfloat16 g_kt_hi[B_ * 9 * C_ * C_];  // [b][tap][oc][ci]
__device__ __align__(16) __nv_bfloat16 g_kt_lo[B_ * 9 * C_ * C_];
// w_qk repacked: [half(2)][tap(9)][oc(64)][ci(64)]
__device__ __align__(16) __nv_bfloat16 g_wq_hi[2 * 9 * 64 * 64];
__device__ __align__(16) __nv_bfloat16 g_wq_lo[2 * 9 * 64 * 64];
// attn GEMM operands: k channel-major [b][co][4096]
__device__ __align__(16) __nv_bfloat16 g_kh[B_ * C_ * 4096];
__device__ __align__(16) __nv_bfloat16 g_kl[B_ * C_ * 4096];
// q shifted copies: [dj(5)][b][ci][68 rows (2 zero-pad top/bottom)][64]
__device__ __align__(16) __nv_bfloat16 g_qh[5 * B_ * C_ * 68 * 64];
__device__ __align__(16) __nv_bfloat16 g_ql[5 * B_ * C_ * 68 * 64];

__device__ __forceinline__ uint32_t smem_u32(const void* p) {
    uint32_t a;
    asm("{ .reg .u64 t; cvta.to.shared.u64 t, %1; cvt.u32.u64 %0, t; }" : "=r"(a) : "l"(p));
    return a;
}

__device__ __forceinline__ void ldsm_x4(uint32_t* r, uint32_t addr) {
    asm volatile("ldmatrix.sync.aligned.m8n8.x4.shared.b16 {%0,%1,%2,%3}, [%4];"
                 : "=r"(r[0]), "=r"(r[1]), "=r"(r[2]), "=r"(r[3])
                 : "r"(addr));
}

__device__ __forceinline__ void mma_bf16(float* d, const uint32_t* a, const uint32_t* b) {
    asm volatile(
        "mma.sync.aligned.m16n8k16.row.col.f32.bf16.bf16.f32 "
        "{%0,%1,%2,%3}, {%4,%5,%6,%7}, {%8,%9}, {%0,%1,%2,%3};"
        : "+f"(d[0]), "+f"(d[1]), "+f"(d[2]), "+f"(d[3])
        : "r"(a[0]), "r"(a[1]), "r"(a[2]), "r"(a[3]), "r"(b[0]), "r"(b[1]));
}

__device__ __forceinline__ void split_bf16(float v, __nv_bfloat16& h, __nv_bfloat16& l) {
    h = __float2bfloat16(v);
    l = __float2bfloat16(v - __bfloat162float(h));
}

// ---------------------------------------------------------------------------
// Kernel E0: x (fp32 NCHW) -> channel-last bf16 hi/lo.
// Extra grid-y slice (b==16) repacks w_qk into g_wq_hi/lo.
// ---------------------------------------------------------------------------
__global__ void __launch_bounds__(256) xcl_kernel(const float* __restrict__ x,
                                                  const float* __restrict__ w_qk) {
    const int seg = blockIdx.x;
    const int b = blockIdx.y;
    const int tid = threadIdx.x;

    if (b == 16) {
        // w_qk repack: one block per oc_global (seg < 128)
        if (seg < 128) {
            const int half = seg >> 6, oc = seg & 63;
            for (int t = tid; t < 576; t += 256) {
                int ci = t / 9, tap = t % 9;
                __nv_bfloat16 h, l;
                split_bf16(w_qk[(seg * 64 + ci) * 9 + tap], h, l);
                int o = ((half * 9 + tap) * 64 + oc) * 64 + ci;
                g_wq_hi[o] = h;
                g_wq_lo[o] = l;
            }
        }
        return;
    }

    const int y = seg / 3;
    const int x0 = (seg % 3) * 64;
    __shared__ float s[64][65];

#pragma unroll
    for (int i = 0; i < 16; ++i) {
        int idx = tid + i * 256;
        int c = idx >> 6, p = idx & 63;
        s[p][c] = x[((b * 64 + c) * 192 + y) * 192 + x0 + p];
    }
    __syncthreads();
#pragma unroll
    for (int i = 0; i < 16; ++i) {
        int idx = tid + i * 256;
        int p = idx >> 6, c = idx & 63;
        __nv_bfloat16 h, l;
        split_bf16(s[p][c], h, l);
        int o = ((b * 192 + y) * 192 + x0 + p) * 64 + c;
        g_x_hi[o] = h;
        g_x_lo[o] = l;
    }
}

// ---------------------------------------------------------------------------
// Kernel A: qk conv via mma.sync implicit GEMM (stride-3 VALID).
// grid (32 mtiles, 2 half, 16 b), block 128 (4 warps).
// M=128 px (2 i-rows x 64 j), N=64 oc, K=9 taps x 64 ci. 3-term bf16 split.
// Output fp32 channel-last into g_q / g_k (NOT normalized; scale cancels).
// ---------------------------------------------------------------------------
#define QK_AHI  0
#define QK_ALO  16384
#define QK_BHI  32768
#define QK_BLO  40960
#define QK_TOT  49152

__global__ void __launch_bounds__(128) qk_mma_kernel() {
    extern __shared__ char smem[];
    const int mtile = blockIdx.x, half = blockIdx.y, b = blockIdx.z;
    const int i0 = mtile * 2;
    const int tid = threadIdx.x, wid = tid >> 5, lid = tid & 31;
    const uint32_t sbase = smem_u32(smem);

    const int r = tid;                 // A row = pixel m
    const int ri = i0 + (r >> 6), rj = r & 63;

    float acc[2][8][4];
#pragma unroll
    for (int mt = 0; mt < 2; ++mt)
#pragma unroll
        for (int j = 0; j < 8; ++j)
#pragma unroll
            for (int e = 0; e < 4; ++e) acc[mt][j][e] = 0.f;

    const int arow0 = wid * 32 + (lid & 15);
    const int apart = lid >> 4;
    const int brow0 = (lid & 7) + ((lid >> 4) << 3);
    const int bpart = (lid >> 3) & 1;

    for (int tap = 0; tap < 9; ++tap) {
        const int dy = tap / 3, dx = tap % 3;
        __syncthreads();
        // A: pixel (3*ri+dy, 3*rj+dx), 64 ci = 8 uint4, always in bounds
        {
            long base = ((long)(b * 192 + 3 * ri + dy) * 192 + 3 * rj + dx) * 8;
            const uint4* sh = (const uint4*)g_x_hi + base;
            const uint4* sl = (const uint4*)g_x_lo + base;
#pragma unroll
            for (int c = 0; c < 8; ++c) {
                uint32_t off = (uint32_t)r * 128u + (uint32_t)((c ^ (r & 7)) * 16);
                *(uint4*)(smem + QK_AHI + off) = sh[c];
                *(uint4*)(smem + QK_ALO + off) = sl[c];
            }
        }
        // B: g_wq[half][tap] 64x64
        {
            const uint4* kh = (const uint4*)g_wq_hi + (half * 9 + tap) * 512;
            const uint4* kl = (const uint4*)g_wq_lo + (half * 9 + tap) * 512;
#pragma unroll
            for (int i = 0; i < 4; ++i) {
                int idx = tid + i * 128;
                int row = idx >> 3, c = idx & 7;
                uint32_t off = (uint32_t)row * 128u + (uint32_t)((c ^ (row & 7)) * 16);
                *(uint4*)(smem + QK_BHI + off) = kh[idx];
                *(uint4*)(smem + QK_BLO + off) = kl[idx];
            }
        }
        __syncthreads();

#pragma unroll
        for (int kc = 0; kc < 4; ++kc) {
            const int acol = kc * 2 + apart;
            const int bcol = kc * 2 + bpart;
            uint32_t bf[4][4], ah[2][4], al[2][4];
#pragma unroll
            for (int nt = 0; nt < 4; ++nt) {
                int row = brow0 + nt * 16;
                ldsm_x4(bf[nt], sbase + QK_BHI + row * 128 + ((bcol ^ (row & 7)) << 4));
            }
#pragma unroll
            for (int mt = 0; mt < 2; ++mt) {
                int row = arow0 + mt * 16;
                ldsm_x4(ah[mt], sbase + QK_AHI + row * 128 + ((acol ^ (row & 7)) << 4));
            }
#pragma unroll
            for (int mt = 0; mt < 2; ++mt)
#pragma unroll
                for (int j = 0; j < 8; ++j)
                    mma_bf16(acc[mt][j], ah[mt], &bf[j >> 1][2 * (j & 1)]);
#pragma unroll
            for (int mt = 0; mt < 2; ++mt) {
                int row = arow0 + mt * 16;
                ldsm_x4(al[mt], sbase + QK_ALO + row * 128 + ((acol ^ (row & 7)) << 4));
            }
#pragma unroll
            for (int mt = 0; mt < 2; ++mt)
#pragma unroll
                for (int j = 0; j < 8; ++j)
                    mma_bf16(acc[mt][j], al[mt], &bf[j >> 1][2 * (j & 1)]);
#pragma unroll
            for (int nt = 0; nt < 4; ++nt) {
                int row = brow0 + nt * 16;
                ldsm_x4(bf[nt], sbase + QK_BLO + row * 128 + ((bcol ^ (row & 7)) << 4));
            }
#pragma unroll
            for (int mt = 0; mt < 2; ++mt)
#pragma unroll
                for (int j = 0; j < 8; ++j)
                    mma_bf16(acc[mt][j], ah[mt], &bf[j >> 1][2 * (j & 1)]);
        }
    }

    // epilogue: fp32 channel-last stores
    float* dst = half ? g_k : g_q;
#pragma unroll
    for (int mt = 0; mt < 2; ++mt)
#pragma unroll
        for (int j = 0; j < 8; ++j)
#pragma unroll
            for (int e = 0; e < 4; ++e) {
                int m = wid * 32 + mt * 16 + (lid >> 2) + ((e >> 1) << 3);
                int oc = j * 8 + (lid & 3) * 2 + (e & 1);
                int i = i0 + (m >> 6), jx = m & 63;
                dst[((b * H2_ + i) * W2_ + jx) * C_ + oc] = acc[mt][j][e];
            }
}

// ---------------------------------------------------------------------------
// Kernel Bprep: g_q/g_k (fp32 channel-last) -> bf16 hi/lo channel-major.
// ---------------------------------------------------------------------------
__global__ void __launch_bounds__(256) bprep_kernel() {
    const int h = blockIdx.x, b = blockIdx.y;
    __shared__ float sq[64][65], sk[64][65];
    const int tid = threadIdx.x;

#pragma unroll
    for (int i = 0; i < 16; ++i) {
        int idx = tid + i * 256;
        int w = idx >> 6, c = idx & 63;
        sq[w][c] = g_q[((b * H2_ + h) * W2_ + w) * C_ + c];
        sk[w][c] = g_k[((b * H2_ + h) * W2_ + w) * C_ + c];
    }
    __syncthreads();

#pragma unroll
    for (int i = 0; i < 16; ++i) {
        int idx = tid + i * 256;
        int c = idx >> 6, w = idx & 63;
        __nv_bfloat16 hh, ll;
        split_bf16(sk[w][c], hh, ll);
        long o = (long)(b * 64 + c) * 4096 + h * 64 + w;
        g_kh[o] = hh;
        g_kl[o] = ll;
    }
#pragma unroll
    for (int djx = 0; djx < 5; ++djx) {
        const int sft = djx - 2;
#pragma unroll
        for (int i = 0; i < 16; ++i) {
            int idx = tid + i * 256;
            int c = idx >> 6, w = idx & 63;
            int wsrc = w + sft;
            float v = ((unsigned)wsrc < 64u) ? sq[wsrc][c] : 0.f;
            __nv_bfloat16 hh, ll;
            split_bf16(v, hh, ll);
            long o = (((long)(djx * 16 + b) * 64 + c) * 68 + (h + 2)) * 64 + w;
            g_qh[o] = hh;
            g_ql[o] = ll;
        }
    }
}

// ---------------------------------------------------------------------------
// Kernel B: attn via mma.sync. grid (25, 16 b), block 128.
// ---------------------------------------------------------------------------
#define AT_AH 0
#define AT_AL 16384
#define AT_BH 32768
#define AT_BL 49152
#define AT_TOT 65536

__global__ void __launch_bounds__(128) attn_mma_kernel() {
    extern __shared__ char smem[];
    const int dj = blockIdx.x % 5, di = blockIdx.x / 5, b = blockIdx.y;
    const int tid = threadIdx.x, wid = tid >> 5, lid = tid & 31;
    const uint32_t sbase = smem_u32(smem);
    const int mrow = (wid & 1) * 32, ncol = (wid >> 1) * 32;

    float acc[2][4][4];
#pragma unroll
    for (int mt = 0; mt < 2; ++mt)
#pragma unroll
        for (int j = 0; j < 4; ++j)
#pragma unroll
            for (int e = 0; e < 4; ++e) acc[mt][j][e] = 0.f;

    const uint4* __restrict__ kh = (const uint4*)g_kh + (long)b * 64 * 512;
    const uint4* __restrict__ kl = (const uint4*)g_kl + (long)b * 64 * 512;
    const uint4* __restrict__ qh = (const uint4*)g_qh + (long)(dj * 16 + b) * 64 * 544 + di * 8;
    const uint4* __restrict__ ql = (const uint4*)g_ql + (long)(dj * 16 + b) * 64 * 544 + di * 8;

    const int apart = lid >> 4;
    const int brow_l = (lid & 7) + ((lid >> 4) << 3);
    const int bpart = (lid >> 3) & 1;

    for (int kc = 0; kc < 32; ++kc) {
        __syncthreads();
#pragma unroll
        for (int u = 0; u < 8; ++u) {
            int idx = tid + u * 128;
            int row = idx >> 4, c16 = idx & 15;
            uint32_t soff = (uint32_t)row * 256u + (uint32_t)((c16 ^ (row & 7)) << 4);
            int gA = row * 512 + kc * 16 + c16;
            int gB = row * 544 + kc * 16 + c16;
            *(uint4*)(smem + AT_AH + soff) = kh[gA];
            *(uint4*)(smem + AT_AL + soff) = kl[gA];
            *(uint4*)(smem + AT_BH + soff) = qh[gB];
            *(uint4*)(smem + AT_BL + soff) = ql[gB];
        }
        __syncthreads();

#pragma unroll
        for (int kk = 0; kk < 8; ++kk) {
            uint32_t ah[2][4], al[2][4], bh[2][4], bl[2][4];
            const int acol = kk * 2 + apart;
            const int bcol = kk * 2 + bpart;
#pragma unroll
            for (int mt = 0; mt < 2; ++mt) {
                int row = mrow + mt * 16 + (lid & 15);
                uint32_t off = (uint32_t)row * 256u + (uint32_t)((acol ^ (row & 7)) << 4);
                ldsm_x4(ah[mt], sbase + AT_AH + off);
                ldsm_x4(al[mt], sbase + AT_AL + off);
            }
#pragma unroll
            for (int nt = 0; nt < 2; ++nt) {
                int row = ncol + nt * 16 + brow_l;
                uint32_t off = (uint32_t)row * 256u + (uint32_t)((bcol ^ (row & 7)) << 4);
                ldsm_x4(bh[nt], sbase + AT_BH + off);
                ldsm_x4(bl[nt], sbase + AT_BL + off);
            }
#pragma unroll
            for (int mt = 0; mt < 2; ++mt)
#pragma unroll
                for (int j = 0; j < 4; ++j) {
                    const uint32_t* bhp = &bh[j >> 1][2 * (j & 1)];
                    mma_bf16(acc[mt][j], ah[mt], bhp);
                    mma_bf16(acc[mt][j], al[mt], bhp);
                    mma_bf16(acc[mt][j], ah[mt], &bl[j >> 1][2 * (j & 1)]);
                }
        }
    }

#pragma unroll
    for (int mt = 0; mt < 2; ++mt)
#pragma unroll
        for (int j = 0; j < 4; ++j)
#pragma unroll
            for (int e = 0; e < 4; ++e) {
                int co = mrow + mt * 16 + (lid >> 2) + ((e >> 1) << 3);
                int ci = ncol + j * 8 + (lid & 3) * 2 + (e & 1);
                g_attn[((b * 64 + co) * 64 + ci) * 25 + di * 5 + dj] = acc[mt][j][e];
            }
}

// ---------------------------------------------------------------------------
// Kernel C1: ak conv (VALID 3x3 over 5x5 attn), transposed output.
// ---------------------------------------------------------------------------
__global__ void __launch_bounds__(256) akconv_kernel(const float* __restrict__ weight) {
    const int cAg = blockIdx.x;
    const int b   = blockIdx.y;
    const int tid = threadIdx.x;
    const int s  = tid >> 6;
    const int cB = tid & 63;
    const int cA = cAg * 4 + s;

    __shared__ float as4[4][64][25];
    __shared__ float ws[64][73];

    for (int t = tid; t < 6400; t += 256) {
        int a = t / 1600, r = t % 1600;
        as4[a][r / 25][r % 25] = g_attn[(b * 64 + cAg * 4 + a) * 1600 + r];
    }

    float acc[9];
#pragma unroll
    for (int t9 = 0; t9 < 9; ++t9) acc[t9] = 0.f;

    for (int cic = 0; cic < 8; ++cic) {
        __syncthreads();
        for (int t = tid; t < 4608; t += 256) {
            int c2 = t / 72;
            int rr = t % 72;
            ws[c2][rr] = weight[c2 * 576 + (cic * 8 + rr / 9) * 9 + (rr % 9)];
        }
        __syncthreads();
#pragma unroll
        for (int ci = 0; ci < 8; ++ci) {
            float av[25];
#pragma unroll
            for (int p = 0; p < 25; ++p) av[p] = as4[s][cic * 8 + ci][p];
#pragma unroll
            for (int dy = 0; dy < 3; ++dy)
#pragma unroll
                for (int dx = 0; dx < 3; ++dx) {
                    float wv = ws[cB][ci * 9 + dy * 3 + dx];
#pragma unroll
                    for (int ky = 0; ky < 3; ++ky)
#pragma unroll
                        for (int kx = 0; kx < 3; ++kx)
                            acc[ky * 3 + kx] =
                                fmaf(av[(ky + dy) * 5 + (kx + dx)], wv, acc[ky * 3 + kx]);
                }
        }
    }
#pragma unroll
    for (int t9 = 0; t9 < 9; ++t9)
        g_ak[((b * 64 + cB) * 64 + cA) * 9 + t9] = acc[t9];
}

// ---------------------------------------------------------------------------
// Kernel C2: normalize ak, build dynamic kernels -> bf16 hi/lo B tiles
// ---------------------------------------------------------------------------
__global__ void __launch_bounds__(64) kern_kernel(const float* __restrict__ weight,
                                                  const float* __restrict__ temperature) {
    const int cB  = blockIdx.x;
    const int b   = blockIdx.y;
    const int tid = threadIdx.x;  // = cA

    const float* ak = g_ak + (b * 64 + cB) * 64 * 9;
    float v[9];
    float ss = 0.f;
#pragma unroll
    for (int t9 = 0; t9 < 9; ++t9) {
        v[t9] = ak[tid * 9 + t9];
        ss = fmaf(v[t9], v[t9], ss);
    }

    __shared__ float red[64];
    red[tid] = ss;
    __syncthreads();
#pragma unroll
    for (int s = 32; s >= 1; s >>= 1) {
        if (tid < s) red[tid] += red[tid + s];
        __syncthreads();
    }
    float nrm = sqrtf(red[0]);
    float scale = temperature[0] / fmaxf(nrm, 1e-12f);

#pragma unroll
    for (int t9 = 0; t9 < 9; ++t9) {
        float vv = weight[(cB * 64 + tid) * 9 + t9] + v[t9] * scale;
        __nv_bfloat16 h, l;
        split_bf16(vv, h, l);
        int o = ((b * 9 + t9) * 64 + cB) * 64 + tid;
        g_kt_hi[o] = h;
        g_kt_lo[o] = l;
    }
}

// ---------------------------------------------------------------------------
// Kernel D: final conv via mma.sync. SINGLE A-halo fill (4x66 px rows, all 9
// taps addressed by ldmatrix row shifts) + double-buffered per-tap B.
// smem: A hi 33792 | A lo 33792 | B 2x(hi 8192 + lo 8192) = 100352 B.
// ---------------------------------------------------------------------------
#define DA_HI  0
#define DA_LO  33792
#define DB     67584
#define D_TOT  100352

__global__ void __launch_bounds__(128) final_mma_kernel(float* __restrict__ out) {
    extern __shared__ char smem[];
    const int xt = blockIdx.x, yp = blockIdx.y, b = blockIdx.z;
    const int x0 = xt * 64, y0 = yp * 2;
    const int tid = threadIdx.x, wid = tid >> 5, lid = tid & 31;
    const uint32_t sbase = smem_u32(smem);

    float acc[2][8][4];
#pragma unroll
    for (int mt = 0; mt < 2; ++mt)
#pragma unroll
        for (int j = 0; j < 8; ++j)
#pragma unroll
            for (int e = 0; e < 4; ++e) acc[mt][j][e] = 0.f;

    // ldmatrix lane components
    const int apart = lid >> 4;
    const int brow0 = (lid & 7) + ((lid >> 4) << 3);
    const int bpart = (lid >> 3) & 1;
    // per-mt halo-row base for this lane: pixel m = wid*32 + mt*16 + (lid&15)
    int hra[2];
#pragma unroll
    for (int mt = 0; mt < 2; ++mt) {
        int m = wid * 32 + mt * 16 + (lid & 15);
        hra[mt] = ((m >> 6) + 1) * 66 + (m & 63) + 1;
    }

    // ---- one-time A halo fill: 264 rows (4y x 66x), zero OOB ----
    for (int hr = tid; hr < 264; hr += 128) {
        int hy = hr / 66, hx = hr % 66;
        int y = y0 - 1 + hy, xg = x0 - 1 + hx;
        bool ok = ((unsigned)y < (unsigned)H_) && ((unsigned)xg < (unsigned)W_);
        long base = ((long)(b * 192 + y) * 192 + xg) * 8;
        const uint4* sh = (const uint4*)g_x_hi + base;
        const uint4* sl = (const uint4*)g_x_lo + base;
        const uint4 z = make_uint4(0, 0, 0, 0);
#pragma unroll
        for (int c = 0; c < 8; ++c) {
            uint32_t off = (uint32_t)hr * 128u + (uint32_t)((c ^ (hr & 7)) * 16);
            *(uint4*)(smem + DA_HI + off) = ok ? sh[c] : z;
            *(uint4*)(smem + DA_LO + off) = ok ? sl[c] : z;
        }
    }
    // ---- B tap0 into buffer 0 ----
    {
        const uint4* kh = (const uint4*)g_kt_hi + (b * 9 + 0) * 512;
        const uint4* kl = (const uint4*)g_kt_lo + (b * 9 + 0) * 512;
#pragma unroll
        for (int i = 0; i < 4; ++i) {
            int idx = tid + i * 128;
            int row = idx >> 3, c = idx & 7;
            uint32_t off = (uint32_t)row * 128u + (uint32_t)((c ^ (row & 7)) * 16);
            *(uint4*)(smem + DB + off) = kh[idx];
            *(uint4*)(smem + DB + 8192 + off) = kl[idx];
        }
    }
    __syncthreads();

    for (int tap = 0; tap < 9; ++tap) {
        // prefetch next tap's B into the other buffer
        if (tap < 8) {
            const int nb = (tap + 1) & 1;
            const uint4* kh = (const uint4*)g_kt_hi + (b * 9 + tap + 1) * 512;
            const uint4* kl = (const uint4*)g_kt_lo + (b * 9 + tap + 1) * 512;
#pragma unroll
            for (int i = 0; i < 4; ++i) {
                int idx = tid + i * 128;
                int row = idx >> 3, c = idx & 7;
                uint32_t off = (uint32_t)row * 128u + (uint32_t)((c ^ (row & 7)) * 16);
                *(uint4*)(smem + DB + nb * 16384 + off) = kh[idx];
                *(uint4*)(smem + DB + nb * 16384 + 8192 + off) = kl[idx];
            }
        }

        const int dOff = (tap / 3 - 1) * 66 + (tap % 3 - 1);
        const uint32_t sbh = sbase + DB + (uint32_t)(tap & 1) * 16384u;
        const uint32_t sbl = sbh + 8192u;

#pragma unroll
        for (int kc = 0; kc < 4; ++kc) {
            const int acol = kc * 2 + apart;
            const int bcol = kc * 2 + bpart;
            uint32_t bf[4][4], ah[2][4], al[2][4];
#pragma unroll
            for (int nt = 0; nt < 4; ++nt) {
                int row = brow0 + nt * 16;
                ldsm_x4(bf[nt], sbh + row * 128 + ((bcol ^ (row & 7)) << 4));
            }
#pragma unroll
            for (int mt = 0; mt < 2; ++mt) {
                int hr = hra[mt] + dOff;
                uint32_t off = (uint32_t)hr * 128u + (uint32_t)((acol ^ (hr & 7)) << 4);
                ldsm_x4(ah[mt], sbase + DA_HI + off);
                ldsm_x4(al[mt], sbase + DA_LO + off);
            }
#pragma unroll
            for (int mt = 0; mt < 2; ++mt)
#pragma unroll
                for (int j = 0; j < 8; ++j) {
                    const uint32_t* bhp = &bf[j >> 1][2 * (j & 1)];
                    mma_bf16(acc[mt][j], ah[mt], bhp);
                    mma_bf16(acc[mt][j], al[mt], bhp);
                }
#pragma unroll
            for (int nt = 0; nt < 4; ++nt) {
                int row = brow0 + nt * 16;
                ldsm_x4(bf[nt], sbl + row * 128 + ((bcol ^ (row & 7)) << 4));
            }
#pragma unroll
            for (int mt = 0; mt < 2; ++mt)
#pragma unroll
                for (int j = 0; j < 8; ++j)
                    mma_bf16(acc[mt][j], ah[mt], &bf[j >> 1][2 * (j & 1)]);
        }
        __syncthreads();  // B prefetch complete + safe to overwrite read buffer
    }

    // epilogue: stage fp32 [m][oc] in smem (reuse A region), coalesced store
    float* st = (float*)smem;
#pragma unroll
    for (int mt = 0; mt < 2; ++mt)
#pragma unroll
        for (int j = 0; j < 8; ++j)
#pragma unroll
            for (int e = 0; e < 4; ++e) {
                int row = wid * 32 + mt * 16 + (lid >> 2) + ((e >> 1) << 3);
                int col = j * 8 + (lid & 3) * 2 + (e & 1);
                st[row * 66 + col] = acc[mt][j][e];
            }
    __syncthreads();

    for (int t = tid; t < 8192; t += 128) {
        int oc = t >> 7, m = t & 127;
        float v = fmaxf(st[m * 66 + oc], 0.f);
        out[((long)(b * 64 + oc) * 192 + (y0 + (m >> 6))) * 192 + x0 + (m & 63)] = v;
    }
}

// ---------------------------------------------------------------------------
// Launch
// ---------------------------------------------------------------------------
extern "C" void kernel_launch(void* const* d_in, const int* in_sizes, int n_in,
                              void* d_out, int out_size) {
    const float* x    = (const float*)d_in[0];  // (16,64,192,192)
    const float* w_qk = (const float*)d_in[1];  // (128,64,3,3)
    const float* wgt  = (const float*)d_in[2];  // (64,64,3,3)
    const float* temp = (const float*)d_in[3];  // (1,1,1)
    float* out = (float*)d_out;                 // (16,64,192,192)

    cudaFuncSetAttribute(attn_mma_kernel, cudaFuncAttributeMaxDynamicSharedMemorySize, AT_TOT);
    cudaFuncSetAttribute(final_mma_kernel, cudaFuncAttributeMaxDynamicSharedMemorySize, D_TOT);

    xcl_kernel<<<dim3(576, 17), 256>>>(x, w_qk);
    qk_mma_kernel<<<dim3(32, 2, 16), 128, QK_TOT>>>();
    bprep_kernel<<<dim3(64, 16), 256>>>();
    attn_mma_kernel<<<dim3(25, 16), 128, AT_TOT>>>();
    akconv_kernel<<<dim3(16, 16), 256>>>(wgt);
    kern_kernel<<<dim3(64, 16), 64>>>(wgt, temp);
    final_mma_kernel<<<dim3(3, 96, 16), 128, D_TOT>>>(out);
}

// round 10
// speedup vs baseline: 4.7836x; 1.2015x over previous
#include <cuda_runtime.h>
#include <cuda_bf16.h>
#include <cstdint>
#include <math.h>

// Problem constants
#define B_  16
#define C_  64
#define H_  192
#define W_  192
#define H2_ 64
#define W2_ 64
#define S_  5

// ---------------------------------------------------------------------------
// Scratch buffers (static device globals; zero-initialized at load)
// ---------------------------------------------------------------------------
__device__ float g_attn[B_ * C_ * C_ * S_ * S_];  // [b][co(k-ch)][ci(q-ch)][i][j]
__device__ float g_ak[B_ * C_ * C_ * 9];          // transposed ak (pre-norm)

// bf16 split operands
__device__ __align__(16) __nv_bfloat16 g_x_hi[B_ * H_ * W_ * C_];  // channel-last
__device__ __align__(16) __nv_bfloat16 g_x_lo[B_ * H_ * W_ * C_];
__device__ __align__(16) __nv_bfloat16 g_kt_hi[B_ * 9 * C_ * C_];  // [b][tap][oc][ci]
__device__ __align__(16) __nv_bfloat16 g_kt_lo[B_ * 9 * C_ * C_];
// w_qk repacked: [half(2)][tap(9)][oc(64)][ci(64)]
__device__ __align__(16) __nv_bfloat16 g_wq_hi[2 * 9 * 64 * 64];
__device__ __align__(16) __nv_bfloat16 g_wq_lo[2 * 9 * 64 * 64];
// attn GEMM operands: k channel-major [b][co][4096]
__device__ __align__(16) __nv_bfloat16 g_kh[B_ * C_ * 4096];
__device__ __align__(16) __nv_bfloat16 g_kl[B_ * C_ * 4096];
// q shifted copies: [dj(5)][b][ci][68 rows (2 zero-pad top/bottom)][64]
__device__ __align__(16) __nv_bfloat16 g_qh[5 * B_ * C_ * 68 * 64];
__device__ __align__(16) __nv_bfloat16 g_ql[5 * B_ * C_ * 68 * 64];

__device__ __forceinline__ uint32_t smem_u32(const void* p) {
    uint32_t a;
    asm("{ .reg .u64 t; cvta.to.shared.u64 t, %1; cvt.u32.u64 %0, t; }" : "=r"(a) : "l"(p));
    return a;
}

__device__ __forceinline__ void ldsm_x4(uint32_t* r, uint32_t addr) {
    asm volatile("ldmatrix.sync.aligned.m8n8.x4.shared.b16 {%0,%1,%2,%3}, [%4];"
                 : "=r"(r[0]), "=r"(r[1]), "=r"(r[2]), "=r"(r[3])
                 : "r"(addr));
}

__device__ __forceinline__ void mma_bf16(float* d, const uint32_t* a, const uint32_t* b) {
    asm volatile(
        "mma.sync.aligned.m16n8k16.row.col.f32.bf16.bf16.f32 "
        "{%0,%1,%2,%3}, {%4,%5,%6,%7}, {%8,%9}, {%0,%1,%2,%3};"
        : "+f"(d[0]), "+f"(d[1]), "+f"(d[2]), "+f"(d[3])
        : "r"(a[0]), "r"(a[1]), "r"(a[2]), "r"(a[3]), "r"(b[0]), "r"(b[1]));
}

#define CP16(dst, src) \
    asm volatile("cp.async.cg.shared.global [%0], [%1], 16;" ::"r"(dst), "l"(src))
#define CP_COMMIT() asm volatile("cp.async.commit_group;" ::: "memory")
#define CP_WAIT(N) asm volatile("cp.async.wait_group %0;" ::"n"(N) : "memory")

__device__ __forceinline__ void split_bf16(float v, __nv_bfloat16& h, __nv_bfloat16& l) {
    h = __float2bfloat16(v);
    l = __float2bfloat16(v - __bfloat162float(h));
}

// ---------------------------------------------------------------------------
// Kernel E0: x (fp32 NCHW) -> channel-last bf16 hi/lo; b==16 repacks w_qk.
// ---------------------------------------------------------------------------
__global__ void __launch_bounds__(256) xcl_kernel(const float* __restrict__ x,
                                                  const float* __restrict__ w_qk) {
    const int seg = blockIdx.x;
    const int b = blockIdx.y;
    const int tid = threadIdx.x;

    if (b == 16) {
        if (seg < 128) {
            const int half = seg >> 6, oc = seg & 63;
            for (int t = tid; t < 576; t += 256) {
                int ci = t / 9, tap = t % 9;
                __nv_bfloat16 h, l;
                split_bf16(w_qk[(seg * 64 + ci) * 9 + tap], h, l);
                int o = ((half * 9 + tap) * 64 + oc) * 64 + ci;
                g_wq_hi[o] = h;
                g_wq_lo[o] = l;
            }
        }
        return;
    }

    const int y = seg / 3;
    const int x0 = (seg % 3) * 64;
    __shared__ float s[64][65];

#pragma unroll
    for (int i = 0; i < 16; ++i) {
        int idx = tid + i * 256;
        int c = idx >> 6, p = idx & 63;
        s[p][c] = x[((b * 64 + c) * 192 + y) * 192 + x0 + p];
    }
    __syncthreads();
#pragma unroll
    for (int i = 0; i < 16; ++i) {
        int idx = tid + i * 256;
        int p = idx >> 6, c = idx & 63;
        __nv_bfloat16 h, l;
        split_bf16(s[p][c], h, l);
        int o = ((b * 192 + y) * 192 + x0 + p) * 64 + c;
        g_x_hi[o] = h;
        g_x_lo[o] = l;
    }
}

// ---------------------------------------------------------------------------
// Kernel A: qk conv via mma.sync (stride-3), cp.async tap double-buffer.
// FUSED epilogue: writes attn operands (g_kh/g_kl, 5x dj-shifted g_qh/g_ql)
// directly as bf16 hi/lo. grid (32 mtiles, 2 half, 16 b), 128 thr.
// smem: 2 x (Ah16K|Al16K|Bh8K|Bl8K) = 96KB.
// ---------------------------------------------------------------------------
#define QK_BUF  49152
#define QK_TOT  98304

__global__ void __launch_bounds__(128) qk_mma_kernel() {
    extern __shared__ char smem[];
    const int mtile = blockIdx.x, half = blockIdx.y, b = blockIdx.z;
    const int i0 = mtile * 2;
    const int tid = threadIdx.x, wid = tid >> 5, lid = tid & 31;
    const uint32_t sbase = smem_u32(smem);

    const int r = tid;
    const int ri = i0 + (r >> 6), rj = r & 63;

    float acc[2][8][4];
#pragma unroll
    for (int mt = 0; mt < 2; ++mt)
#pragma unroll
        for (int j = 0; j < 8; ++j)
#pragma unroll
            for (int e = 0; e < 4; ++e) acc[mt][j][e] = 0.f;

    const int arow0 = wid * 32 + (lid & 15);
    const int apart = lid >> 4;
    const int brow0 = (lid & 7) + ((lid >> 4) << 3);
    const int bpart = (lid >> 3) & 1;

    auto prefetch = [&](int tap, int bi) {
        uint32_t sb = sbase + (uint32_t)bi * QK_BUF;
        const int dy = tap / 3, dx = tap % 3;
        long abase = ((long)(b * 192 + 3 * ri + dy) * 192 + 3 * rj + dx) * 8;
        const uint4* sh = (const uint4*)g_x_hi + abase;
        const uint4* sl = (const uint4*)g_x_lo + abase;
#pragma unroll
        for (int c = 0; c < 8; ++c) {
            uint32_t off = (uint32_t)r * 128u + (uint32_t)((c ^ (r & 7)) << 4);
            CP16(sb + off, sh + c);
            CP16(sb + 16384 + off, sl + c);
        }
        const uint4* wh = (const uint4*)g_wq_hi + (half * 9 + tap) * 512;
        const uint4* wl = (const uint4*)g_wq_lo + (half * 9 + tap) * 512;
#pragma unroll
        for (int i = 0; i < 4; ++i) {
            int idx = tid + i * 128;
            int row = idx >> 3, c = idx & 7;
            uint32_t off = (uint32_t)row * 128u + (uint32_t)((c ^ (row & 7)) << 4);
            CP16(sb + 32768 + off, wh + idx);
            CP16(sb + 40960 + off, wl + idx);
        }
    };

    prefetch(0, 0);
    CP_COMMIT();

    for (int tap = 0; tap < 9; ++tap) {
        // TAIL FIX: when no new group is committed (last tap), wait for ALL.
        if (tap < 8) {
            prefetch(tap + 1, (tap + 1) & 1);
            CP_COMMIT();
            CP_WAIT(1);  // tap's group done; tap+1's may still be in flight
        } else {
            CP_WAIT(0);  // last tap: its own group must complete
        }
        __syncthreads();

        const uint32_t sb = sbase + (uint32_t)(tap & 1) * QK_BUF;
#pragma unroll
        for (int kc = 0; kc < 4; ++kc) {
            const int acol = kc * 2 + apart;
            const int bcol = kc * 2 + bpart;
            uint32_t bf[4][4], ah[2][4], al[2][4];
#pragma unroll
            for (int nt = 0; nt < 4; ++nt) {
                int row = brow0 + nt * 16;
                ldsm_x4(bf[nt], sb + 32768 + row * 128 + ((bcol ^ (row & 7)) << 4));
            }
#pragma unroll
            for (int mt = 0; mt < 2; ++mt) {
                int row = arow0 + mt * 16;
                uint32_t off = row * 128 + ((acol ^ (row & 7)) << 4);
                ldsm_x4(ah[mt], sb + off);
                ldsm_x4(al[mt], sb + 16384 + off);
            }
#pragma unroll
            for (int mt = 0; mt < 2; ++mt)
#pragma unroll
                for (int j = 0; j < 8; ++j) {
                    const uint32_t* bhp = &bf[j >> 1][2 * (j & 1)];
                    mma_bf16(acc[mt][j], ah[mt], bhp);
                    mma_bf16(acc[mt][j], al[mt], bhp);
                }
#pragma unroll
            for (int nt = 0; nt < 4; ++nt) {
                int row = brow0 + nt * 16;
                ldsm_x4(bf[nt], sb + 40960 + row * 128 + ((bcol ^ (row & 7)) << 4));
            }
#pragma unroll
            for (int mt = 0; mt < 2; ++mt)
#pragma unroll
                for (int j = 0; j < 8; ++j)
                    mma_bf16(acc[mt][j], ah[mt], &bf[j >> 1][2 * (j & 1)]);
        }
        __syncthreads();
    }

    // ---- fused epilogue: stage fp32 [m][ch] (stride 65), emit bf16 operands
    float* st = (float*)smem;
#pragma unroll
    for (int mt = 0; mt < 2; ++mt)
#pragma unroll
        for (int j = 0; j < 8; ++j)
#pragma unroll
            for (int e = 0; e < 4; ++e) {
                int m = wid * 32 + mt * 16 + (lid >> 2) + ((e >> 1) << 3);
                int col = j * 8 + (lid & 3) * 2 + (e & 1);
                st[m * 65 + col] = acc[mt][j][e];
            }
    __syncthreads();

    if (half) {
        // k: channel-major [b][co][h][w]
        for (int t = tid; t < 8192; t += 128) {
            int co = t >> 7, m = t & 127;
            int h = i0 + (m >> 6), w = m & 63;
            __nv_bfloat16 hh, ll;
            split_bf16(st[m * 65 + co], hh, ll);
            long o = (long)(b * 64 + co) * 4096 + h * 64 + w;
            g_kh[o] = hh;
            g_kl[o] = ll;
        }
    } else {
        // q: 5 dj-shifted padded copies
        for (int dj = 0; dj < 5; ++dj) {
            for (int t = tid; t < 8192; t += 128) {
                int ci = t >> 7, m = t & 127;
                int h = i0 + (m >> 6), w = m & 63;
                int wsrc = w + dj - 2;
                float v = ((unsigned)wsrc < 64u) ? st[((m >> 6) * 64 + wsrc) * 65 + ci] : 0.f;
                __nv_bfloat16 hh, ll;
                split_bf16(v, hh, ll);
                long o = (((long)(dj * 16 + b) * 64 + ci) * 68 + (h + 2)) * 64 + w;
                g_qh[o] = hh;
                g_ql[o] = ll;
            }
        }
    }
}

// ---------------------------------------------------------------------------
// Kernel B: attn via mma.sync, K-chunk 64, cp.async double buffer.
// grid (25, 16 b), 128 thr. smem 2 x (Ah8K|Al8K|Bh8K|Bl8K) = 64KB.
// ---------------------------------------------------------------------------
#define AT_BUF 32768
#define AT_TOT 65536

__global__ void __launch_bounds__(128) attn_mma_kernel() {
    extern __shared__ char smem[];
    const int dj = blockIdx.x % 5, di = blockIdx.x / 5, b = blockIdx.y;
    const int tid = threadIdx.x, wid = tid >> 5, lid = tid & 31;
    const uint32_t sbase = smem_u32(smem);
    const int mrow = (wid & 1) * 32, ncol = (wid >> 1) * 32;

    float acc[2][4][4];
#pragma unroll
    for (int mt = 0; mt < 2; ++mt)
#pragma unroll
        for (int j = 0; j < 4; ++j)
#pragma unroll
            for (int e = 0; e < 4; ++e) acc[mt][j][e] = 0.f;

    const uint4* __restrict__ kh = (const uint4*)g_kh + (long)b * 64 * 512;
    const uint4* __restrict__ kl = (const uint4*)g_kl + (long)b * 64 * 512;
    const uint4* __restrict__ qh = (const uint4*)g_qh + (long)(dj * 16 + b) * 64 * 544 + di * 8;
    const uint4* __restrict__ ql = (const uint4*)g_ql + (long)(dj * 16 + b) * 64 * 544 + di * 8;

    const int apart = lid >> 4;
    const int brow_l = (lid & 7) + ((lid >> 4) << 3);
    const int bpart = (lid >> 3) & 1;

    auto prefetch = [&](int kc, int bi) {
        uint32_t sb = sbase + (uint32_t)bi * AT_BUF;
#pragma unroll
        for (int a = 0; a < 4; ++a) {
            const uint4* gp = (a == 0) ? kh : (a == 1) ? kl : (a == 2) ? qh : ql;
            const int stride = (a < 2) ? 512 : 544;
#pragma unroll
            for (int u = 0; u < 4; ++u) {
                int idx = tid + u * 128;  // 0..511
                int row = idx >> 3, c = idx & 7;
                uint32_t off = (uint32_t)a * 8192u + (uint32_t)row * 128u +
                               (uint32_t)((c ^ (row & 7)) << 4);
                CP16(sb + off, gp + (long)row * stride + kc * 8 + c);
            }
        }
    };

    prefetch(0, 0);
    CP_COMMIT();

    for (int kc = 0; kc < 64; ++kc) {
        // TAIL FIX: last chunk commits nothing -> must wait for ALL groups.
        if (kc < 63) {
            prefetch(kc + 1, (kc + 1) & 1);
            CP_COMMIT();
            CP_WAIT(1);
        } else {
            CP_WAIT(0);
        }
        __syncthreads();

        const uint32_t sb = sbase + (uint32_t)(kc & 1) * AT_BUF;
#pragma unroll
        for (int kk = 0; kk < 4; ++kk) {
            uint32_t ah[2][4], al[2][4], bh[2][4], bl[2][4];
            const int acol = kk * 2 + apart;
            const int bcol = kk * 2 + bpart;
#pragma unroll
            for (int mt = 0; mt < 2; ++mt) {
                int row = mrow + mt * 16 + (lid & 15);
                uint32_t off = (uint32_t)row * 128u + (uint32_t)((acol ^ (row & 7)) << 4);
                ldsm_x4(ah[mt], sb + off);
                ldsm_x4(al[mt], sb + 8192 + off);
            }
#pragma unroll
            for (int nt = 0; nt < 2; ++nt) {
                int row = ncol + nt * 16 + brow_l;
                uint32_t off = (uint32_t)row * 128u + (uint32_t)((bcol ^ (row & 7)) << 4);
                ldsm_x4(bh[nt], sb + 16384 + off);
                ldsm_x4(bl[nt], sb + 24576 + off);
            }
#pragma unroll
            for (int mt = 0; mt < 2; ++mt)
#pragma unroll
                for (int j = 0; j < 4; ++j) {
                    const uint32_t* bhp = &bh[j >> 1][2 * (j & 1)];
                    mma_bf16(acc[mt][j], ah[mt], bhp);
                    mma_bf16(acc[mt][j], al[mt], bhp);
                    mma_bf16(acc[mt][j], ah[mt], &bl[j >> 1][2 * (j & 1)]);
                }
        }
        __syncthreads();
    }

#pragma unroll
    for (int mt = 0; mt < 2; ++mt)
#pragma unroll
        for (int j = 0; j < 4; ++j)
#pragma unroll
            for (int e = 0; e < 4; ++e) {
                int co = mrow + mt * 16 + (lid >> 2) + ((e >> 1) << 3);
                int ci = ncol + j * 8 + (lid & 3) * 2 + (e & 1);
                g_attn[((b * 64 + co) * 64 + ci) * 25 + di * 5 + dj] = acc[mt][j][e];
            }
}

// ---------------------------------------------------------------------------
// Kernel C1: ak conv (VALID 3x3 over 5x5 attn), transposed output.
// ---------------------------------------------------------------------------
__global__ void __launch_bounds__(256) akconv_kernel(const float* __restrict__ weight) {
    const int cAg = blockIdx.x;
    const int b   = blockIdx.y;
    const int tid = threadIdx.x;
    const int s  = tid >> 6;
    const int cB = tid & 63;
    const int cA = cAg * 4 + s;

    __shared__ float as4[4][64][25];
    __shared__ float ws[64][73];

    for (int t = tid; t < 6400; t += 256) {
        int a = t / 1600, r = t % 1600;
        as4[a][r / 25][r % 25] = g_attn[(b * 64 + cAg * 4 + a) * 1600 + r];
    }

    float acc[9];
#pragma unroll
    for (int t9 = 0; t9 < 9; ++t9) acc[t9] = 0.f;

    for (int cic = 0; cic < 8; ++cic) {
        __syncthreads();
        for (int t = tid; t < 4608; t += 256) {
            int c2 = t / 72;
            int rr = t % 72;
            ws[c2][rr] = weight[c2 * 576 + (cic * 8 + rr / 9) * 9 + (rr % 9)];
        }
        __syncthreads();
#pragma unroll
        for (int ci = 0; ci < 8; ++ci) {
            float av[25];
#pragma unroll
            for (int p = 0; p < 25; ++p) av[p] = as4[s][cic * 8 + ci][p];
#pragma unroll
            for (int dy = 0; dy < 3; ++dy)
#pragma unroll
                for (int dx = 0; dx < 3; ++dx) {
                    float wv = ws[cB][ci * 9 + dy * 3 + dx];
#pragma unroll
                    for (int ky = 0; ky < 3; ++ky)
#pragma unroll
                        for (int kx = 0; kx < 3; ++kx)
                            acc[ky * 3 + kx] =
                                fmaf(av[(ky + dy) * 5 + (kx + dx)], wv, acc[ky * 3 + kx]);
                }
        }
    }
#pragma unroll
    for (int t9 = 0; t9 < 9; ++t9)
        g_ak[((b * 64 + cB) * 64 + cA) * 9 + t9] = acc[t9];
}

// ---------------------------------------------------------------------------
// Kernel C2: normalize ak, build dynamic kernels -> bf16 hi/lo B tiles
// ---------------------------------------------------------------------------
__global__ void __launch_bounds__(64) kern_kernel(const float* __restrict__ weight,
                                                  const float* __restrict__ temperature) {
    const int cB  = blockIdx.x;
    const int b   = blockIdx.y;
    const int tid = threadIdx.x;  // = cA

    const float* ak = g_ak + (b * 64 + cB) * 64 * 9;
    float v[9];
    float ss = 0.f;
#pragma unroll
    for (int t9 = 0; t9 < 9; ++t9) {
        v[t9] = ak[tid * 9 + t9];
        ss = fmaf(v[t9], v[t9], ss);
    }

    __shared__ float red[64];
    red[tid] = ss;
    __syncthreads();
#pragma unroll
    for (int s = 32; s >= 1; s >>= 1) {
        if (tid < s) red[tid] += red[tid + s];
        __syncthreads();
    }
    float nrm = sqrtf(red[0]);
    float scale = temperature[0] / fmaxf(nrm, 1e-12f);

#pragma unroll
    for (int t9 = 0; t9 < 9; ++t9) {
        float vv = weight[(cB * 64 + tid) * 9 + t9] + v[t9] * scale;
        __nv_bfloat16 h, l;
        split_bf16(vv, h, l);
        int o = ((b * 9 + t9) * 64 + cB) * 64 + tid;
        g_kt_hi[o] = h;
        g_kt_lo[o] = l;
    }
}

// ---------------------------------------------------------------------------
// Kernel D: final conv via mma.sync, M=256 (4 y-rows x 64 x), 256 threads.
// Single A halo fill (6x66 rows) serves all 9 taps; B cp.async double-buffer.
// smem: Ahi 50688 | Alo 50688 | B 2x16384 = 134144.
// ---------------------------------------------------------------------------
#define DA_HI  0
#define DA_LO  50688
#define DB     101376
#define D_TOT  134144

__global__ void __launch_bounds__(256) final_mma_kernel(float* __restrict__ out) {
    extern __shared__ char smem[];
    const int xt = blockIdx.x, yp = blockIdx.y, b = blockIdx.z;
    const int x0 = xt * 64, y0 = yp * 4;
    const int tid = threadIdx.x, wid = tid >> 5, lid = tid & 31;
    const uint32_t sbase = smem_u32(smem);

    float acc[2][8][4];
#pragma unroll
    for (int mt = 0; mt < 2; ++mt)
#pragma unroll
        for (int j = 0; j < 8; ++j)
#pragma unroll
            for (int e = 0; e < 4; ++e) acc[mt][j][e] = 0.f;

    const int apart = lid >> 4;
    const int brow0 = (lid & 7) + ((lid >> 4) << 3);
    const int bpart = (lid >> 3) & 1;
    int hra[2];
#pragma unroll
    for (int mt = 0; mt < 2; ++mt) {
        int m = wid * 32 + mt * 16 + (lid & 15);
        hra[mt] = ((m >> 6) + 1) * 66 + (m & 63) + 1;
    }

    auto prefetchB = [&](int tap, int bi) {
        uint32_t sb = sbase + DB + (uint32_t)bi * 16384u;
        const uint4* kh = (const uint4*)g_kt_hi + (b * 9 + tap) * 512;
        const uint4* kl = (const uint4*)g_kt_lo + (b * 9 + tap) * 512;
#pragma unroll
        for (int u = 0; u < 2; ++u) {
            int idx = tid + u * 256;
            int row = idx >> 3, c = idx & 7;
            uint32_t off = (uint32_t)row * 128u + (uint32_t)((c ^ (row & 7)) << 4);
            CP16(sb + off, kh + idx);
            CP16(sb + 8192 + off, kl + idx);
        }
    };

    // ---- one-time A halo fill (396 rows) + B tap0; cp.async ----
    for (int hr = tid; hr < 396; hr += 256) {
        int hy = hr / 66, hx = hr % 66;
        int y = y0 - 1 + hy, xg = x0 - 1 + hx;
        bool ok = ((unsigned)y < (unsigned)H_) && ((unsigned)xg < (unsigned)W_);
        long base = ((long)(b * 192 + y) * 192 + xg) * 8;
        const uint4* sh = (const uint4*)g_x_hi + base;
        const uint4* sl = (const uint4*)g_x_lo + base;
        const uint4 z = make_uint4(0, 0, 0, 0);
#pragma unroll
        for (int c = 0; c < 8; ++c) {
            uint32_t off = (uint32_t)hr * 128u + (uint32_t)((c ^ (hr & 7)) << 4);
            if (ok) {
                CP16(sbase + DA_HI + off, sh + c);
                CP16(sbase + DA_LO + off, sl + c);
            } else {
                *(uint4*)(smem + DA_HI + off) = z;
                *(uint4*)(smem + DA_LO + off) = z;
            }
        }
    }
    prefetchB(0, 0);
    CP_COMMIT();
    CP_WAIT(0);
    __syncthreads();

    for (int tap = 0; tap < 9; ++tap) {
        if (tap < 8) {
            prefetchB(tap + 1, (tap + 1) & 1);
            CP_COMMIT();
        }

        const int dOff = (tap / 3 - 1) * 66 + (tap % 3 - 1);
        const uint32_t sbh = sbase + DB + (uint32_t)(tap & 1) * 16384u;
        const uint32_t sbl = sbh + 8192u;

#pragma unroll
        for (int kc = 0; kc < 4; ++kc) {
            const int acol = kc * 2 + apart;
            const int bcol = kc * 2 + bpart;
            uint32_t bf[4][4], ah[2][4], al[2][4];
#pragma unroll
            for (int nt = 0; nt < 4; ++nt) {
                int row = brow0 + nt * 16;
                ldsm_x4(bf[nt], sbh + row * 128 + ((bcol ^ (row & 7)) << 4));
            }
#pragma unroll
            for (int mt = 0; mt < 2; ++mt) {
                int hr = hra[mt] + dOff;
                uint32_t off = (uint32_t)hr * 128u + (uint32_t)((acol ^ (hr & 7)) << 4);
                ldsm_x4(ah[mt], sbase + DA_HI + off);
                ldsm_x4(al[mt], sbase + DA_LO + off);
            }
#pragma unroll
            for (int mt = 0; mt < 2; ++mt)
#pragma unroll
                for (int j = 0; j < 8; ++j) {
                    const uint32_t* bhp = &bf[j >> 1][2 * (j & 1)];
                    mma_bf16(acc[mt][j], ah[mt], bhp);
                    mma_bf16(acc[mt][j], al[mt], bhp);
                }
#pragma unroll
            for (int nt = 0; nt < 4; ++nt) {
                int row = brow0 + nt * 16;
                ldsm_x4(bf[nt], sbl + row * 128 + ((bcol ^ (row & 7)) << 4));
            }
#pragma unroll
            for (int mt = 0; mt < 2; ++mt)
#pragma unroll
                for (int j = 0; j < 8; ++j)
                    mma_bf16(acc[mt][j], ah[mt], &bf[j >> 1][2 * (j & 1)]);
        }
        CP_WAIT(0);
        __syncthreads();
    }

    // epilogue: stage fp32 [m][oc] (stride 65, reuse A region), coalesced store
    float* st = (float*)smem;
#pragma unroll
    for (int mt = 0; mt < 2; ++mt)
#pragma unroll
        for (int j = 0; j < 8; ++j)
#pragma unroll
            for (int e = 0; e < 4; ++e) {
                int row = wid * 32 + mt * 16 + (lid >> 2) + ((e >> 1) << 3);
                int col = j * 8 + (lid & 3) * 2 + (e & 1);
                st[row * 65 + col] = acc[mt][j][e];
            }
    __syncthreads();

    for (int t = tid; t < 16384; t += 256) {
        int oc = t >> 8, m = t & 255;
        float v = fmaxf(st[m * 65 + oc], 0.f);
        out[((long)(b * 64 + oc) * 192 + (y0 + (m >> 6))) * 192 + x0 + (m & 63)] = v;
    }
}

// ---------------------------------------------------------------------------
// Launch
// ---------------------------------------------------------------------------
extern "C" void kernel_launch(void* const* d_in, const int* in_sizes, int n_in,
                              void* d_out, int out_size) {
    const float* x    = (const float*)d_in[0];  // (16,64,192,192)
    const float* w_qk = (const float*)d_in[1];  // (128,64,3,3)
    const float* wgt  = (const float*)d_in[2];  // (64,64,3,3)
    const float* temp = (const float*)d_in[3];  // (1,1,1)
    float* out = (float*)d_out;                 // (16,64,192,192)

    cudaFuncSetAttribute(qk_mma_kernel, cudaFuncAttributeMaxDynamicSharedMemorySize, QK_TOT);
    cudaFuncSetAttribute(attn_mma_kernel, cudaFuncAttributeMaxDynamicSharedMemorySize, AT_TOT);
    cudaFuncSetAttribute(final_mma_kernel, cudaFuncAttributeMaxDynamicSharedMemorySize, D_TOT);

    xcl_kernel<<<dim3(576, 17), 256>>>(x, w_qk);               // 0
    qk_mma_kernel<<<dim3(32, 2, 16), 128, QK_TOT>>>();         // 1
    attn_mma_kernel<<<dim3(25, 16), 128, AT_TOT>>>();          // 2
    akconv_kernel<<<dim3(16, 16), 256>>>(wgt);                 // 3
    kern_kernel<<<dim3(64, 16), 64>>>(wgt, temp);              // 4
    final_mma_kernel<<<dim3(3, 48, 16), 256, D_TOT>>>(out);    // 5 (ncu slot)
}

// round 11
// speedup vs baseline: 5.2060x; 1.0883x over previous
#include <cuda_runtime.h>
#include <cuda_bf16.h>
#include <cstdint>
#include <math.h>

// Problem constants
#define B_  16
#define C_  64
#define H_  192
#define W_  192
#define H2_ 64
#define W2_ 64
#define S_  5

// ---------------------------------------------------------------------------
// Scratch buffers (static device globals; zero-initialized at load)
// ---------------------------------------------------------------------------
__device__ float g_attn[B_ * C_ * C_ * S_ * S_];   // K-half 0 partials
__device__ float g_attn2[B_ * C_ * C_ * S_ * S_];  // K-half 1 partials
__device__ float g_ak[B_ * C_ * C_ * 9];           // transposed ak (pre-norm)

// bf16 split operands
__device__ __align__(16) __nv_bfloat16 g_x_hi[B_ * H_ * W_ * C_];  // channel-last
__device__ __align__(16) __nv_bfloat16 g_x_lo[B_ * H_ * W_ * C_];
__device__ __align__(16) __nv_bfloat16 g_kt_hi[B_ * 9 * C_ * C_];  // [b][tap][oc][ci]
__device__ __align__(16) __nv_bfloat16 g_kt_lo[B_ * 9 * C_ * C_];
// w_qk repacked: [half(2)][tap(9)][oc(64)][ci(64)]
__device__ __align__(16) __nv_bfloat16 g_wq_hi[2 * 9 * 64 * 64];
__device__ __align__(16) __nv_bfloat16 g_wq_lo[2 * 9 * 64 * 64];
// attn GEMM operands: k channel-major [b][co][4096]
__device__ __align__(16) __nv_bfloat16 g_kh[B_ * C_ * 4096];
__device__ __align__(16) __nv_bfloat16 g_kl[B_ * C_ * 4096];
// q shifted copies: [dj(5)][b][ci][68 rows (2 zero-pad top/bottom)][64]
__device__ __align__(16) __nv_bfloat16 g_qh[5 * B_ * C_ * 68 * 64];
__device__ __align__(16) __nv_bfloat16 g_ql[5 * B_ * C_ * 68 * 64];

__device__ __forceinline__ uint32_t smem_u32(const void* p) {
    uint32_t a;
    asm("{ .reg .u64 t; cvta.to.shared.u64 t, %1; cvt.u32.u64 %0, t; }" : "=r"(a) : "l"(p));
    return a;
}

__device__ __forceinline__ void ldsm_x4(uint32_t* r, uint32_t addr) {
    asm volatile("ldmatrix.sync.aligned.m8n8.x4.shared.b16 {%0,%1,%2,%3}, [%4];"
                 : "=r"(r[0]), "=r"(r[1]), "=r"(r[2]), "=r"(r[3])
                 : "r"(addr));
}

__device__ __forceinline__ void mma_bf16(float* d, const uint32_t* a, const uint32_t* b) {
    asm volatile(
        "mma.sync.aligned.m16n8k16.row.col.f32.bf16.bf16.f32 "
        "{%0,%1,%2,%3}, {%4,%5,%6,%7}, {%8,%9}, {%0,%1,%2,%3};"
        : "+f"(d[0]), "+f"(d[1]), "+f"(d[2]), "+f"(d[3])
        : "r"(a[0]), "r"(a[1]), "r"(a[2]), "r"(a[3]), "r"(b[0]), "r"(b[1]));
}

#define CP16(dst, src) \
    asm volatile("cp.async.cg.shared.global [%0], [%1], 16;" ::"r"(dst), "l"(src))
#define CP_COMMIT() asm volatile("cp.async.commit_group;" ::: "memory")
#define CP_WAIT(N) asm volatile("cp.async.wait_group %0;" ::"n"(N) : "memory")

__device__ __forceinline__ void split_bf16(float v, __nv_bfloat16& h, __nv_bfloat16& l) {
    h = __float2bfloat16(v);
    l = __float2bfloat16(v - __bfloat162float(h));
}

// ---------------------------------------------------------------------------
// Kernel E0: x (fp32 NCHW) -> channel-last bf16 hi/lo; b==16 repacks w_qk.
// ---------------------------------------------------------------------------
__global__ void __launch_bounds__(256) xcl_kernel(const float* __restrict__ x,
                                                  const float* __restrict__ w_qk) {
    const int seg = blockIdx.x;
    const int b = blockIdx.y;
    const int tid = threadIdx.x;

    if (b == 16) {
        if (seg < 128) {
            const int half = seg >> 6, oc = seg & 63;
            for (int t = tid; t < 576; t += 256) {
                int ci = t / 9, tap = t % 9;
                __nv_bfloat16 h, l;
                split_bf16(w_qk[(seg * 64 + ci) * 9 + tap], h, l);
                int o = ((half * 9 + tap) * 64 + oc) * 64 + ci;
                g_wq_hi[o] = h;
                g_wq_lo[o] = l;
            }
        }
        return;
    }

    const int y = seg / 3;
    const int x0 = (seg % 3) * 64;
    __shared__ float s[64][65];

#pragma unroll
    for (int i = 0; i < 16; ++i) {
        int idx = tid + i * 256;
        int c = idx >> 6, p = idx & 63;
        s[p][c] = x[((b * 64 + c) * 192 + y) * 192 + x0 + p];
    }
    __syncthreads();
#pragma unroll
    for (int i = 0; i < 16; ++i) {
        int idx = tid + i * 256;
        int p = idx >> 6, c = idx & 63;
        __nv_bfloat16 h, l;
        split_bf16(s[p][c], h, l);
        int o = ((b * 192 + y) * 192 + x0 + p) * 64 + c;
        g_x_hi[o] = h;
        g_x_lo[o] = l;
    }
}

// ---------------------------------------------------------------------------
// Kernel A: qk conv via mma.sync (stride-3), cp.async tap double-buffer.
// FUSED epilogue: writes attn operands (g_kh/g_kl, 5x dj-shifted g_qh/g_ql).
// grid (32 mtiles, 2 half, 16 b), 128 thr. smem 2x48KB.
// ---------------------------------------------------------------------------
#define QK_BUF  49152
#define QK_TOT  98304

__global__ void __launch_bounds__(128) qk_mma_kernel() {
    extern __shared__ char smem[];
    const int mtile = blockIdx.x, half = blockIdx.y, b = blockIdx.z;
    const int i0 = mtile * 2;
    const int tid = threadIdx.x, wid = tid >> 5, lid = tid & 31;
    const uint32_t sbase = smem_u32(smem);

    const int r = tid;
    const int ri = i0 + (r >> 6), rj = r & 63;

    float acc[2][8][4];
#pragma unroll
    for (int mt = 0; mt < 2; ++mt)
#pragma unroll
        for (int j = 0; j < 8; ++j)
#pragma unroll
            for (int e = 0; e < 4; ++e) acc[mt][j][e] = 0.f;

    const int arow0 = wid * 32 + (lid & 15);
    const int apart = lid >> 4;
    const int brow0 = (lid & 7) + ((lid >> 4) << 3);
    const int bpart = (lid >> 3) & 1;

    auto prefetch = [&](int tap, int bi) {
        uint32_t sb = sbase + (uint32_t)bi * QK_BUF;
        const int dy = tap / 3, dx = tap % 3;
        long abase = ((long)(b * 192 + 3 * ri + dy) * 192 + 3 * rj + dx) * 8;
        const uint4* sh = (const uint4*)g_x_hi + abase;
        const uint4* sl = (const uint4*)g_x_lo + abase;
#pragma unroll
        for (int c = 0; c < 8; ++c) {
            uint32_t off = (uint32_t)r * 128u + (uint32_t)((c ^ (r & 7)) << 4);
            CP16(sb + off, sh + c);
            CP16(sb + 16384 + off, sl + c);
        }
        const uint4* wh = (const uint4*)g_wq_hi + (half * 9 + tap) * 512;
        const uint4* wl = (const uint4*)g_wq_lo + (half * 9 + tap) * 512;
#pragma unroll
        for (int i = 0; i < 4; ++i) {
            int idx = tid + i * 128;
            int row = idx >> 3, c = idx & 7;
            uint32_t off = (uint32_t)row * 128u + (uint32_t)((c ^ (row & 7)) << 4);
            CP16(sb + 32768 + off, wh + idx);
            CP16(sb + 40960 + off, wl + idx);
        }
    };

    prefetch(0, 0);
    CP_COMMIT();

    for (int tap = 0; tap < 9; ++tap) {
        if (tap < 8) {
            prefetch(tap + 1, (tap + 1) & 1);
            CP_COMMIT();
            CP_WAIT(1);
        } else {
            CP_WAIT(0);
        }
        __syncthreads();

        const uint32_t sb = sbase + (uint32_t)(tap & 1) * QK_BUF;
#pragma unroll
        for (int kc = 0; kc < 4; ++kc) {
            const int acol = kc * 2 + apart;
            const int bcol = kc * 2 + bpart;
            uint32_t bfh[4][4], bfl[4][4], ah[2][4], al[2][4];
#pragma unroll
            for (int nt = 0; nt < 4; ++nt) {
                int row = brow0 + nt * 16;
                uint32_t off = row * 128 + ((bcol ^ (row & 7)) << 4);
                ldsm_x4(bfh[nt], sb + 32768 + off);
                ldsm_x4(bfl[nt], sb + 40960 + off);
            }
#pragma unroll
            for (int mt = 0; mt < 2; ++mt) {
                int row = arow0 + mt * 16;
                uint32_t off = row * 128 + ((acol ^ (row & 7)) << 4);
                ldsm_x4(ah[mt], sb + off);
                ldsm_x4(al[mt], sb + 16384 + off);
            }
#pragma unroll
            for (int mt = 0; mt < 2; ++mt)
#pragma unroll
                for (int j = 0; j < 8; ++j) {
                    const uint32_t* bhp = &bfh[j >> 1][2 * (j & 1)];
                    mma_bf16(acc[mt][j], ah[mt], bhp);
                    mma_bf16(acc[mt][j], al[mt], bhp);
                    mma_bf16(acc[mt][j], ah[mt], &bfl[j >> 1][2 * (j & 1)]);
                }
        }
        __syncthreads();
    }

    // ---- fused epilogue: stage fp32 [m][ch] (stride 65), emit bf16 operands
    float* st = (float*)smem;
#pragma unroll
    for (int mt = 0; mt < 2; ++mt)
#pragma unroll
        for (int j = 0; j < 8; ++j)
#pragma unroll
            for (int e = 0; e < 4; ++e) {
                int m = wid * 32 + mt * 16 + (lid >> 2) + ((e >> 1) << 3);
                int col = j * 8 + (lid & 3) * 2 + (e & 1);
                st[m * 65 + col] = acc[mt][j][e];
            }
    __syncthreads();

    if (half) {
        for (int t = tid; t < 8192; t += 128) {
            int co = t >> 7, m = t & 127;
            int h = i0 + (m >> 6), w = m & 63;
            __nv_bfloat16 hh, ll;
            split_bf16(st[m * 65 + co], hh, ll);
            long o = (long)(b * 64 + co) * 4096 + h * 64 + w;
            g_kh[o] = hh;
            g_kl[o] = ll;
        }
    } else {
        for (int dj = 0; dj < 5; ++dj) {
            for (int t = tid; t < 8192; t += 128) {
                int ci = t >> 7, m = t & 127;
                int h = i0 + (m >> 6), w = m & 63;
                int wsrc = w + dj - 2;
                float v = ((unsigned)wsrc < 64u) ? st[((m >> 6) * 64 + wsrc) * 65 + ci] : 0.f;
                __nv_bfloat16 hh, ll;
                split_bf16(v, hh, ll);
                long o = (((long)(dj * 16 + b) * 64 + ci) * 68 + (h + 2)) * 64 + w;
                g_qh[o] = hh;
                g_ql[o] = ll;
            }
        }
    }
}

// ---------------------------------------------------------------------------
// Kernel B: attn via mma.sync, K SPLIT IN 2 (h halves) for 2x parallelism.
// grid (25, 2 halves, 16 b), 128 thr. Partial sums -> g_attn / g_attn2.
// ---------------------------------------------------------------------------
#define AT_BUF 32768
#define AT_TOT 65536

__global__ void __launch_bounds__(128) attn_mma_kernel() {
    extern __shared__ char smem[];
    const int dj = blockIdx.x % 5, di = blockIdx.x / 5;
    const int half = blockIdx.y, b = blockIdx.z;
    const int tid = threadIdx.x, wid = tid >> 5, lid = tid & 31;
    const uint32_t sbase = smem_u32(smem);
    const int mrow = (wid & 1) * 32, ncol = (wid >> 1) * 32;

    float acc[2][4][4];
#pragma unroll
    for (int mt = 0; mt < 2; ++mt)
#pragma unroll
        for (int j = 0; j < 4; ++j)
#pragma unroll
            for (int e = 0; e < 4; ++e) acc[mt][j][e] = 0.f;

    const uint4* __restrict__ kh = (const uint4*)g_kh + (long)b * 64 * 512;
    const uint4* __restrict__ kl = (const uint4*)g_kl + (long)b * 64 * 512;
    const uint4* __restrict__ qh = (const uint4*)g_qh + (long)(dj * 16 + b) * 64 * 544 + di * 8;
    const uint4* __restrict__ ql = (const uint4*)g_ql + (long)(dj * 16 + b) * 64 * 544 + di * 8;

    const int apart = lid >> 4;
    const int brow_l = (lid & 7) + ((lid >> 4) << 3);
    const int bpart = (lid >> 3) & 1;
    const int kc0 = half * 32;

    auto prefetch = [&](int kc, int bi) {
        uint32_t sb = sbase + (uint32_t)bi * AT_BUF;
#pragma unroll
        for (int a = 0; a < 4; ++a) {
            const uint4* gp = (a == 0) ? kh : (a == 1) ? kl : (a == 2) ? qh : ql;
            const int stride = (a < 2) ? 512 : 544;
#pragma unroll
            for (int u = 0; u < 4; ++u) {
                int idx = tid + u * 128;  // 0..511
                int row = idx >> 3, c = idx & 7;
                uint32_t off = (uint32_t)a * 8192u + (uint32_t)row * 128u +
                               (uint32_t)((c ^ (row & 7)) << 4);
                CP16(sb + off, gp + (long)row * stride + kc * 8 + c);
            }
        }
    };

    prefetch(kc0, 0);
    CP_COMMIT();

    for (int kc2 = 0; kc2 < 32; ++kc2) {
        if (kc2 < 31) {
            prefetch(kc0 + kc2 + 1, (kc2 + 1) & 1);
            CP_COMMIT();
            CP_WAIT(1);
        } else {
            CP_WAIT(0);
        }
        __syncthreads();

        const uint32_t sb = sbase + (uint32_t)(kc2 & 1) * AT_BUF;
#pragma unroll
        for (int kk = 0; kk < 4; ++kk) {
            uint32_t ah[2][4], al[2][4], bh[2][4], bl[2][4];
            const int acol = kk * 2 + apart;
            const int bcol = kk * 2 + bpart;
#pragma unroll
            for (int mt = 0; mt < 2; ++mt) {
                int row = mrow + mt * 16 + (lid & 15);
                uint32_t off = (uint32_t)row * 128u + (uint32_t)((acol ^ (row & 7)) << 4);
                ldsm_x4(ah[mt], sb + off);
                ldsm_x4(al[mt], sb + 8192 + off);
            }
#pragma unroll
            for (int nt = 0; nt < 2; ++nt) {
                int row = ncol + nt * 16 + brow_l;
                uint32_t off = (uint32_t)row * 128u + (uint32_t)((bcol ^ (row & 7)) << 4);
                ldsm_x4(bh[nt], sb + 16384 + off);
                ldsm_x4(bl[nt], sb + 24576 + off);
            }
#pragma unroll
            for (int mt = 0; mt < 2; ++mt)
#pragma unroll
                for (int j = 0; j < 4; ++j) {
                    const uint32_t* bhp = &bh[j >> 1][2 * (j & 1)];
                    mma_bf16(acc[mt][j], ah[mt], bhp);
                    mma_bf16(acc[mt][j], al[mt], bhp);
                    mma_bf16(acc[mt][j], ah[mt], &bl[j >> 1][2 * (j & 1)]);
                }
        }
        __syncthreads();
    }

    float* dst = half ? g_attn2 : g_attn;
#pragma unroll
    for (int mt = 0; mt < 2; ++mt)
#pragma unroll
        for (int j = 0; j < 4; ++j)
#pragma unroll
            for (int e = 0; e < 4; ++e) {
                int co = mrow + mt * 16 + (lid >> 2) + ((e >> 1) << 3);
                int ci = ncol + j * 8 + (lid & 3) * 2 + (e & 1);
                dst[((b * 64 + co) * 64 + ci) * 25 + di * 5 + dj] = acc[mt][j][e];
            }
}

// ---------------------------------------------------------------------------
// Kernel C1: ak conv (VALID 3x3 over 5x5 attn), sums the two K-half partials.
// ---------------------------------------------------------------------------
__global__ void __launch_bounds__(256) akconv_kernel(const float* __restrict__ weight) {
    const int cAg = blockIdx.x;
    const int b   = blockIdx.y;
    const int tid = threadIdx.x;
    const int s  = tid >> 6;
    const int cB = tid & 63;
    const int cA = cAg * 4 + s;

    __shared__ float as4[4][64][25];
    __shared__ float ws[64][73];

    for (int t = tid; t < 6400; t += 256) {
        int a = t / 1600, r = t % 1600;
        long o = (long)(b * 64 + cAg * 4 + a) * 1600 + r;
        as4[a][r / 25][r % 25] = g_attn[o] + g_attn2[o];
    }

    float acc[9];
#pragma unroll
    for (int t9 = 0; t9 < 9; ++t9) acc[t9] = 0.f;

    for (int cic = 0; cic < 8; ++cic) {
        __syncthreads();
        for (int t = tid; t < 4608; t += 256) {
            int c2 = t / 72;
            int rr = t % 72;
            ws[c2][rr] = weight[c2 * 576 + (cic * 8 + rr / 9) * 9 + (rr % 9)];
        }
        __syncthreads();
#pragma unroll
        for (int ci = 0; ci < 8; ++ci) {
            float av[25];
#pragma unroll
            for (int p = 0; p < 25; ++p) av[p] = as4[s][cic * 8 + ci][p];
#pragma unroll
            for (int dy = 0; dy < 3; ++dy)
#pragma unroll
                for (int dx = 0; dx < 3; ++dx) {
                    float wv = ws[cB][ci * 9 + dy * 3 + dx];
#pragma unroll
                    for (int ky = 0; ky < 3; ++ky)
#pragma unroll
                        for (int kx = 0; kx < 3; ++kx)
                            acc[ky * 3 + kx] =
                                fmaf(av[(ky + dy) * 5 + (kx + dx)], wv, acc[ky * 3 + kx]);
                }
        }
    }
#pragma unroll
    for (int t9 = 0; t9 < 9; ++t9)
        g_ak[((b * 64 + cB) * 64 + cA) * 9 + t9] = acc[t9];
}

// ---------------------------------------------------------------------------
// Kernel C2: normalize ak, build dynamic kernels -> bf16 hi/lo B tiles
// ---------------------------------------------------------------------------
__global__ void __launch_bounds__(64) kern_kernel(const float* __restrict__ weight,
                                                  const float* __restrict__ temperature) {
    const int cB  = blockIdx.x;
    const int b   = blockIdx.y;
    const int tid = threadIdx.x;  // = cA

    const float* ak = g_ak + (b * 64 + cB) * 64 * 9;
    float v[9];
    float ss = 0.f;
#pragma unroll
    for (int t9 = 0; t9 < 9; ++t9) {
        v[t9] = ak[tid * 9 + t9];
        ss = fmaf(v[t9], v[t9], ss);
    }

    __shared__ float red[64];
    red[tid] = ss;
    __syncthreads();
#pragma unroll
    for (int s = 32; s >= 1; s >>= 1) {
        if (tid < s) red[tid] += red[tid + s];
        __syncthreads();
    }
    float nrm = sqrtf(red[0]);
    float scale = temperature[0] / fmaxf(nrm, 1e-12f);

#pragma unroll
    for (int t9 = 0; t9 < 9; ++t9) {
        float vv = weight[(cB * 64 + tid) * 9 + t9] + v[t9] * scale;
        __nv_bfloat16 h, l;
        split_bf16(vv, h, l);
        int o = ((b * 9 + t9) * 64 + cB) * 64 + tid;
        g_kt_hi[o] = h;
        g_kt_lo[o] = l;
    }
}

// ---------------------------------------------------------------------------
// Kernel D: final conv via mma.sync, M=128 (4y x 32x), 128 threads.
// 32-wide x-tiles -> 85KB smem -> 2 CTAs/SM. Single A-halo fill serves all
// 9 taps; B cp.async double-buffered.
// smem: Ahi 26112 | Alo 26112 | B 2x16384 = 84992.
// ---------------------------------------------------------------------------
#define DA_HI  0
#define DA_LO  26112
#define DB     52224
#define D_TOT  84992

__global__ void __launch_bounds__(128) final_mma_kernel(float* __restrict__ out) {
    extern __shared__ char smem[];
    const int xt = blockIdx.x, yp = blockIdx.y, b = blockIdx.z;
    const int x0 = xt * 32, y0 = yp * 4;
    const int tid = threadIdx.x, wid = tid >> 5, lid = tid & 31;
    const uint32_t sbase = smem_u32(smem);

    float acc[2][8][4];
#pragma unroll
    for (int mt = 0; mt < 2; ++mt)
#pragma unroll
        for (int j = 0; j < 8; ++j)
#pragma unroll
            for (int e = 0; e < 4; ++e) acc[mt][j][e] = 0.f;

    const int apart = lid >> 4;
    const int brow0 = (lid & 7) + ((lid >> 4) << 3);
    const int bpart = (lid >> 3) & 1;
    int hra[2];
#pragma unroll
    for (int mt = 0; mt < 2; ++mt) {
        int m = wid * 32 + mt * 16 + (lid & 15);
        hra[mt] = ((m >> 5) + 1) * 34 + (m & 31) + 1;
    }

    auto prefetchB = [&](int tap, int bi) {
        uint32_t sb = sbase + DB + (uint32_t)bi * 16384u;
        const uint4* kh = (const uint4*)g_kt_hi + (b * 9 + tap) * 512;
        const uint4* kl = (const uint4*)g_kt_lo + (b * 9 + tap) * 512;
#pragma unroll
        for (int u = 0; u < 4; ++u) {
            int idx = tid + u * 128;
            int row = idx >> 3, c = idx & 7;
            uint32_t off = (uint32_t)row * 128u + (uint32_t)((c ^ (row & 7)) << 4);
            CP16(sb + off, kh + idx);
            CP16(sb + 8192 + off, kl + idx);
        }
    };

    // ---- one-time A halo fill (204 rows = 6y x 34x) + B tap0 ----
    for (int hr = tid; hr < 204; hr += 128) {
        int hy = hr / 34, hx = hr % 34;
        int y = y0 - 1 + hy, xg = x0 - 1 + hx;
        bool ok = ((unsigned)y < (unsigned)H_) && ((unsigned)xg < (unsigned)W_);
        long base = ((long)(b * 192 + y) * 192 + xg) * 8;
        const uint4* sh = (const uint4*)g_x_hi + base;
        const uint4* sl = (const uint4*)g_x_lo + base;
        const uint4 z = make_uint4(0, 0, 0, 0);
#pragma unroll
        for (int c = 0; c < 8; ++c) {
            uint32_t off = (uint32_t)hr * 128u + (uint32_t)((c ^ (hr & 7)) << 4);
            if (ok) {
                CP16(sbase + DA_HI + off, sh + c);
                CP16(sbase + DA_LO + off, sl + c);
            } else {
                *(uint4*)(smem + DA_HI + off) = z;
                *(uint4*)(smem + DA_LO + off) = z;
            }
        }
    }
    prefetchB(0, 0);
    CP_COMMIT();
    CP_WAIT(0);
    __syncthreads();

    for (int tap = 0; tap < 9; ++tap) {
        if (tap < 8) {
            prefetchB(tap + 1, (tap + 1) & 1);
            CP_COMMIT();
        }

        const int dOff = (tap / 3 - 1) * 34 + (tap % 3 - 1);
        const uint32_t sbh = sbase + DB + (uint32_t)(tap & 1) * 16384u;
        const uint32_t sbl = sbh + 8192u;

#pragma unroll
        for (int kc = 0; kc < 4; ++kc) {
            const int acol = kc * 2 + apart;
            const int bcol = kc * 2 + bpart;
            uint32_t bfh[4][4], bfl[4][4], ah[2][4], al[2][4];
#pragma unroll
            for (int nt = 0; nt < 4; ++nt) {
                int row = brow0 + nt * 16;
                uint32_t off = row * 128 + ((bcol ^ (row & 7)) << 4);
                ldsm_x4(bfh[nt], sbh + off);
                ldsm_x4(bfl[nt], sbl + off);
            }
#pragma unroll
            for (int mt = 0; mt < 2; ++mt) {
                int hr = hra[mt] + dOff;
                uint32_t off = (uint32_t)hr * 128u + (uint32_t)((acol ^ (hr & 7)) << 4);
                ldsm_x4(ah[mt], sbase + DA_HI + off);
                ldsm_x4(al[mt], sbase + DA_LO + off);
            }
#pragma unroll
            for (int mt = 0; mt < 2; ++mt)
#pragma unroll
                for (int j = 0; j < 8; ++j) {
                    const uint32_t* bhp = &bfh[j >> 1][2 * (j & 1)];
                    mma_bf16(acc[mt][j], ah[mt], bhp);
                    mma_bf16(acc[mt][j], al[mt], bhp);
                    mma_bf16(acc[mt][j], ah[mt], &bfl[j >> 1][2 * (j & 1)]);
                }
        }
        CP_WAIT(0);
        __syncthreads();
    }

    // epilogue: stage fp32 [m][oc] (stride 65, reuse A region), coalesced store
    float* st = (float*)smem;
#pragma unroll
    for (int mt = 0; mt < 2; ++mt)
#pragma unroll
        for (int j = 0; j < 8; ++j)
#pragma unroll
            for (int e = 0; e < 4; ++e) {
                int row = wid * 32 + mt * 16 + (lid >> 2) + ((e >> 1) << 3);
                int col = j * 8 + (lid & 3) * 2 + (e & 1);
                st[row * 65 + col] = acc[mt][j][e];
            }
    __syncthreads();

    for (int t = tid; t < 8192; t += 128) {
        int oc = t >> 7, m = t & 127;
        float v = fmaxf(st[m * 65 + oc], 0.f);
        out[((long)(b * 64 + oc) * 192 + (y0 + (m >> 5))) * 192 + x0 + (m & 31)] = v;
    }
}

// ---------------------------------------------------------------------------
// Launch
// ---------------------------------------------------------------------------
extern "C" void kernel_launch(void* const* d_in, const int* in_sizes, int n_in,
                              void* d_out, int out_size) {
    const float* x    = (const float*)d_in[0];  // (16,64,192,192)
    const float* w_qk = (const float*)d_in[1];  // (128,64,3,3)
    const float* wgt  = (const float*)d_in[2];  // (64,64,3,3)
    const float* temp = (const float*)d_in[3];  // (1,1,1)
    float* out = (float*)d_out;                 // (16,64,192,192)

    cudaFuncSetAttribute(qk_mma_kernel, cudaFuncAttributeMaxDynamicSharedMemorySize, QK_TOT);
    cudaFuncSetAttribute(attn_mma_kernel, cudaFuncAttributeMaxDynamicSharedMemorySize, AT_TOT);
    cudaFuncSetAttribute(final_mma_kernel, cudaFuncAttributeMaxDynamicSharedMemorySize, D_TOT);

    xcl_kernel<<<dim3(576, 17), 256>>>(x, w_qk);               // 0
    qk_mma_kernel<<<dim3(32, 2, 16), 128, QK_TOT>>>();         // 1
    attn_mma_kernel<<<dim3(25, 2, 16), 128, AT_TOT>>>();       // 2
    akconv_kernel<<<dim3(16, 16), 256>>>(wgt);                 // 3
    kern_kernel<<<dim3(64, 16), 64>>>(wgt, temp);              // 4
    final_mma_kernel<<<dim3(6, 48, 16), 128, D_TOT>>>(out);    // 5 (ncu slot)
}

// round 12
// speedup vs baseline: 6.7144x; 1.2897x over previous
#include <cuda_runtime.h>
#include <cuda_fp16.h>
#include <cstdint>
#include <math.h>

// Problem constants
#define B_  16
#define C_  64
#define H_  192
#define W_  192
#define H2_ 64
#define W2_ 64
#define S_  5

// ---------------------------------------------------------------------------
// Scratch buffers (static device globals; zero-initialized at load)
// ---------------------------------------------------------------------------
__device__ float g_attnP[4][B_ * C_ * C_ * S_ * S_];  // 4 K-quarter partials
__device__ float g_ak[B_ * C_ * C_ * 9];              // transposed ak (pre-norm)

// fp16 operands. Split (hi/lo) ONLY on the A side of each GEMM.
__device__ __align__(16) __half g_x_hi[B_ * H_ * W_ * C_];  // channel-last
__device__ __align__(16) __half g_x_lo[B_ * H_ * W_ * C_];
__device__ __align__(16) __half g_kt[B_ * 9 * C_ * C_];     // [b][tap][oc][ci] single
__device__ __align__(16) __half g_wq[2 * 9 * 64 * 64];      // [half][tap][oc][ci] single
// attn A operand: k channel-major [b][co][4096], split
__device__ __align__(16) __half g_kh[B_ * C_ * 4096];
__device__ __align__(16) __half g_kl[B_ * C_ * 4096];
// attn B operand: q shifted copies [dj(5)][b][ci][68 rows (zero-pad)][64], single
__device__ __align__(16) __half g_q5[5 * B_ * C_ * 68 * 64];

__device__ __forceinline__ uint32_t smem_u32(const void* p) {
    uint32_t a;
    asm("{ .reg .u64 t; cvta.to.shared.u64 t, %1; cvt.u32.u64 %0, t; }" : "=r"(a) : "l"(p));
    return a;
}

__device__ __forceinline__ void ldsm_x4(uint32_t* r, uint32_t addr) {
    asm volatile("ldmatrix.sync.aligned.m8n8.x4.shared.b16 {%0,%1,%2,%3}, [%4];"
                 : "=r"(r[0]), "=r"(r[1]), "=r"(r[2]), "=r"(r[3])
                 : "r"(addr));
}

// mma.sync m16n8k16 fp16 -> fp32 accum (in-place)
__device__ __forceinline__ void mma_fp16(float* d, const uint32_t* a, const uint32_t* b) {
    asm volatile(
        "mma.sync.aligned.m16n8k16.row.col.f32.f16.f16.f32 "
        "{%0,%1,%2,%3}, {%4,%5,%6,%7}, {%8,%9}, {%0,%1,%2,%3};"
        : "+f"(d[0]), "+f"(d[1]), "+f"(d[2]), "+f"(d[3])
        : "r"(a[0]), "r"(a[1]), "r"(a[2]), "r"(a[3]), "r"(b[0]), "r"(b[1]));
}

#define CP16(dst, src) \
    asm volatile("cp.async.cg.shared.global [%0], [%1], 16;" ::"r"(dst), "l"(src))
#define CP_COMMIT() asm volatile("cp.async.commit_group;" ::: "memory")
#define CP_WAIT(N) asm volatile("cp.async.wait_group %0;" ::"n"(N) : "memory")

__device__ __forceinline__ void split_fp16(float v, __half& h, __half& l) {
    h = __float2half(v);
    l = __float2half(v - __half2float(h));
}

// ---------------------------------------------------------------------------
// Kernel E0: x (fp32 NCHW) -> channel-last fp16 hi/lo; b==16 repacks w_qk.
// ---------------------------------------------------------------------------
__global__ void __launch_bounds__(256) xcl_kernel(const float* __restrict__ x,
                                                  const float* __restrict__ w_qk) {
    const int seg = blockIdx.x;
    const int b = blockIdx.y;
    const int tid = threadIdx.x;

    if (b == 16) {
        if (seg < 128) {
            const int half = seg >> 6, oc = seg & 63;
            for (int t = tid; t < 576; t += 256) {
                int ci = t / 9, tap = t % 9;
                g_wq[((half * 9 + tap) * 64 + oc) * 64 + ci] =
                    __float2half(w_qk[(seg * 64 + ci) * 9 + tap]);
            }
        }
        return;
    }

    const int y = seg / 3;
    const int x0 = (seg % 3) * 64;
    __shared__ float s[64][65];

#pragma unroll
    for (int i = 0; i < 16; ++i) {
        int idx = tid + i * 256;
        int c = idx >> 6, p = idx & 63;
        s[p][c] = x[((b * 64 + c) * 192 + y) * 192 + x0 + p];
    }
    __syncthreads();
#pragma unroll
    for (int i = 0; i < 16; ++i) {
        int idx = tid + i * 256;
        int p = idx >> 6, c = idx & 63;
        __half h, l;
        split_fp16(s[p][c], h, l);
        int o = ((b * 192 + y) * 192 + x0 + p) * 64 + c;
        g_x_hi[o] = h;
        g_x_lo[o] = l;
    }
}

// ---------------------------------------------------------------------------
// Kernel A: qk conv via mma.sync (stride-3), cp.async tap double-buffer.
// A = x (hi/lo fp16 split), B = w_qk (single fp16). 2 mma terms.
// FUSED epilogue: k -> g_kh/g_kl (split), q -> g_q5 (5 dj copies, single).
// grid (32 mtiles, 2 half, 16 b), 128 thr. smem 2 x 40KB.
// ---------------------------------------------------------------------------
#define QK_AL   16384
#define QK_B    32768
#define QK_BUF  40960
#define QK_TOT  81920

__global__ void __launch_bounds__(128) qk_mma_kernel() {
    extern __shared__ char smem[];
    const int mtile = blockIdx.x, half = blockIdx.y, b = blockIdx.z;
    const int i0 = mtile * 2;
    const int tid = threadIdx.x, wid = tid >> 5, lid = tid & 31;
    const uint32_t sbase = smem_u32(smem);

    const int r = tid;
    const int ri = i0 + (r >> 6), rj = r & 63;

    float acc[2][8][4];
#pragma unroll
    for (int mt = 0; mt < 2; ++mt)
#pragma unroll
        for (int j = 0; j < 8; ++j)
#pragma unroll
            for (int e = 0; e < 4; ++e) acc[mt][j][e] = 0.f;

    const int arow0 = wid * 32 + (lid & 15);
    const int apart = lid >> 4;
    const int brow0 = (lid & 7) + ((lid >> 4) << 3);
    const int bpart = (lid >> 3) & 1;

    auto prefetch = [&](int tap, int bi) {
        uint32_t sb = sbase + (uint32_t)bi * QK_BUF;
        const int dy = tap / 3, dx = tap % 3;
        long abase = ((long)(b * 192 + 3 * ri + dy) * 192 + 3 * rj + dx) * 8;
        const uint4* sh = (const uint4*)g_x_hi + abase;
        const uint4* sl = (const uint4*)g_x_lo + abase;
#pragma unroll
        for (int c = 0; c < 8; ++c) {
            uint32_t off = (uint32_t)r * 128u + (uint32_t)((c ^ (r & 7)) << 4);
            CP16(sb + off, sh + c);
            CP16(sb + QK_AL + off, sl + c);
        }
        const uint4* wp = (const uint4*)g_wq + (half * 9 + tap) * 512;
#pragma unroll
        for (int i = 0; i < 4; ++i) {
            int idx = tid + i * 128;
            int row = idx >> 3, c = idx & 7;
            uint32_t off = (uint32_t)row * 128u + (uint32_t)((c ^ (row & 7)) << 4);
            CP16(sb + QK_B + off, wp + idx);
        }
    };

    prefetch(0, 0);
    CP_COMMIT();

    for (int tap = 0; tap < 9; ++tap) {
        if (tap < 8) {
            prefetch(tap + 1, (tap + 1) & 1);
            CP_COMMIT();
            CP_WAIT(1);
        } else {
            CP_WAIT(0);
        }
        __syncthreads();

        const uint32_t sb = sbase + (uint32_t)(tap & 1) * QK_BUF;
#pragma unroll
        for (int kc = 0; kc < 4; ++kc) {
            const int acol = kc * 2 + apart;
            const int bcol = kc * 2 + bpart;
            uint32_t bf[4][4], ah[2][4], al[2][4];
#pragma unroll
            for (int nt = 0; nt < 4; ++nt) {
                int row = brow0 + nt * 16;
                ldsm_x4(bf[nt], sb + QK_B + row * 128 + ((bcol ^ (row & 7)) << 4));
            }
#pragma unroll
            for (int mt = 0; mt < 2; ++mt) {
                int row = arow0 + mt * 16;
                uint32_t off = row * 128 + ((acol ^ (row & 7)) << 4);
                ldsm_x4(ah[mt], sb + off);
                ldsm_x4(al[mt], sb + QK_AL + off);
            }
#pragma unroll
            for (int mt = 0; mt < 2; ++mt)
#pragma unroll
                for (int j = 0; j < 8; ++j) {
                    const uint32_t* bp = &bf[j >> 1][2 * (j & 1)];
                    mma_fp16(acc[mt][j], ah[mt], bp);
                    mma_fp16(acc[mt][j], al[mt], bp);
                }
        }
        __syncthreads();
    }

    // ---- fused epilogue: stage fp32 [m][ch] (stride 65), emit fp16 operands
    float* st = (float*)smem;
#pragma unroll
    for (int mt = 0; mt < 2; ++mt)
#pragma unroll
        for (int j = 0; j < 8; ++j)
#pragma unroll
            for (int e = 0; e < 4; ++e) {
                int m = wid * 32 + mt * 16 + (lid >> 2) + ((e >> 1) << 3);
                int col = j * 8 + (lid & 3) * 2 + (e & 1);
                st[m * 65 + col] = acc[mt][j][e];
            }
    __syncthreads();

    if (half) {
        // k: channel-major split
        for (int t = tid; t < 8192; t += 128) {
            int co = t >> 7, m = t & 127;
            int h = i0 + (m >> 6), w = m & 63;
            __half hh, ll;
            split_fp16(st[m * 65 + co], hh, ll);
            long o = (long)(b * 64 + co) * 4096 + h * 64 + w;
            g_kh[o] = hh;
            g_kl[o] = ll;
        }
    } else {
        // q: 5 dj-shifted padded copies, single fp16
        for (int dj = 0; dj < 5; ++dj) {
            for (int t = tid; t < 8192; t += 128) {
                int ci = t >> 7, m = t & 127;
                int h = i0 + (m >> 6), w = m & 63;
                int wsrc = w + dj - 2;
                float v = ((unsigned)wsrc < 64u) ? st[((m >> 6) * 64 + wsrc) * 65 + ci] : 0.f;
                long o = (((long)(dj * 16 + b) * 64 + ci) * 68 + (h + 2)) * 64 + w;
                g_q5[o] = __float2half(v);
            }
        }
    }
}

// ---------------------------------------------------------------------------
// Kernel B: attn via mma.sync, K SPLIT IN 4. A = k (hi/lo), B = q (single).
// grid (25, 4 quarters, 16 b), 128 thr. smem 2 x 24KB.
// ---------------------------------------------------------------------------
#define AT_KL  8192
#define AT_Q   16384
#define AT_BUF 24576
#define AT_TOT 49152

__global__ void __launch_bounds__(128) attn_mma_kernel() {
    extern __shared__ char smem[];
    const int dj = blockIdx.x % 5, di = blockIdx.x / 5;
    const int quarter = blockIdx.y, b = blockIdx.z;
    const int tid = threadIdx.x, wid = tid >> 5, lid = tid & 31;
    const uint32_t sbase = smem_u32(smem);
    const int mrow = (wid & 1) * 32, ncol = (wid >> 1) * 32;

    float acc[2][4][4];
#pragma unroll
    for (int mt = 0; mt < 2; ++mt)
#pragma unroll
        for (int j = 0; j < 4; ++j)
#pragma unroll
            for (int e = 0; e < 4; ++e) acc[mt][j][e] = 0.f;

    const uint4* __restrict__ kh = (const uint4*)g_kh + (long)b * 64 * 512;
    const uint4* __restrict__ kl = (const uint4*)g_kl + (long)b * 64 * 512;
    const uint4* __restrict__ qp = (const uint4*)g_q5 + (long)(dj * 16 + b) * 64 * 544 + di * 8;

    const int apart = lid >> 4;
    const int brow_l = (lid & 7) + ((lid >> 4) << 3);
    const int bpart = (lid >> 3) & 1;
    const int kc0 = quarter * 16;

    auto prefetch = [&](int kc, int bi) {
        uint32_t sb = sbase + (uint32_t)bi * AT_BUF;
#pragma unroll
        for (int a = 0; a < 3; ++a) {
            const uint4* gp = (a == 0) ? kh : (a == 1) ? kl : qp;
            const int stride = (a < 2) ? 512 : 544;
#pragma unroll
            for (int u = 0; u < 4; ++u) {
                int idx = tid + u * 128;  // 0..511
                int row = idx >> 3, c = idx & 7;
                uint32_t off = (uint32_t)a * 8192u + (uint32_t)row * 128u +
                               (uint32_t)((c ^ (row & 7)) << 4);
                CP16(sb + off, gp + (long)row * stride + kc * 8 + c);
            }
        }
    };

    prefetch(kc0, 0);
    CP_COMMIT();

    for (int kc2 = 0; kc2 < 16; ++kc2) {
        if (kc2 < 15) {
            prefetch(kc0 + kc2 + 1, (kc2 + 1) & 1);
            CP_COMMIT();
            CP_WAIT(1);
        } else {
            CP_WAIT(0);
        }
        __syncthreads();

        const uint32_t sb = sbase + (uint32_t)(kc2 & 1) * AT_BUF;
#pragma unroll
        for (int kk = 0; kk < 4; ++kk) {
            uint32_t ah[2][4], al[2][4], bh[2][4];
            const int acol = kk * 2 + apart;
            const int bcol = kk * 2 + bpart;
#pragma unroll
            for (int mt = 0; mt < 2; ++mt) {
                int row = mrow + mt * 16 + (lid & 15);
                uint32_t off = (uint32_t)row * 128u + (uint32_t)((acol ^ (row & 7)) << 4);
                ldsm_x4(ah[mt], sb + off);
                ldsm_x4(al[mt], sb + AT_KL + off);
            }
#pragma unroll
            for (int nt = 0; nt < 2; ++nt) {
                int row = ncol + nt * 16 + brow_l;
                uint32_t off = (uint32_t)row * 128u + (uint32_t)((bcol ^ (row & 7)) << 4);
                ldsm_x4(bh[nt], sb + AT_Q + off);
            }
#pragma unroll
            for (int mt = 0; mt < 2; ++mt)
#pragma unroll
                for (int j = 0; j < 4; ++j) {
                    const uint32_t* bp = &bh[j >> 1][2 * (j & 1)];
                    mma_fp16(acc[mt][j], ah[mt], bp);
                    mma_fp16(acc[mt][j], al[mt], bp);
                }
        }
        __syncthreads();
    }

    float* dst = g_attnP[quarter];
#pragma unroll
    for (int mt = 0; mt < 2; ++mt)
#pragma unroll
        for (int j = 0; j < 4; ++j)
#pragma unroll
            for (int e = 0; e < 4; ++e) {
                int co = mrow + mt * 16 + (lid >> 2) + ((e >> 1) << 3);
                int ci = ncol + j * 8 + (lid & 3) * 2 + (e & 1);
                dst[((b * 64 + co) * 64 + ci) * 25 + di * 5 + dj] = acc[mt][j][e];
            }
}

// ---------------------------------------------------------------------------
// Kernel C1: ak conv (VALID 3x3 over 5x5 attn), sums the 4 K-quarter partials.
// ---------------------------------------------------------------------------
__global__ void __launch_bounds__(256) akconv_kernel(const float* __restrict__ weight) {
    const int cAg = blockIdx.x;
    const int b   = blockIdx.y;
    const int tid = threadIdx.x;
    const int s  = tid >> 6;
    const int cB = tid & 63;
    const int cA = cAg * 4 + s;

    __shared__ float as4[4][64][25];
    __shared__ float ws[64][73];

    for (int t = tid; t < 6400; t += 256) {
        int a = t / 1600, r = t % 1600;
        long o = (long)(b * 64 + cAg * 4 + a) * 1600 + r;
        as4[a][r / 25][r % 25] =
            (g_attnP[0][o] + g_attnP[1][o]) + (g_attnP[2][o] + g_attnP[3][o]);
    }

    float acc[9];
#pragma unroll
    for (int t9 = 0; t9 < 9; ++t9) acc[t9] = 0.f;

    for (int cic = 0; cic < 8; ++cic) {
        __syncthreads();
        for (int t = tid; t < 4608; t += 256) {
            int c2 = t / 72;
            int rr = t % 72;
            ws[c2][rr] = weight[c2 * 576 + (cic * 8 + rr / 9) * 9 + (rr % 9)];
        }
        __syncthreads();
#pragma unroll
        for (int ci = 0; ci < 8; ++ci) {
            float av[25];
#pragma unroll
            for (int p = 0; p < 25; ++p) av[p] = as4[s][cic * 8 + ci][p];
#pragma unroll
            for (int dy = 0; dy < 3; ++dy)
#pragma unroll
                for (int dx = 0; dx < 3; ++dx) {
                    float wv = ws[cB][ci * 9 + dy * 3 + dx];
#pragma unroll
                    for (int ky = 0; ky < 3; ++ky)
#pragma unroll
                        for (int kx = 0; kx < 3; ++kx)
                            acc[ky * 3 + kx] =
                                fmaf(av[(ky + dy) * 5 + (kx + dx)], wv, acc[ky * 3 + kx]);
                }
        }
    }
#pragma unroll
    for (int t9 = 0; t9 < 9; ++t9)
        g_ak[((b * 64 + cB) * 64 + cA) * 9 + t9] = acc[t9];
}

// ---------------------------------------------------------------------------
// Kernel C2: normalize ak, build dynamic kernels -> single fp16 B tiles
// ---------------------------------------------------------------------------
__global__ void __launch_bounds__(64) kern_kernel(const float* __restrict__ weight,
                                                  const float* __restrict__ temperature) {
    const int cB  = blockIdx.x;
    const int b   = blockIdx.y;
    const int tid = threadIdx.x;  // = cA

    const float* ak = g_ak + (b * 64 + cB) * 64 * 9;
    float v[9];
    float ss = 0.f;
#pragma unroll
    for (int t9 = 0; t9 < 9; ++t9) {
        v[t9] = ak[tid * 9 + t9];
        ss = fmaf(v[t9], v[t9], ss);
    }

    __shared__ float red[64];
    red[tid] = ss;
    __syncthreads();
#pragma unroll
    for (int s = 32; s >= 1; s >>= 1) {
        if (tid < s) red[tid] += red[tid + s];
        __syncthreads();
    }
    float nrm = sqrtf(red[0]);
    float scale = temperature[0] / fmaxf(nrm, 1e-12f);

#pragma unroll
    for (int t9 = 0; t9 < 9; ++t9) {
        float vv = weight[(cB * 64 + tid) * 9 + t9] + v[t9] * scale;
        g_kt[((b * 9 + t9) * 64 + cB) * 64 + tid] = __float2half(vv);
    }
}

// ---------------------------------------------------------------------------
// Kernel D: final conv via mma.sync, M=128 (4y x 32x), 128 threads.
// A = x (hi/lo), B = kern (single). smem 68.5KB -> 3 CTAs/SM.
// smem: Ahi 26112 | Alo 26112 | B 2x8192 = 68608.
// ---------------------------------------------------------------------------
#define DA_HI  0
#define DA_LO  26112
#define DB     52224
#define D_TOT  68608

__global__ void __launch_bounds__(128) final_mma_kernel(float* __restrict__ out) {
    extern __shared__ char smem[];
    const int xt = blockIdx.x, yp = blockIdx.y, b = blockIdx.z;
    const int x0 = xt * 32, y0 = yp * 4;
    const int tid = threadIdx.x, wid = tid >> 5, lid = tid & 31;
    const uint32_t sbase = smem_u32(smem);

    float acc[2][8][4];
#pragma unroll
    for (int mt = 0; mt < 2; ++mt)
#pragma unroll
        for (int j = 0; j < 8; ++j)
#pragma unroll
            for (int e = 0; e < 4; ++e) acc[mt][j][e] = 0.f;

    const int apart = lid >> 4;
    const int brow0 = (lid & 7) + ((lid >> 4) << 3);
    const int bpart = (lid >> 3) & 1;
    int hra[2];
#pragma unroll
    for (int mt = 0; mt < 2; ++mt) {
        int m = wid * 32 + mt * 16 + (lid & 15);
        hra[mt] = ((m >> 5) + 1) * 34 + (m & 31) + 1;
    }

    auto prefetchB = [&](int tap, int bi) {
        uint32_t sb = sbase + DB + (uint32_t)bi * 8192u;
        const uint4* kp = (const uint4*)g_kt + (b * 9 + tap) * 512;
#pragma unroll
        for (int u = 0; u < 4; ++u) {
            int idx = tid + u * 128;
            int row = idx >> 3, c = idx & 7;
            uint32_t off = (uint32_t)row * 128u + (uint32_t)((c ^ (row & 7)) << 4);
            CP16(sb + off, kp + idx);
        }
    };

    // ---- one-time A halo fill (204 rows = 6y x 34x) + B tap0 ----
    for (int hr = tid; hr < 204; hr += 128) {
        int hy = hr / 34, hx = hr % 34;
        int y = y0 - 1 + hy, xg = x0 - 1 + hx;
        bool ok = ((unsigned)y < (unsigned)H_) && ((unsigned)xg < (unsigned)W_);
        long base = ((long)(b * 192 + y) * 192 + xg) * 8;
        const uint4* sh = (const uint4*)g_x_hi + base;
        const uint4* sl = (const uint4*)g_x_lo + base;
        const uint4 z = make_uint4(0, 0, 0, 0);
#pragma unroll
        for (int c = 0; c < 8; ++c) {
            uint32_t off = (uint32_t)hr * 128u + (uint32_t)((c ^ (hr & 7)) << 4);
            if (ok) {
                CP16(sbase + DA_HI + off, sh + c);
                CP16(sbase + DA_LO + off, sl + c);
            } else {
                *(uint4*)(smem + DA_HI + off) = z;
                *(uint4*)(smem + DA_LO + off) = z;
            }
        }
    }
    prefetchB(0, 0);
    CP_COMMIT();
    CP_WAIT(0);
    __syncthreads();

    for (int tap = 0; tap < 9; ++tap) {
        if (tap < 8) {
            prefetchB(tap + 1, (tap + 1) & 1);
            CP_COMMIT();
        }

        const int dOff = (tap / 3 - 1) * 34 + (tap % 3 - 1);
        const uint32_t sbh = sbase + DB + (uint32_t)(tap & 1) * 8192u;

#pragma unroll
        for (int kc = 0; kc < 4; ++kc) {
            const int acol = kc * 2 + apart;
            const int bcol = kc * 2 + bpart;
            uint32_t bf[4][4], ah[2][4], al[2][4];
#pragma unroll
            for (int nt = 0; nt < 4; ++nt) {
                int row = brow0 + nt * 16;
                ldsm_x4(bf[nt], sbh + row * 128 + ((bcol ^ (row & 7)) << 4));
            }
#pragma unroll
            for (int mt = 0; mt < 2; ++mt) {
                int hr = hra[mt] + dOff;
                uint32_t off = (uint32_t)hr * 128u + (uint32_t)((acol ^ (hr & 7)) << 4);
                ldsm_x4(ah[mt], sbase + DA_HI + off);
                ldsm_x4(al[mt], sbase + DA_LO + off);
            }
#pragma unroll
            for (int mt = 0; mt < 2; ++mt)
#pragma unroll
                for (int j = 0; j < 8; ++j) {
                    const uint32_t* bp = &bf[j >> 1][2 * (j & 1)];
                    mma_fp16(acc[mt][j], ah[mt], bp);
                    mma_fp16(acc[mt][j], al[mt], bp);
                }
        }
        CP_WAIT(0);
        __syncthreads();
    }

    // epilogue: stage fp32 [m][oc] (stride 65, reuse A region), coalesced store
    float* st = (float*)smem;
#pragma unroll
    for (int mt = 0; mt < 2; ++mt)
#pragma unroll
        for (int j = 0; j < 8; ++j)
#pragma unroll
            for (int e = 0; e < 4; ++e) {
                int row = wid * 32 + mt * 16 + (lid >> 2) + ((e >> 1) << 3);
                int col = j * 8 + (lid & 3) * 2 + (e & 1);
                st[row * 65 + col] = acc[mt][j][e];
            }
    __syncthreads();

    for (int t = tid; t < 8192; t += 128) {
        int oc = t >> 7, m = t & 127;
        float v = fmaxf(st[m * 65 + oc], 0.f);
        out[((long)(b * 64 + oc) * 192 + (y0 + (m >> 5))) * 192 + x0 + (m & 31)] = v;
    }
}

// ---------------------------------------------------------------------------
// Launch
// ---------------------------------------------------------------------------
extern "C" void kernel_launch(void* const* d_in, const int* in_sizes, int n_in,
                              void* d_out, int out_size) {
    const float* x    = (const float*)d_in[0];  // (16,64,192,192)
    const float* w_qk = (const float*)d_in[1];  // (128,64,3,3)
    const float* wgt  = (const float*)d_in[2];  // (64,64,3,3)
    const float* temp = (const float*)d_in[3];  // (1,1,1)
    float* out = (float*)d_out;                 // (16,64,192,192)

    cudaFuncSetAttribute(qk_mma_kernel, cudaFuncAttributeMaxDynamicSharedMemorySize, QK_TOT);
    cudaFuncSetAttribute(attn_mma_kernel, cudaFuncAttributeMaxDynamicSharedMemorySize, AT_TOT);
    cudaFuncSetAttribute(final_mma_kernel, cudaFuncAttributeMaxDynamicSharedMemorySize, D_TOT);

    xcl_kernel<<<dim3(576, 17), 256>>>(x, w_qk);               // 0
    qk_mma_kernel<<<dim3(32, 2, 16), 128, QK_TOT>>>();         // 1
    attn_mma_kernel<<<dim3(25, 4, 16), 128, AT_TOT>>>();       // 2
    akconv_kernel<<<dim3(16, 16), 256>>>(wgt);                 // 3
    kern_kernel<<<dim3(64, 16), 64>>>(wgt, temp);              // 4
    final_mma_kernel<<<dim3(6, 48, 16), 128, D_TOT>>>(out);    // 5 (ncu slot)
}

// round 13
// speedup vs baseline: 7.5307x; 1.1216x over previous
#include <cuda_runtime.h>
#include <cuda_fp16.h>
#include <cstdint>
#include <math.h>

// Problem constants
#define B_  16
#define C_  64
#define H_  192
#define W_  192
#define H2_ 64
#define W2_ 64
#define S_  5

// ---------------------------------------------------------------------------
// Scratch buffers (static device globals; zero-initialized at load)
// ---------------------------------------------------------------------------
__device__ float g_attnP[4][B_ * C_ * C_ * S_ * S_];  // 4 K-quarter partials
__device__ float g_ak[B_ * C_ * C_ * 9];              // transposed ak (pre-norm)

// fp16 operands. Split (hi/lo) ONLY where the error budget requires it:
// qk's x (feeds 3 downstream stages) and attn's k. final uses x_hi only.
__device__ __align__(16) __half g_x_hi[B_ * H_ * W_ * C_];  // channel-last
__device__ __align__(16) __half g_x_lo[B_ * H_ * W_ * C_];
__device__ __align__(16) __half g_kt[B_ * 9 * C_ * C_];     // [b][tap][oc][ci] single
__device__ __align__(16) __half g_wq[2 * 9 * 64 * 64];      // [half][tap][oc][ci] single
// attn A operand: k channel-major [b][co][4096], split
__device__ __align__(16) __half g_kh[B_ * C_ * 4096];
__device__ __align__(16) __half g_kl[B_ * C_ * 4096];
// attn B operand: q shifted copies [dj(5)][b][ci][68 rows (zero-pad)][64], single
__device__ __align__(16) __half g_q5[5 * B_ * C_ * 68 * 64];

__device__ __forceinline__ uint32_t smem_u32(const void* p) {
    uint32_t a;
    asm("{ .reg .u64 t; cvta.to.shared.u64 t, %1; cvt.u32.u64 %0, t; }" : "=r"(a) : "l"(p));
    return a;
}

__device__ __forceinline__ void ldsm_x4(uint32_t* r, uint32_t addr) {
    asm volatile("ldmatrix.sync.aligned.m8n8.x4.shared.b16 {%0,%1,%2,%3}, [%4];"
                 : "=r"(r[0]), "=r"(r[1]), "=r"(r[2]), "=r"(r[3])
                 : "r"(addr));
}

// mma.sync m16n8k16 fp16 -> fp32 accum (in-place)
__device__ __forceinline__ void mma_fp16(float* d, const uint32_t* a, const uint32_t* b) {
    asm volatile(
        "mma.sync.aligned.m16n8k16.row.col.f32.f16.f16.f32 "
        "{%0,%1,%2,%3}, {%4,%5,%6,%7}, {%8,%9}, {%0,%1,%2,%3};"
        : "+f"(d[0]), "+f"(d[1]), "+f"(d[2]), "+f"(d[3])
        : "r"(a[0]), "r"(a[1]), "r"(a[2]), "r"(a[3]), "r"(b[0]), "r"(b[1]));
}

#define CP16(dst, src) \
    asm volatile("cp.async.cg.shared.global [%0], [%1], 16;" ::"r"(dst), "l"(src))
#define CP_COMMIT() asm volatile("cp.async.commit_group;" ::: "memory")
#define CP_WAIT(N) asm volatile("cp.async.wait_group %0;" ::"n"(N) : "memory")

__device__ __forceinline__ void split_fp16(float v, __half& h, __half& l) {
    h = __float2half(v);
    l = __float2half(v - __half2float(h));
}

// ---------------------------------------------------------------------------
// Kernel E0: x (fp32 NCHW) -> channel-last fp16 hi/lo; b==16 repacks w_qk.
// ---------------------------------------------------------------------------
__global__ void __launch_bounds__(256) xcl_kernel(const float* __restrict__ x,
                                                  const float* __restrict__ w_qk) {
    const int seg = blockIdx.x;
    const int b = blockIdx.y;
    const int tid = threadIdx.x;

    if (b == 16) {
        if (seg < 128) {
            const int half = seg >> 6, oc = seg & 63;
            for (int t = tid; t < 576; t += 256) {
                int ci = t / 9, tap = t % 9;
                g_wq[((half * 9 + tap) * 64 + oc) * 64 + ci] =
                    __float2half(w_qk[(seg * 64 + ci) * 9 + tap]);
            }
        }
        return;
    }

    const int y = seg / 3;
    const int x0 = (seg % 3) * 64;
    __shared__ float s[64][65];

#pragma unroll
    for (int i = 0; i < 16; ++i) {
        int idx = tid + i * 256;
        int c = idx >> 6, p = idx & 63;
        s[p][c] = x[((b * 64 + c) * 192 + y) * 192 + x0 + p];
    }
    __syncthreads();
#pragma unroll
    for (int i = 0; i < 16; ++i) {
        int idx = tid + i * 256;
        int p = idx >> 6, c = idx & 63;
        __half h, l;
        split_fp16(s[p][c], h, l);
        int o = ((b * 192 + y) * 192 + x0 + p) * 64 + c;
        g_x_hi[o] = h;
        g_x_lo[o] = l;
    }
}

// ---------------------------------------------------------------------------
// Kernel A: qk conv via mma.sync (stride-3), cp.async tap double-buffer.
// A = x (hi/lo fp16 split), B = w_qk (single fp16). 2 mma terms.
// FUSED epilogue: k -> g_kh/g_kl (split), q -> g_q5 (5 dj copies, single).
// grid (32 mtiles, 2 half, 16 b), 128 thr. smem 2 x 40KB.
// ---------------------------------------------------------------------------
#define QK_AL   16384
#define QK_B    32768
#define QK_BUF  40960
#define QK_TOT  81920

__global__ void __launch_bounds__(128) qk_mma_kernel() {
    extern __shared__ char smem[];
    const int mtile = blockIdx.x, half = blockIdx.y, b = blockIdx.z;
    const int i0 = mtile * 2;
    const int tid = threadIdx.x, wid = tid >> 5, lid = tid & 31;
    const uint32_t sbase = smem_u32(smem);

    const int r = tid;
    const int ri = i0 + (r >> 6), rj = r & 63;

    float acc[2][8][4];
#pragma unroll
    for (int mt = 0; mt < 2; ++mt)
#pragma unroll
        for (int j = 0; j < 8; ++j)
#pragma unroll
            for (int e = 0; e < 4; ++e) acc[mt][j][e] = 0.f;

    const int arow0 = wid * 32 + (lid & 15);
    const int apart = lid >> 4;
    const int brow0 = (lid & 7) + ((lid >> 4) << 3);
    const int bpart = (lid >> 3) & 1;

    auto prefetch = [&](int tap, int bi) {
        uint32_t sb = sbase + (uint32_t)bi * QK_BUF;
        const int dy = tap / 3, dx = tap % 3;
        long abase = ((long)(b * 192 + 3 * ri + dy) * 192 + 3 * rj + dx) * 8;
        const uint4* sh = (const uint4*)g_x_hi + abase;
        const uint4* sl = (const uint4*)g_x_lo + abase;
#pragma unroll
        for (int c = 0; c < 8; ++c) {
            uint32_t off = (uint32_t)r * 128u + (uint32_t)((c ^ (r & 7)) << 4);
            CP16(sb + off, sh + c);
            CP16(sb + QK_AL + off, sl + c);
        }
        const uint4* wp = (const uint4*)g_wq + (half * 9 + tap) * 512;
#pragma unroll
        for (int i = 0; i < 4; ++i) {
            int idx = tid + i * 128;
            int row = idx >> 3, c = idx & 7;
            uint32_t off = (uint32_t)row * 128u + (uint32_t)((c ^ (row & 7)) << 4);
            CP16(sb + QK_B + off, wp + idx);
        }
    };

    prefetch(0, 0);
    CP_COMMIT();

    for (int tap = 0; tap < 9; ++tap) {
        if (tap < 8) {
            prefetch(tap + 1, (tap + 1) & 1);
            CP_COMMIT();
            CP_WAIT(1);
        } else {
            CP_WAIT(0);
        }
        __syncthreads();

        const uint32_t sb = sbase + (uint32_t)(tap & 1) * QK_BUF;
#pragma unroll
        for (int kc = 0; kc < 4; ++kc) {
            const int acol = kc * 2 + apart;
            const int bcol = kc * 2 + bpart;
            uint32_t bf[4][4], ah[2][4], al[2][4];
#pragma unroll
            for (int nt = 0; nt < 4; ++nt) {
                int row = brow0 + nt * 16;
                ldsm_x4(bf[nt], sb + QK_B + row * 128 + ((bcol ^ (row & 7)) << 4));
            }
#pragma unroll
            for (int mt = 0; mt < 2; ++mt) {
                int row = arow0 + mt * 16;
                uint32_t off = row * 128 + ((acol ^ (row & 7)) << 4);
                ldsm_x4(ah[mt], sb + off);
                ldsm_x4(al[mt], sb + QK_AL + off);
            }
#pragma unroll
            for (int mt = 0; mt < 2; ++mt)
#pragma unroll
                for (int j = 0; j < 8; ++j) {
                    const uint32_t* bp = &bf[j >> 1][2 * (j & 1)];
                    mma_fp16(acc[mt][j], ah[mt], bp);
                    mma_fp16(acc[mt][j], al[mt], bp);
                }
        }
        __syncthreads();
    }

    // ---- fused epilogue: stage fp32 [m][ch] (stride 65), emit fp16 operands
    float* st = (float*)smem;
#pragma unroll
    for (int mt = 0; mt < 2; ++mt)
#pragma unroll
        for (int j = 0; j < 8; ++j)
#pragma unroll
            for (int e = 0; e < 4; ++e) {
                int m = wid * 32 + mt * 16 + (lid >> 2) + ((e >> 1) << 3);
                int col = j * 8 + (lid & 3) * 2 + (e & 1);
                st[m * 65 + col] = acc[mt][j][e];
            }
    __syncthreads();

    if (half) {
        // k: channel-major split
        for (int t = tid; t < 8192; t += 128) {
            int co = t >> 7, m = t & 127;
            int h = i0 + (m >> 6), w = m & 63;
            __half hh, ll;
            split_fp16(st[m * 65 + co], hh, ll);
            long o = (long)(b * 64 + co) * 4096 + h * 64 + w;
            g_kh[o] = hh;
            g_kl[o] = ll;
        }
    } else {
        // q: 5 dj-shifted padded copies, single fp16
        for (int dj = 0; dj < 5; ++dj) {
            for (int t = tid; t < 8192; t += 128) {
                int ci = t >> 7, m = t & 127;
                int h = i0 + (m >> 6), w = m & 63;
                int wsrc = w + dj - 2;
                float v = ((unsigned)wsrc < 64u) ? st[((m >> 6) * 64 + wsrc) * 65 + ci] : 0.f;
                long o = (((long)(dj * 16 + b) * 64 + ci) * 68 + (h + 2)) * 64 + w;
                g_q5[o] = __float2half(v);
            }
        }
    }
}

// ---------------------------------------------------------------------------
// Kernel B: attn via mma.sync, K SPLIT IN 4. A = k (hi/lo), B = q (single).
// grid (25, 4 quarters, 16 b), 128 thr. smem 2 x 24KB.
// ---------------------------------------------------------------------------
#define AT_KL  8192
#define AT_Q   16384
#define AT_BUF 24576
#define AT_TOT 49152

__global__ void __launch_bounds__(128) attn_mma_kernel() {
    extern __shared__ char smem[];
    const int dj = blockIdx.x % 5, di = blockIdx.x / 5;
    const int quarter = blockIdx.y, b = blockIdx.z;
    const int tid = threadIdx.x, wid = tid >> 5, lid = tid & 31;
    const uint32_t sbase = smem_u32(smem);
    const int mrow = (wid & 1) * 32, ncol = (wid >> 1) * 32;

    float acc[2][4][4];
#pragma unroll
    for (int mt = 0; mt < 2; ++mt)
#pragma unroll
        for (int j = 0; j < 4; ++j)
#pragma unroll
            for (int e = 0; e < 4; ++e) acc[mt][j][e] = 0.f;

    const uint4* __restrict__ kh = (const uint4*)g_kh + (long)b * 64 * 512;
    const uint4* __restrict__ kl = (const uint4*)g_kl + (long)b * 64 * 512;
    const uint4* __restrict__ qp = (const uint4*)g_q5 + (long)(dj * 16 + b) * 64 * 544 + di * 8;

    const int apart = lid >> 4;
    const int brow_l = (lid & 7) + ((lid >> 4) << 3);
    const int bpart = (lid >> 3) & 1;
    const int kc0 = quarter * 16;

    auto prefetch = [&](int kc, int bi) {
        uint32_t sb = sbase + (uint32_t)bi * AT_BUF;
#pragma unroll
        for (int a = 0; a < 3; ++a) {
            const uint4* gp = (a == 0) ? kh : (a == 1) ? kl : qp;
            const int stride = (a < 2) ? 512 : 544;
#pragma unroll
            for (int u = 0; u < 4; ++u) {
                int idx = tid + u * 128;  // 0..511
                int row = idx >> 3, c = idx & 7;
                uint32_t off = (uint32_t)a * 8192u + (uint32_t)row * 128u +
                               (uint32_t)((c ^ (row & 7)) << 4);
                CP16(sb + off, gp + (long)row * stride + kc * 8 + c);
            }
        }
    };

    prefetch(kc0, 0);
    CP_COMMIT();

    for (int kc2 = 0; kc2 < 16; ++kc2) {
        if (kc2 < 15) {
            prefetch(kc0 + kc2 + 1, (kc2 + 1) & 1);
            CP_COMMIT();
            CP_WAIT(1);
        } else {
            CP_WAIT(0);
        }
        __syncthreads();

        const uint32_t sb = sbase + (uint32_t)(kc2 & 1) * AT_BUF;
#pragma unroll
        for (int kk = 0; kk < 4; ++kk) {
            uint32_t ah[2][4], al[2][4], bh[2][4];
            const int acol = kk * 2 + apart;
            const int bcol = kk * 2 + bpart;
#pragma unroll
            for (int mt = 0; mt < 2; ++mt) {
                int row = mrow + mt * 16 + (lid & 15);
                uint32_t off = (uint32_t)row * 128u + (uint32_t)((acol ^ (row & 7)) << 4);
                ldsm_x4(ah[mt], sb + off);
                ldsm_x4(al[mt], sb + AT_KL + off);
            }
#pragma unroll
            for (int nt = 0; nt < 2; ++nt) {
                int row = ncol + nt * 16 + brow_l;
                uint32_t off = (uint32_t)row * 128u + (uint32_t)((bcol ^ (row & 7)) << 4);
                ldsm_x4(bh[nt], sb + AT_Q + off);
            }
#pragma unroll
            for (int mt = 0; mt < 2; ++mt)
#pragma unroll
                for (int j = 0; j < 4; ++j) {
                    const uint32_t* bp = &bh[j >> 1][2 * (j & 1)];
                    mma_fp16(acc[mt][j], ah[mt], bp);
                    mma_fp16(acc[mt][j], al[mt], bp);
                }
        }
        __syncthreads();
    }

    float* dst = g_attnP[quarter];
#pragma unroll
    for (int mt = 0; mt < 2; ++mt)
#pragma unroll
        for (int j = 0; j < 4; ++j)
#pragma unroll
            for (int e = 0; e < 4; ++e) {
                int co = mrow + mt * 16 + (lid >> 2) + ((e >> 1) << 3);
                int ci = ncol + j * 8 + (lid & 3) * 2 + (e & 1);
                dst[((b * 64 + co) * 64 + ci) * 25 + di * 5 + dj] = acc[mt][j][e];
            }
}

// ---------------------------------------------------------------------------
// Kernel C1: ak conv (VALID 3x3 over 5x5 attn), sums the 4 K-quarter partials.
// grid (32 cAg, 16 b), 128 thr = 2 cA x 64 cB (was 256 blocks -> grid-starved).
// ---------------------------------------------------------------------------
__global__ void __launch_bounds__(128) akconv_kernel(const float* __restrict__ weight) {
    const int cAg = blockIdx.x;   // 0..31
    const int b   = blockIdx.y;
    const int tid = threadIdx.x;
    const int s  = tid >> 6;      // 0..1
    const int cB = tid & 63;
    const int cA = cAg * 2 + s;

    __shared__ float as4[2][64][25];
    __shared__ float ws[64][73];

    for (int t = tid; t < 3200; t += 128) {
        int a = t / 1600, r = t % 1600;
        long o = (long)(b * 64 + cAg * 2 + a) * 1600 + r;
        as4[a][r / 25][r % 25] =
            (g_attnP[0][o] + g_attnP[1][o]) + (g_attnP[2][o] + g_attnP[3][o]);
    }

    float acc[9];
#pragma unroll
    for (int t9 = 0; t9 < 9; ++t9) acc[t9] = 0.f;

    for (int cic = 0; cic < 8; ++cic) {
        __syncthreads();
        for (int t = tid; t < 4608; t += 128) {
            int c2 = t / 72;
            int rr = t % 72;
            ws[c2][rr] = weight[c2 * 576 + (cic * 8 + rr / 9) * 9 + (rr % 9)];
        }
        __syncthreads();
#pragma unroll
        for (int ci = 0; ci < 8; ++ci) {
            float av[25];
#pragma unroll
            for (int p = 0; p < 25; ++p) av[p] = as4[s][cic * 8 + ci][p];
#pragma unroll
            for (int dy = 0; dy < 3; ++dy)
#pragma unroll
                for (int dx = 0; dx < 3; ++dx) {
                    float wv = ws[cB][ci * 9 + dy * 3 + dx];
#pragma unroll
                    for (int ky = 0; ky < 3; ++ky)
#pragma unroll
                        for (int kx = 0; kx < 3; ++kx)
                            acc[ky * 3 + kx] =
                                fmaf(av[(ky + dy) * 5 + (kx + dx)], wv, acc[ky * 3 + kx]);
                }
        }
    }
#pragma unroll
    for (int t9 = 0; t9 < 9; ++t9)
        g_ak[((b * 64 + cB) * 64 + cA) * 9 + t9] = acc[t9];
}

// ---------------------------------------------------------------------------
// Kernel C2: normalize ak, build dynamic kernels -> single fp16 B tiles
// ---------------------------------------------------------------------------
__global__ void __launch_bounds__(64) kern_kernel(const float* __restrict__ weight,
                                                  const float* __restrict__ temperature) {
    const int cB  = blockIdx.x;
    const int b   = blockIdx.y;
    const int tid = threadIdx.x;  // = cA

    const float* ak = g_ak + (b * 64 + cB) * 64 * 9;
    float v[9];
    float ss = 0.f;
#pragma unroll
    for (int t9 = 0; t9 < 9; ++t9) {
        v[t9] = ak[tid * 9 + t9];
        ss = fmaf(v[t9], v[t9], ss);
    }

    __shared__ float red[64];
    red[tid] = ss;
    __syncthreads();
#pragma unroll
    for (int s = 32; s >= 1; s >>= 1) {
        if (tid < s) red[tid] += red[tid + s];
        __syncthreads();
    }
    float nrm = sqrtf(red[0]);
    float scale = temperature[0] / fmaxf(nrm, 1e-12f);

#pragma unroll
    for (int t9 = 0; t9 < 9; ++t9) {
        float vv = weight[(cB * 64 + tid) * 9 + t9] + v[t9] * scale;
        g_kt[((b * 9 + t9) * 64 + cB) * 64 + tid] = __float2half(vv);
    }
}

// ---------------------------------------------------------------------------
// Kernel D: final conv via mma.sync, M=128 (4y x 32x), 128 threads.
// A = x_hi ONLY (single term; error budget allows it), B = kern (single).
// smem: A 26112 | B 2x8192 = 42496 -> 5 CTAs/SM.
// ---------------------------------------------------------------------------
#define DA_HI  0
#define DB     26112
#define D_TOT  42496

__global__ void __launch_bounds__(128) final_mma_kernel(float* __restrict__ out) {
    extern __shared__ char smem[];
    const int xt = blockIdx.x, yp = blockIdx.y, b = blockIdx.z;
    const int x0 = xt * 32, y0 = yp * 4;
    const int tid = threadIdx.x, wid = tid >> 5, lid = tid & 31;
    const uint32_t sbase = smem_u32(smem);

    float acc[2][8][4];
#pragma unroll
    for (int mt = 0; mt < 2; ++mt)
#pragma unroll
        for (int j = 0; j < 8; ++j)
#pragma unroll
            for (int e = 0; e < 4; ++e) acc[mt][j][e] = 0.f;

    const int apart = lid >> 4;
    const int brow0 = (lid & 7) + ((lid >> 4) << 3);
    const int bpart = (lid >> 3) & 1;
    int hra[2];
#pragma unroll
    for (int mt = 0; mt < 2; ++mt) {
        int m = wid * 32 + mt * 16 + (lid & 15);
        hra[mt] = ((m >> 5) + 1) * 34 + (m & 31) + 1;
    }

    auto prefetchB = [&](int tap, int bi) {
        uint32_t sb = sbase + DB + (uint32_t)bi * 8192u;
        const uint4* kp = (const uint4*)g_kt + (b * 9 + tap) * 512;
#pragma unroll
        for (int u = 0; u < 4; ++u) {
            int idx = tid + u * 128;
            int row = idx >> 3, c = idx & 7;
            uint32_t off = (uint32_t)row * 128u + (uint32_t)((c ^ (row & 7)) << 4);
            CP16(sb + off, kp + idx);
        }
    };

    // ---- one-time A halo fill (204 rows = 6y x 34x) + B tap0 ----
    for (int hr = tid; hr < 204; hr += 128) {
        int hy = hr / 34, hx = hr % 34;
        int y = y0 - 1 + hy, xg = x0 - 1 + hx;
        bool ok = ((unsigned)y < (unsigned)H_) && ((unsigned)xg < (unsigned)W_);
        long base = ((long)(b * 192 + y) * 192 + xg) * 8;
        const uint4* sh = (const uint4*)g_x_hi + base;
        const uint4 z = make_uint4(0, 0, 0, 0);
#pragma unroll
        for (int c = 0; c < 8; ++c) {
            uint32_t off = (uint32_t)hr * 128u + (uint32_t)((c ^ (hr & 7)) << 4);
            if (ok) {
                CP16(sbase + DA_HI + off, sh + c);
            } else {
                *(uint4*)(smem + DA_HI + off) = z;
            }
        }
    }
    prefetchB(0, 0);
    CP_COMMIT();
    CP_WAIT(0);
    __syncthreads();

    for (int tap = 0; tap < 9; ++tap) {
        if (tap < 8) {
            prefetchB(tap + 1, (tap + 1) & 1);
            CP_COMMIT();
        }

        const int dOff = (tap / 3 - 1) * 34 + (tap % 3 - 1);
        const uint32_t sbh = sbase + DB + (uint32_t)(tap & 1) * 8192u;

#pragma unroll
        for (int kc = 0; kc < 4; ++kc) {
            const int acol = kc * 2 + apart;
            const int bcol = kc * 2 + bpart;
            uint32_t bf[4][4], ah[2][4];
#pragma unroll
            for (int nt = 0; nt < 4; ++nt) {
                int row = brow0 + nt * 16;
                ldsm_x4(bf[nt], sbh + row * 128 + ((bcol ^ (row & 7)) << 4));
            }
#pragma unroll
            for (int mt = 0; mt < 2; ++mt) {
                int hr = hra[mt] + dOff;
                uint32_t off = (uint32_t)hr * 128u + (uint32_t)((acol ^ (hr & 7)) << 4);
                ldsm_x4(ah[mt], sbase + DA_HI + off);
            }
#pragma unroll
            for (int mt = 0; mt < 2; ++mt)
#pragma unroll
                for (int j = 0; j < 8; ++j)
                    mma_fp16(acc[mt][j], ah[mt], &bf[j >> 1][2 * (j & 1)]);
        }
        CP_WAIT(0);
        __syncthreads();
    }

    // epilogue: stage fp32 [m][oc] (stride 65, reuse A region), coalesced store
    float* st = (float*)smem;
#pragma unroll
    for (int mt = 0; mt < 2; ++mt)
#pragma unroll
        for (int j = 0; j < 8; ++j)
#pragma unroll
            for (int e = 0; e < 4; ++e) {
                int row = wid * 32 + mt * 16 + (lid >> 2) + ((e >> 1) << 3);
                int col = j * 8 + (lid & 3) * 2 + (e & 1);
                st[row * 65 + col] = acc[mt][j][e];
            }
    __syncthreads();

    for (int t = tid; t < 8192; t += 128) {
        int oc = t >> 7, m = t & 127;
        float v = fmaxf(st[m * 65 + oc], 0.f);
        out[((long)(b * 64 + oc) * 192 + (y0 + (m >> 5))) * 192 + x0 + (m & 31)] = v;
    }
}

// ---------------------------------------------------------------------------
// Launch
// ---------------------------------------------------------------------------
extern "C" void kernel_launch(void* const* d_in, const int* in_sizes, int n_in,
                              void* d_out, int out_size) {
    const float* x    = (const float*)d_in[0];  // (16,64,192,192)
    const float* w_qk = (const float*)d_in[1];  // (128,64,3,3)
    const float* wgt  = (const float*)d_in[2];  // (64,64,3,3)
    const float* temp = (const float*)d_in[3];  // (1,1,1)
    float* out = (float*)d_out;                 // (16,64,192,192)

    cudaFuncSetAttribute(qk_mma_kernel, cudaFuncAttributeMaxDynamicSharedMemorySize, QK_TOT);
    cudaFuncSetAttribute(attn_mma_kernel, cudaFuncAttributeMaxDynamicSharedMemorySize, AT_TOT);
    cudaFuncSetAttribute(final_mma_kernel, cudaFuncAttributeMaxDynamicSharedMemorySize, D_TOT);

    xcl_kernel<<<dim3(576, 17), 256>>>(x, w_qk);               // 0
    qk_mma_kernel<<<dim3(32, 2, 16), 128, QK_TOT>>>();         // 1
    attn_mma_kernel<<<dim3(25, 4, 16), 128, AT_TOT>>>();       // 2
    akconv_kernel<<<dim3(32, 16), 128>>>(wgt);                 // 3
    kern_kernel<<<dim3(64, 16), 64>>>(wgt, temp);              // 4
    final_mma_kernel<<<dim3(6, 48, 16), 128, D_TOT>>>(out);    // 5 (ncu slot)
}

// round 14
// speedup vs baseline: 8.4849x; 1.1267x over previous
#include <cuda_runtime.h>
#include <cuda_fp16.h>
#include <cstdint>
#include <math.h>

// Problem constants
#define B_  16
#define C_  64
#define H_  192
#define W_  192
#define H2_ 64
#define W2_ 64
#define S_  5

// ---------------------------------------------------------------------------
// Scratch buffers (static device globals; zero-initialized at load)
// ---------------------------------------------------------------------------
__device__ float g_attnP[2][B_ * C_ * C_ * S_ * S_];  // 2 K-half partials
__device__ float g_ak[B_ * C_ * C_ * 9];              // transposed ak (pre-norm)

// fp16 operands. Split (hi/lo) ONLY on qk's x (feeds 3 downstream stages).
__device__ __align__(16) __half g_x_hi[B_ * H_ * W_ * C_];  // channel-last
__device__ __align__(16) __half g_x_lo[B_ * H_ * W_ * C_];
__device__ __align__(16) __half g_kt[B_ * 9 * C_ * C_];     // [b][tap][oc][ci] single
__device__ __align__(16) __half g_wq[2 * 9 * 64 * 64];      // [half][tap][oc][ci] single
// attn A operand: k channel-major [b][co][4096], SINGLE fp16
__device__ __align__(16) __half g_k1[B_ * C_ * 4096];
// attn B operand: q shifted copies [dj(5)][b][ci][68 rows (zero-pad)][64], single
__device__ __align__(16) __half g_q5[5 * B_ * C_ * 68 * 64];

__device__ __forceinline__ uint32_t smem_u32(const void* p) {
    uint32_t a;
    asm("{ .reg .u64 t; cvta.to.shared.u64 t, %1; cvt.u32.u64 %0, t; }" : "=r"(a) : "l"(p));
    return a;
}

__device__ __forceinline__ void ldsm_x4(uint32_t* r, uint32_t addr) {
    asm volatile("ldmatrix.sync.aligned.m8n8.x4.shared.b16 {%0,%1,%2,%3}, [%4];"
                 : "=r"(r[0]), "=r"(r[1]), "=r"(r[2]), "=r"(r[3])
                 : "r"(addr));
}

// mma.sync m16n8k16 fp16 -> fp32 accum (in-place)
__device__ __forceinline__ void mma_fp16(float* d, const uint32_t* a, const uint32_t* b) {
    asm volatile(
        "mma.sync.aligned.m16n8k16.row.col.f32.f16.f16.f32 "
        "{%0,%1,%2,%3}, {%4,%5,%6,%7}, {%8,%9}, {%0,%1,%2,%3};"
        : "+f"(d[0]), "+f"(d[1]), "+f"(d[2]), "+f"(d[3])
        : "r"(a[0]), "r"(a[1]), "r"(a[2]), "r"(a[3]), "r"(b[0]), "r"(b[1]));
}

#define CP16(dst, src) \
    asm volatile("cp.async.cg.shared.global [%0], [%1], 16;" ::"r"(dst), "l"(src))
#define CP_COMMIT() asm volatile("cp.async.commit_group;" ::: "memory")
#define CP_WAIT(N) asm volatile("cp.async.wait_group %0;" ::"n"(N) : "memory")

__device__ __forceinline__ void split_fp16(float v, __half& h, __half& l) {
    h = __float2half(v);
    l = __float2half(v - __half2float(h));
}

// ---------------------------------------------------------------------------
// Kernel E0: x (fp32 NCHW) -> channel-last fp16 hi/lo; b==16 repacks w_qk.
// ---------------------------------------------------------------------------
__global__ void __launch_bounds__(256) xcl_kernel(const float* __restrict__ x,
                                                  const float* __restrict__ w_qk) {
    const int seg = blockIdx.x;
    const int b = blockIdx.y;
    const int tid = threadIdx.x;

    if (b == 16) {
        if (seg < 128) {
            const int half = seg >> 6, oc = seg & 63;
            for (int t = tid; t < 576; t += 256) {
                int ci = t / 9, tap = t % 9;
                g_wq[((half * 9 + tap) * 64 + oc) * 64 + ci] =
                    __float2half(w_qk[(seg * 64 + ci) * 9 + tap]);
            }
        }
        return;
    }

    const int y = seg / 3;
    const int x0 = (seg % 3) * 64;
    __shared__ float s[64][65];

#pragma unroll
    for (int i = 0; i < 16; ++i) {
        int idx = tid + i * 256;
        int c = idx >> 6, p = idx & 63;
        s[p][c] = x[((b * 64 + c) * 192 + y) * 192 + x0 + p];
    }
    __syncthreads();
#pragma unroll
    for (int i = 0; i < 16; ++i) {
        int idx = tid + i * 256;
        int p = idx >> 6, c = idx & 63;
        __half h, l;
        split_fp16(s[p][c], h, l);
        int o = ((b * 192 + y) * 192 + x0 + p) * 64 + c;
        g_x_hi[o] = h;
        g_x_lo[o] = l;
    }
}

// ---------------------------------------------------------------------------
// Kernel A: qk conv via mma.sync (stride-3), cp.async tap double-buffer.
// A = x (hi/lo fp16 split), B = w_qk (single fp16). 2 mma terms.
// FUSED epilogue: k -> g_k1 (single), q -> g_q5 (5 dj copies, single).
// grid (32 mtiles, 2 half, 16 b), 128 thr. smem 2 x 40KB.
// ---------------------------------------------------------------------------
#define QK_AL   16384
#define QK_B    32768
#define QK_BUF  40960
#define QK_TOT  81920

__global__ void __launch_bounds__(128) qk_mma_kernel() {
    extern __shared__ char smem[];
    const int mtile = blockIdx.x, half = blockIdx.y, b = blockIdx.z;
    const int i0 = mtile * 2;
    const int tid = threadIdx.x, wid = tid >> 5, lid = tid & 31;
    const uint32_t sbase = smem_u32(smem);

    const int r = tid;
    const int ri = i0 + (r >> 6), rj = r & 63;

    float acc[2][8][4];
#pragma unroll
    for (int mt = 0; mt < 2; ++mt)
#pragma unroll
        for (int j = 0; j < 8; ++j)
#pragma unroll
            for (int e = 0; e < 4; ++e) acc[mt][j][e] = 0.f;

    const int arow0 = wid * 32 + (lid & 15);
    const int apart = lid >> 4;
    const int brow0 = (lid & 7) + ((lid >> 4) << 3);
    const int bpart = (lid >> 3) & 1;

    auto prefetch = [&](int tap, int bi) {
        uint32_t sb = sbase + (uint32_t)bi * QK_BUF;
        const int dy = tap / 3, dx = tap % 3;
        long abase = ((long)(b * 192 + 3 * ri + dy) * 192 + 3 * rj + dx) * 8;
        const uint4* sh = (const uint4*)g_x_hi + abase;
        const uint4* sl = (const uint4*)g_x_lo + abase;
#pragma unroll
        for (int c = 0; c < 8; ++c) {
            uint32_t off = (uint32_t)r * 128u + (uint32_t)((c ^ (r & 7)) << 4);
            CP16(sb + off, sh + c);
            CP16(sb + QK_AL + off, sl + c);
        }
        const uint4* wp = (const uint4*)g_wq + (half * 9 + tap) * 512;
#pragma unroll
        for (int i = 0; i < 4; ++i) {
            int idx = tid + i * 128;
            int row = idx >> 3, c = idx & 7;
            uint32_t off = (uint32_t)row * 128u + (uint32_t)((c ^ (row & 7)) << 4);
            CP16(sb + QK_B + off, wp + idx);
        }
    };

    prefetch(0, 0);
    CP_COMMIT();

    for (int tap = 0; tap < 9; ++tap) {
        if (tap < 8) {
            prefetch(tap + 1, (tap + 1) & 1);
            CP_COMMIT();
            CP_WAIT(1);
        } else {
            CP_WAIT(0);
        }
        __syncthreads();

        const uint32_t sb = sbase + (uint32_t)(tap & 1) * QK_BUF;
#pragma unroll
        for (int kc = 0; kc < 4; ++kc) {
            const int acol = kc * 2 + apart;
            const int bcol = kc * 2 + bpart;
            uint32_t bf[4][4], ah[2][4], al[2][4];
#pragma unroll
            for (int nt = 0; nt < 4; ++nt) {
                int row = brow0 + nt * 16;
                ldsm_x4(bf[nt], sb + QK_B + row * 128 + ((bcol ^ (row & 7)) << 4));
            }
#pragma unroll
            for (int mt = 0; mt < 2; ++mt) {
                int row = arow0 + mt * 16;
                uint32_t off = row * 128 + ((acol ^ (row & 7)) << 4);
                ldsm_x4(ah[mt], sb + off);
                ldsm_x4(al[mt], sb + QK_AL + off);
            }
#pragma unroll
            for (int mt = 0; mt < 2; ++mt)
#pragma unroll
                for (int j = 0; j < 8; ++j) {
                    const uint32_t* bp = &bf[j >> 1][2 * (j & 1)];
                    mma_fp16(acc[mt][j], ah[mt], bp);
                    mma_fp16(acc[mt][j], al[mt], bp);
                }
        }
        __syncthreads();
    }

    // ---- fused epilogue: stage fp32 [m][ch] (stride 65), emit fp16 operands
    float* st = (float*)smem;
#pragma unroll
    for (int mt = 0; mt < 2; ++mt)
#pragma unroll
        for (int j = 0; j < 8; ++j)
#pragma unroll
            for (int e = 0; e < 4; ++e) {
                int m = wid * 32 + mt * 16 + (lid >> 2) + ((e >> 1) << 3);
                int col = j * 8 + (lid & 3) * 2 + (e & 1);
                st[m * 65 + col] = acc[mt][j][e];
            }
    __syncthreads();

    if (half) {
        // k: channel-major single fp16
        for (int t = tid; t < 8192; t += 128) {
            int co = t >> 7, m = t & 127;
            int h = i0 + (m >> 6), w = m & 63;
            long o = (long)(b * 64 + co) * 4096 + h * 64 + w;
            g_k1[o] = __float2half(st[m * 65 + co]);
        }
    } else {
        // q: 5 dj-shifted padded copies, single fp16
        for (int dj = 0; dj < 5; ++dj) {
            for (int t = tid; t < 8192; t += 128) {
                int ci = t >> 7, m = t & 127;
                int h = i0 + (m >> 6), w = m & 63;
                int wsrc = w + dj - 2;
                float v = ((unsigned)wsrc < 64u) ? st[((m >> 6) * 64 + wsrc) * 65 + ci] : 0.f;
                long o = (((long)(dj * 16 + b) * 64 + ci) * 68 + (h + 2)) * 64 + w;
                g_q5[o] = __float2half(v);
            }
        }
    }
}

// ---------------------------------------------------------------------------
// Kernel B: attn via mma.sync, K SPLIT IN 2. A = k (single), B = q (single).
// 1-term mma (error budget spends the k_lo term). grid (25, 2, 16), 128 thr.
// smem 2 x 16KB -> 7 CTAs/SM.
// ---------------------------------------------------------------------------
#define AT_Q   8192
#define AT_BUF 16384
#define AT_TOT 32768

__global__ void __launch_bounds__(128) attn_mma_kernel() {
    extern __shared__ char smem[];
    const int dj = blockIdx.x % 5, di = blockIdx.x / 5;
    const int half = blockIdx.y, b = blockIdx.z;
    const int tid = threadIdx.x, wid = tid >> 5, lid = tid & 31;
    const uint32_t sbase = smem_u32(smem);
    const int mrow = (wid & 1) * 32, ncol = (wid >> 1) * 32;

    float acc[2][4][4];
#pragma unroll
    for (int mt = 0; mt < 2; ++mt)
#pragma unroll
        for (int j = 0; j < 4; ++j)
#pragma unroll
            for (int e = 0; e < 4; ++e) acc[mt][j][e] = 0.f;

    const uint4* __restrict__ kp = (const uint4*)g_k1 + (long)b * 64 * 512;
    const uint4* __restrict__ qp = (const uint4*)g_q5 + (long)(dj * 16 + b) * 64 * 544 + di * 8;

    const int apart = lid >> 4;
    const int brow_l = (lid & 7) + ((lid >> 4) << 3);
    const int bpart = (lid >> 3) & 1;
    const int kc0 = half * 32;

    auto prefetch = [&](int kc, int bi) {
        uint32_t sb = sbase + (uint32_t)bi * AT_BUF;
#pragma unroll
        for (int a = 0; a < 2; ++a) {
            const uint4* gp = (a == 0) ? kp : qp;
            const int stride = (a == 0) ? 512 : 544;
#pragma unroll
            for (int u = 0; u < 4; ++u) {
                int idx = tid + u * 128;  // 0..511
                int row = idx >> 3, c = idx & 7;
                uint32_t off = (uint32_t)a * 8192u + (uint32_t)row * 128u +
                               (uint32_t)((c ^ (row & 7)) << 4);
                CP16(sb + off, gp + (long)row * stride + kc * 8 + c);
            }
        }
    };

    prefetch(kc0, 0);
    CP_COMMIT();

    for (int kc2 = 0; kc2 < 32; ++kc2) {
        if (kc2 < 31) {
            prefetch(kc0 + kc2 + 1, (kc2 + 1) & 1);
            CP_COMMIT();
            CP_WAIT(1);
        } else {
            CP_WAIT(0);
        }
        __syncthreads();

        const uint32_t sb = sbase + (uint32_t)(kc2 & 1) * AT_BUF;
#pragma unroll
        for (int kk = 0; kk < 4; ++kk) {
            uint32_t ah[2][4], bh[2][4];
            const int acol = kk * 2 + apart;
            const int bcol = kk * 2 + bpart;
#pragma unroll
            for (int mt = 0; mt < 2; ++mt) {
                int row = mrow + mt * 16 + (lid & 15);
                ldsm_x4(ah[mt], sb + row * 128 + ((acol ^ (row & 7)) << 4));
            }
#pragma unroll
            for (int nt = 0; nt < 2; ++nt) {
                int row = ncol + nt * 16 + brow_l;
                ldsm_x4(bh[nt], sb + AT_Q + row * 128 + ((bcol ^ (row & 7)) << 4));
            }
#pragma unroll
            for (int mt = 0; mt < 2; ++mt)
#pragma unroll
                for (int j = 0; j < 4; ++j)
                    mma_fp16(acc[mt][j], ah[mt], &bh[j >> 1][2 * (j & 1)]);
        }
        __syncthreads();
    }

    float* dst = g_attnP[half];
#pragma unroll
    for (int mt = 0; mt < 2; ++mt)
#pragma unroll
        for (int j = 0; j < 4; ++j)
#pragma unroll
            for (int e = 0; e < 4; ++e) {
                int co = mrow + mt * 16 + (lid >> 2) + ((e >> 1) << 3);
                int ci = ncol + j * 8 + (lid & 3) * 2 + (e & 1);
                dst[((b * 64 + co) * 64 + ci) * 25 + di * 5 + dj] = acc[mt][j][e];
            }
}

// ---------------------------------------------------------------------------
// Kernel C1: ak conv (VALID 3x3 over 5x5 attn), sums the 2 K-half partials.
// grid (16 cAg, 16 b), 256 thr = 4 cA x 64 cB (best-measured config).
// ---------------------------------------------------------------------------
__global__ void __launch_bounds__(256) akconv_kernel(const float* __restrict__ weight) {
    const int cAg = blockIdx.x;
    const int b   = blockIdx.y;
    const int tid = threadIdx.x;
    const int s  = tid >> 6;
    const int cB = tid & 63;
    const int cA = cAg * 4 + s;

    __shared__ float as4[4][64][25];
    __shared__ float ws[64][73];

    for (int t = tid; t < 6400; t += 256) {
        int a = t / 1600, r = t % 1600;
        long o = (long)(b * 64 + cAg * 4 + a) * 1600 + r;
        as4[a][r / 25][r % 25] = g_attnP[0][o] + g_attnP[1][o];
    }

    float acc[9];
#pragma unroll
    for (int t9 = 0; t9 < 9; ++t9) acc[t9] = 0.f;

    for (int cic = 0; cic < 8; ++cic) {
        __syncthreads();
        for (int t = tid; t < 4608; t += 256) {
            int c2 = t / 72;
            int rr = t % 72;
            ws[c2][rr] = weight[c2 * 576 + (cic * 8 + rr / 9) * 9 + (rr % 9)];
        }
        __syncthreads();
#pragma unroll
        for (int ci = 0; ci < 8; ++ci) {
            float av[25];
#pragma unroll
            for (int p = 0; p < 25; ++p) av[p] = as4[s][cic * 8 + ci][p];
#pragma unroll
            for (int dy = 0; dy < 3; ++dy)
#pragma unroll
                for (int dx = 0; dx < 3; ++dx) {
                    float wv = ws[cB][ci * 9 + dy * 3 + dx];
#pragma unroll
                    for (int ky = 0; ky < 3; ++ky)
#pragma unroll
                        for (int kx = 0; kx < 3; ++kx)
                            acc[ky * 3 + kx] =
                                fmaf(av[(ky + dy) * 5 + (kx + dx)], wv, acc[ky * 3 + kx]);
                }
        }
    }
#pragma unroll
    for (int t9 = 0; t9 < 9; ++t9)
        g_ak[((b * 64 + cB) * 64 + cA) * 9 + t9] = acc[t9];
}

// ---------------------------------------------------------------------------
// Kernel C2: normalize ak, build dynamic kernels -> single fp16 B tiles
// ---------------------------------------------------------------------------
__global__ void __launch_bounds__(64) kern_kernel(const float* __restrict__ weight,
                                                  const float* __restrict__ temperature) {
    const int cB  = blockIdx.x;
    const int b   = blockIdx.y;
    const int tid = threadIdx.x;  // = cA

    const float* ak = g_ak + (b * 64 + cB) * 64 * 9;
    float v[9];
    float ss = 0.f;
#pragma unroll
    for (int t9 = 0; t9 < 9; ++t9) {
        v[t9] = ak[tid * 9 + t9];
        ss = fmaf(v[t9], v[t9], ss);
    }

    __shared__ float red[64];
    red[tid] = ss;
    __syncthreads();
#pragma unroll
    for (int s = 32; s >= 1; s >>= 1) {
        if (tid < s) red[tid] += red[tid + s];
        __syncthreads();
    }
    float nrm = sqrtf(red[0]);
    float scale = temperature[0] / fmaxf(nrm, 1e-12f);

#pragma unroll
    for (int t9 = 0; t9 < 9; ++t9) {
        float vv = weight[(cB * 64 + tid) * 9 + t9] + v[t9] * scale;
        g_kt[((b * 9 + t9) * 64 + cB) * 64 + tid] = __float2half(vv);
    }
}

// ---------------------------------------------------------------------------
// Kernel D: final conv via mma.sync, M=128 (4y x 32x), 128 threads.
// A = x_hi (single), B = kern (single). smem 42.5KB -> 5 CTAs/SM.
// ---------------------------------------------------------------------------
#define DA_HI  0
#define DB     26112
#define D_TOT  42496

__global__ void __launch_bounds__(128) final_mma_kernel(float* __restrict__ out) {
    extern __shared__ char smem[];
    const int xt = blockIdx.x, yp = blockIdx.y, b = blockIdx.z;
    const int x0 = xt * 32, y0 = yp * 4;
    const int tid = threadIdx.x, wid = tid >> 5, lid = tid & 31;
    const uint32_t sbase = smem_u32(smem);

    float acc[2][8][4];
#pragma unroll
    for (int mt = 0; mt < 2; ++mt)
#pragma unroll
        for (int j = 0; j < 8; ++j)
#pragma unroll
            for (int e = 0; e < 4; ++e) acc[mt][j][e] = 0.f;

    const int apart = lid >> 4;
    const int brow0 = (lid & 7) + ((lid >> 4) << 3);
    const int bpart = (lid >> 3) & 1;
    int hra[2];
#pragma unroll
    for (int mt = 0; mt < 2; ++mt) {
        int m = wid * 32 + mt * 16 + (lid & 15);
        hra[mt] = ((m >> 5) + 1) * 34 + (m & 31) + 1;
    }

    auto prefetchB = [&](int tap, int bi) {
        uint32_t sb = sbase + DB + (uint32_t)bi * 8192u;
        const uint4* kp = (const uint4*)g_kt + (b * 9 + tap) * 512;
#pragma unroll
        for (int u = 0; u < 4; ++u) {
            int idx = tid + u * 128;
            int row = idx >> 3, c = idx & 7;
            uint32_t off = (uint32_t)row * 128u + (uint32_t)((c ^ (row & 7)) << 4);
            CP16(sb + off, kp + idx);
        }
    };

    // ---- one-time A halo fill (204 rows = 6y x 34x) + B tap0 ----
    for (int hr = tid; hr < 204; hr += 128) {
        int hy = hr / 34, hx = hr % 34;
        int y = y0 - 1 + hy, xg = x0 - 1 + hx;
        bool ok = ((unsigned)y < (unsigned)H_) && ((unsigned)xg < (unsigned)W_);
        long base = ((long)(b * 192 + y) * 192 + xg) * 8;
        const uint4* sh = (const uint4*)g_x_hi + base;
        const uint4 z = make_uint4(0, 0, 0, 0);
#pragma unroll
        for (int c = 0; c < 8; ++c) {
            uint32_t off = (uint32_t)hr * 128u + (uint32_t)((c ^ (hr & 7)) << 4);
            if (ok) {
                CP16(sbase + DA_HI + off, sh + c);
            } else {
                *(uint4*)(smem + DA_HI + off) = z;
            }
        }
    }
    prefetchB(0, 0);
    CP_COMMIT();
    CP_WAIT(0);
    __syncthreads();

    for (int tap = 0; tap < 9; ++tap) {
        if (tap < 8) {
            prefetchB(tap + 1, (tap + 1) & 1);
            CP_COMMIT();
        }

        const int dOff = (tap / 3 - 1) * 34 + (tap % 3 - 1);
        const uint32_t sbh = sbase + DB + (uint32_t)(tap & 1) * 8192u;

#pragma unroll
        for (int kc = 0; kc < 4; ++kc) {
            const int acol = kc * 2 + apart;
            const int bcol = kc * 2 + bpart;
            uint32_t bf[4][4], ah[2][4];
#pragma unroll
            for (int nt = 0; nt < 4; ++nt) {
                int row = brow0 + nt * 16;
                ldsm_x4(bf[nt], sbh + row * 128 + ((bcol ^ (row & 7)) << 4));
            }
#pragma unroll
            for (int mt = 0; mt < 2; ++mt) {
                int hr = hra[mt] + dOff;
                uint32_t off = (uint32_t)hr * 128u + (uint32_t)((acol ^ (hr & 7)) << 4);
                ldsm_x4(ah[mt], sbase + DA_HI + off);
            }
#pragma unroll
            for (int mt = 0; mt < 2; ++mt)
#pragma unroll
                for (int j = 0; j < 8; ++j)
                    mma_fp16(acc[mt][j], ah[mt], &bf[j >> 1][2 * (j & 1)]);
        }
        CP_WAIT(0);
        __syncthreads();
    }

    // epilogue: stage fp32 [m][oc] (stride 65, reuse A region), coalesced store
    float* st = (float*)smem;
#pragma unroll
    for (int mt = 0; mt < 2; ++mt)
#pragma unroll
        for (int j = 0; j < 8; ++j)
#pragma unroll
            for (int e = 0; e < 4; ++e) {
                int row = wid * 32 + mt * 16 + (lid >> 2) + ((e >> 1) << 3);
                int col = j * 8 + (lid & 3) * 2 + (e & 1);
                st[row * 65 + col] = acc[mt][j][e];
            }
    __syncthreads();

    for (int t = tid; t < 8192; t += 128) {
        int oc = t >> 7, m = t & 127;
        float v = fmaxf(st[m * 65 + oc], 0.f);
        out[((long)(b * 64 + oc) * 192 + (y0 + (m >> 5))) * 192 + x0 + (m & 31)] = v;
    }
}

// ---------------------------------------------------------------------------
// Launch
// ---------------------------------------------------------------------------
extern "C" void kernel_launch(void* const* d_in, const int* in_sizes, int n_in,
                              void* d_out, int out_size) {
    const float* x    = (const float*)d_in[0];  // (16,64,192,192)
    const float* w_qk = (const float*)d_in[1];  // (128,64,3,3)
    const float* wgt  = (const float*)d_in[2];  // (64,64,3,3)
    const float* temp = (const float*)d_in[3];  // (1,1,1)
    float* out = (float*)d_out;                 // (16,64,192,192)

    cudaFuncSetAttribute(qk_mma_kernel, cudaFuncAttributeMaxDynamicSharedMemorySize, QK_TOT);
    cudaFuncSetAttribute(attn_mma_kernel, cudaFuncAttributeMaxDynamicSharedMemorySize, AT_TOT);
    cudaFuncSetAttribute(final_mma_kernel, cudaFuncAttributeMaxDynamicSharedMemorySize, D_TOT);

    xcl_kernel<<<dim3(576, 17), 256>>>(x, w_qk);               // 0
    qk_mma_kernel<<<dim3(32, 2, 16), 128, QK_TOT>>>();         // 1
    attn_mma_kernel<<<dim3(25, 2, 16), 128, AT_TOT>>>();       // 2
    akconv_kernel<<<dim3(16, 16), 256>>>(wgt);                 // 3
    kern_kernel<<<dim3(64, 16), 64>>>(wgt, temp);              // 4
    final_mma_kernel<<<dim3(6, 48, 16), 128, D_TOT>>>(out);    // 5 (ncu slot)
}

// round 15
// speedup vs baseline: 10.1058x; 1.1910x over previous
#include <cuda_runtime.h>
#include <cuda_fp16.h>
#include <cstdint>
#include <math.h>

// Problem constants
#define B_  16
#define C_  64
#define H_  192
#define W_  192
#define H2_ 64
#define W2_ 64
#define S_  5

// ---------------------------------------------------------------------------
// Scratch buffers (static device globals; zero-initialized at load)
// ---------------------------------------------------------------------------
__device__ float g_attnP[2][B_ * C_ * C_ * S_ * S_];  // 2 K-half partials
__device__ float g_ak[B_ * C_ * C_ * 9];              // transposed ak (pre-norm)

// fp16 operands (all single precision now; fp32 staging between stages).
__device__ __align__(16) __half g_x_hi[B_ * H_ * W_ * C_];  // channel-last
__device__ __align__(16) __half g_kt[B_ * 9 * C_ * C_];     // [b][tap][oc][ci]
__device__ __align__(16) __half g_wq[2 * 9 * 64 * 64];      // [half][tap][oc][ci]
// attn A operand: k channel-major [b][co][4096]
__device__ __align__(16) __half g_k1[B_ * C_ * 4096];
// attn B operand: q shifted copies [dj(5)][b][ci][68 rows (zero-pad)][64]
__device__ __align__(16) __half g_q5[5 * B_ * C_ * 68 * 64];

__device__ __forceinline__ uint32_t smem_u32(const void* p) {
    uint32_t a;
    asm("{ .reg .u64 t; cvta.to.shared.u64 t, %1; cvt.u32.u64 %0, t; }" : "=r"(a) : "l"(p));
    return a;
}

__device__ __forceinline__ void ldsm_x4(uint32_t* r, uint32_t addr) {
    asm volatile("ldmatrix.sync.aligned.m8n8.x4.shared.b16 {%0,%1,%2,%3}, [%4];"
                 : "=r"(r[0]), "=r"(r[1]), "=r"(r[2]), "=r"(r[3])
                 : "r"(addr));
}

// mma.sync m16n8k16 fp16 -> fp32 accum (in-place)
__device__ __forceinline__ void mma_fp16(float* d, const uint32_t* a, const uint32_t* b) {
    asm volatile(
        "mma.sync.aligned.m16n8k16.row.col.f32.f16.f16.f32 "
        "{%0,%1,%2,%3}, {%4,%5,%6,%7}, {%8,%9}, {%0,%1,%2,%3};"
        : "+f"(d[0]), "+f"(d[1]), "+f"(d[2]), "+f"(d[3])
        : "r"(a[0]), "r"(a[1]), "r"(a[2]), "r"(a[3]), "r"(b[0]), "r"(b[1]));
}

#define CP16(dst, src) \
    asm volatile("cp.async.cg.shared.global [%0], [%1], 16;" ::"r"(dst), "l"(src))
#define CP_COMMIT() asm volatile("cp.async.commit_group;" ::: "memory")
#define CP_WAIT(N) asm volatile("cp.async.wait_group %0;" ::"n"(N) : "memory")

// ---------------------------------------------------------------------------
// Kernel E0: x (fp32 NCHW) -> channel-last fp16 (single); b==16 repacks w_qk.
// ---------------------------------------------------------------------------
__global__ void __launch_bounds__(256) xcl_kernel(const float* __restrict__ x,
                                                  const float* __restrict__ w_qk) {
    const int seg = blockIdx.x;
    const int b = blockIdx.y;
    const int tid = threadIdx.x;

    if (b == 16) {
        if (seg < 128) {
            const int half = seg >> 6, oc = seg & 63;
            for (int t = tid; t < 576; t += 256) {
                int ci = t / 9, tap = t % 9;
                g_wq[((half * 9 + tap) * 64 + oc) * 64 + ci] =
                    __float2half(w_qk[(seg * 64 + ci) * 9 + tap]);
            }
        }
        return;
    }

    const int y = seg / 3;
    const int x0 = (seg % 3) * 64;
    __shared__ float s[64][65];

#pragma unroll
    for (int i = 0; i < 16; ++i) {
        int idx = tid + i * 256;
        int c = idx >> 6, p = idx & 63;
        s[p][c] = x[((b * 64 + c) * 192 + y) * 192 + x0 + p];
    }
    __syncthreads();
#pragma unroll
    for (int i = 0; i < 16; ++i) {
        int idx = tid + i * 256;
        int p = idx >> 6, c = idx & 63;
        g_x_hi[((b * 192 + y) * 192 + x0 + p) * 64 + c] = __float2half(s[p][c]);
    }
}

// ---------------------------------------------------------------------------
// Kernel A: qk conv via mma.sync (stride-3), cp.async tap double-buffer.
// A = x (single fp16), B = w_qk (single fp16). 1 mma term.
// FUSED epilogue: k -> g_k1, q -> g_q5 (5 dj copies).
// grid (32 mtiles, 2 half, 16 b), 128 thr. smem 2 x 24KB.
// ---------------------------------------------------------------------------
#define QK_B    16384
#define QK_BUF  24576
#define QK_TOT  49152

__global__ void __launch_bounds__(128) qk_mma_kernel() {
    extern __shared__ char smem[];
    const int mtile = blockIdx.x, half = blockIdx.y, b = blockIdx.z;
    const int i0 = mtile * 2;
    const int tid = threadIdx.x, wid = tid >> 5, lid = tid & 31;
    const uint32_t sbase = smem_u32(smem);

    const int r = tid;
    const int ri = i0 + (r >> 6), rj = r & 63;

    float acc[2][8][4];
#pragma unroll
    for (int mt = 0; mt < 2; ++mt)
#pragma unroll
        for (int j = 0; j < 8; ++j)
#pragma unroll
            for (int e = 0; e < 4; ++e) acc[mt][j][e] = 0.f;

    const int arow0 = wid * 32 + (lid & 15);
    const int apart = lid >> 4;
    const int brow0 = (lid & 7) + ((lid >> 4) << 3);
    const int bpart = (lid >> 3) & 1;

    auto prefetch = [&](int tap, int bi) {
        uint32_t sb = sbase + (uint32_t)bi * QK_BUF;
        const int dy = tap / 3, dx = tap % 3;
        long abase = ((long)(b * 192 + 3 * ri + dy) * 192 + 3 * rj + dx) * 8;
        const uint4* sh = (const uint4*)g_x_hi + abase;
#pragma unroll
        for (int c = 0; c < 8; ++c) {
            uint32_t off = (uint32_t)r * 128u + (uint32_t)((c ^ (r & 7)) << 4);
            CP16(sb + off, sh + c);
        }
        const uint4* wp = (const uint4*)g_wq + (half * 9 + tap) * 512;
#pragma unroll
        for (int i = 0; i < 4; ++i) {
            int idx = tid + i * 128;
            int row = idx >> 3, c = idx & 7;
            uint32_t off = (uint32_t)row * 128u + (uint32_t)((c ^ (row & 7)) << 4);
            CP16(sb + QK_B + off, wp + idx);
        }
    };

    prefetch(0, 0);
    CP_COMMIT();

    for (int tap = 0; tap < 9; ++tap) {
        if (tap < 8) {
            prefetch(tap + 1, (tap + 1) & 1);
            CP_COMMIT();
            CP_WAIT(1);
        } else {
            CP_WAIT(0);
        }
        __syncthreads();

        const uint32_t sb = sbase + (uint32_t)(tap & 1) * QK_BUF;
#pragma unroll
        for (int kc = 0; kc < 4; ++kc) {
            const int acol = kc * 2 + apart;
            const int bcol = kc * 2 + bpart;
            uint32_t bf[4][4], ah[2][4];
#pragma unroll
            for (int nt = 0; nt < 4; ++nt) {
                int row = brow0 + nt * 16;
                ldsm_x4(bf[nt], sb + QK_B + row * 128 + ((bcol ^ (row & 7)) << 4));
            }
#pragma unroll
            for (int mt = 0; mt < 2; ++mt) {
                int row = arow0 + mt * 16;
                ldsm_x4(ah[mt], sb + row * 128 + ((acol ^ (row & 7)) << 4));
            }
#pragma unroll
            for (int mt = 0; mt < 2; ++mt)
#pragma unroll
                for (int j = 0; j < 8; ++j)
                    mma_fp16(acc[mt][j], ah[mt], &bf[j >> 1][2 * (j & 1)]);
        }
        __syncthreads();
    }

    // ---- fused epilogue: stage fp32 [m][ch] (stride 65), emit fp16 operands
    float* st = (float*)smem;
#pragma unroll
    for (int mt = 0; mt < 2; ++mt)
#pragma unroll
        for (int j = 0; j < 8; ++j)
#pragma unroll
            for (int e = 0; e < 4; ++e) {
                int m = wid * 32 + mt * 16 + (lid >> 2) + ((e >> 1) << 3);
                int col = j * 8 + (lid & 3) * 2 + (e & 1);
                st[m * 65 + col] = acc[mt][j][e];
            }
    __syncthreads();

    if (half) {
        // k: channel-major single fp16
        for (int t = tid; t < 8192; t += 128) {
            int co = t >> 7, m = t & 127;
            int h = i0 + (m >> 6), w = m & 63;
            long o = (long)(b * 64 + co) * 4096 + h * 64 + w;
            g_k1[o] = __float2half(st[m * 65 + co]);
        }
    } else {
        // q: 5 dj-shifted padded copies, single fp16
        for (int dj = 0; dj < 5; ++dj) {
            for (int t = tid; t < 8192; t += 128) {
                int ci = t >> 7, m = t & 127;
                int h = i0 + (m >> 6), w = m & 63;
                int wsrc = w + dj - 2;
                float v = ((unsigned)wsrc < 64u) ? st[((m >> 6) * 64 + wsrc) * 65 + ci] : 0.f;
                long o = (((long)(dj * 16 + b) * 64 + ci) * 68 + (h + 2)) * 64 + w;
                g_q5[o] = __float2half(v);
            }
        }
    }
}

// ---------------------------------------------------------------------------
// Kernel B: attn via mma.sync, K SPLIT IN 2. A = k, B = q (both single fp16).
// grid (25, 2, 16), 128 thr. smem 2 x 16KB.
// ---------------------------------------------------------------------------
#define AT_Q   8192
#define AT_BUF 16384
#define AT_TOT 32768

__global__ void __launch_bounds__(128) attn_mma_kernel() {
    extern __shared__ char smem[];
    const int dj = blockIdx.x % 5, di = blockIdx.x / 5;
    const int half = blockIdx.y, b = blockIdx.z;
    const int tid = threadIdx.x, wid = tid >> 5, lid = tid & 31;
    const uint32_t sbase = smem_u32(smem);
    const int mrow = (wid & 1) * 32, ncol = (wid >> 1) * 32;

    float acc[2][4][4];
#pragma unroll
    for (int mt = 0; mt < 2; ++mt)
#pragma unroll
        for (int j = 0; j < 4; ++j)
#pragma unroll
            for (int e = 0; e < 4; ++e) acc[mt][j][e] = 0.f;

    const uint4* __restrict__ kp = (const uint4*)g_k1 + (long)b * 64 * 512;
    const uint4* __restrict__ qp = (const uint4*)g_q5 + (long)(dj * 16 + b) * 64 * 544 + di * 8;

    const int apart = lid >> 4;
    const int brow_l = (lid & 7) + ((lid >> 4) << 3);
    const int bpart = (lid >> 3) & 1;
    const int kc0 = half * 32;

    auto prefetch = [&](int kc, int bi) {
        uint32_t sb = sbase + (uint32_t)bi * AT_BUF;
#pragma unroll
        for (int a = 0; a < 2; ++a) {
            const uint4* gp = (a == 0) ? kp : qp;
            const int stride = (a == 0) ? 512 : 544;
#pragma unroll
            for (int u = 0; u < 4; ++u) {
                int idx = tid + u * 128;  // 0..511
                int row = idx >> 3, c = idx & 7;
                uint32_t off = (uint32_t)a * 8192u + (uint32_t)row * 128u +
                               (uint32_t)((c ^ (row & 7)) << 4);
                CP16(sb + off, gp + (long)row * stride + kc * 8 + c);
            }
        }
    };

    prefetch(kc0, 0);
    CP_COMMIT();

    for (int kc2 = 0; kc2 < 32; ++kc2) {
        if (kc2 < 31) {
            prefetch(kc0 + kc2 + 1, (kc2 + 1) & 1);
            CP_COMMIT();
            CP_WAIT(1);
        } else {
            CP_WAIT(0);
        }
        __syncthreads();

        const uint32_t sb = sbase + (uint32_t)(kc2 & 1) * AT_BUF;
#pragma unroll
        for (int kk = 0; kk < 4; ++kk) {
            uint32_t ah[2][4], bh[2][4];
            const int acol = kk * 2 + apart;
            const int bcol = kk * 2 + bpart;
#pragma unroll
            for (int mt = 0; mt < 2; ++mt) {
                int row = mrow + mt * 16 + (lid & 15);
                ldsm_x4(ah[mt], sb + row * 128 + ((acol ^ (row & 7)) << 4));
            }
#pragma unroll
            for (int nt = 0; nt < 2; ++nt) {
                int row = ncol + nt * 16 + brow_l;
                ldsm_x4(bh[nt], sb + AT_Q + row * 128 + ((bcol ^ (row & 7)) << 4));
            }
#pragma unroll
            for (int mt = 0; mt < 2; ++mt)
#pragma unroll
                for (int j = 0; j < 4; ++j)
                    mma_fp16(acc[mt][j], ah[mt], &bh[j >> 1][2 * (j & 1)]);
        }
        __syncthreads();
    }

    float* dst = g_attnP[half];
#pragma unroll
    for (int mt = 0; mt < 2; ++mt)
#pragma unroll
        for (int j = 0; j < 4; ++j)
#pragma unroll
            for (int e = 0; e < 4; ++e) {
                int co = mrow + mt * 16 + (lid >> 2) + ((e >> 1) << 3);
                int ci = ncol + j * 8 + (lid & 3) * 2 + (e & 1);
                dst[((b * 64 + co) * 64 + ci) * 25 + di * 5 + dj] = acc[mt][j][e];
            }
}

// ---------------------------------------------------------------------------
// Kernel C1: ak conv (VALID 3x3 over 5x5 attn), sums the 2 K-half partials.
// grid (16 cAg, 16 b), 256 thr = 4 cA x 64 cB (best-measured config).
// ---------------------------------------------------------------------------
__global__ void __launch_bounds__(256) akconv_kernel(const float* __restrict__ weight) {
    const int cAg = blockIdx.x;
    const int b   = blockIdx.y;
    const int tid = threadIdx.x;
    const int s  = tid >> 6;
    const int cB = tid & 63;
    const int cA = cAg * 4 + s;

    __shared__ float as4[4][64][25];
    __shared__ float ws[64][73];

    for (int t = tid; t < 6400; t += 256) {
        int a = t / 1600, r = t % 1600;
        long o = (long)(b * 64 + cAg * 4 + a) * 1600 + r;
        as4[a][r / 25][r % 25] = g_attnP[0][o] + g_attnP[1][o];
    }

    float acc[9];
#pragma unroll
    for (int t9 = 0; t9 < 9; ++t9) acc[t9] = 0.f;

    for (int cic = 0; cic < 8; ++cic) {
        __syncthreads();
        for (int t = tid; t < 4608; t += 256) {
            int c2 = t / 72;
            int rr = t % 72;
            ws[c2][rr] = weight[c2 * 576 + (cic * 8 + rr / 9) * 9 + (rr % 9)];
        }
        __syncthreads();
#pragma unroll
        for (int ci = 0; ci < 8; ++ci) {
            float av[25];
#pragma unroll
            for (int p = 0; p < 25; ++p) av[p] = as4[s][cic * 8 + ci][p];
#pragma unroll
            for (int dy = 0; dy < 3; ++dy)
#pragma unroll
                for (int dx = 0; dx < 3; ++dx) {
                    float wv = ws[cB][ci * 9 + dy * 3 + dx];
#pragma unroll
                    for (int ky = 0; ky < 3; ++ky)
#pragma unroll
                        for (int kx = 0; kx < 3; ++kx)
                            acc[ky * 3 + kx] =
                                fmaf(av[(ky + dy) * 5 + (kx + dx)], wv, acc[ky * 3 + kx]);
                }
        }
    }
#pragma unroll
    for (int t9 = 0; t9 < 9; ++t9)
        g_ak[((b * 64 + cB) * 64 + cA) * 9 + t9] = acc[t9];
}

// ---------------------------------------------------------------------------
// Kernel C2: normalize ak, build dynamic kernels -> single fp16 B tiles
// ---------------------------------------------------------------------------
__global__ void __launch_bounds__(64) kern_kernel(const float* __restrict__ weight,
                                                  const float* __restrict__ temperature) {
    const int cB  = blockIdx.x;
    const int b   = blockIdx.y;
    const int tid = threadIdx.x;  // = cA

    const float* ak = g_ak + (b * 64 + cB) * 64 * 9;
    float v[9];
    float ss = 0.f;
#pragma unroll
    for (int t9 = 0; t9 < 9; ++t9) {
        v[t9] = ak[tid * 9 + t9];
        ss = fmaf(v[t9], v[t9], ss);
    }

    __shared__ float red[64];
    red[tid] = ss;
    __syncthreads();
#pragma unroll
    for (int s = 32; s >= 1; s >>= 1) {
        if (tid < s) red[tid] += red[tid + s];
        __syncthreads();
    }
    float nrm = sqrtf(red[0]);
    float scale = temperature[0] / fmaxf(nrm, 1e-12f);

#pragma unroll
    for (int t9 = 0; t9 < 9; ++t9) {
        float vv = weight[(cB * 64 + tid) * 9 + t9] + v[t9] * scale;
        g_kt[((b * 9 + t9) * 64 + cB) * 64 + tid] = __float2half(vv);
    }
}

// ---------------------------------------------------------------------------
// Kernel D: final conv via mma.sync, M=128 (4y x 32x), 128 threads.
// A = x_hi (single), B = kern (single). smem 42.5KB -> 5 CTAs/SM.
// ---------------------------------------------------------------------------
#define DA_HI  0
#define DB     26112
#define D_TOT  42496

__global__ void __launch_bounds__(128) final_mma_kernel(float* __restrict__ out) {
    extern __shared__ char smem[];
    const int xt = blockIdx.x, yp = blockIdx.y, b = blockIdx.z;
    const int x0 = xt * 32, y0 = yp * 4;
    const int tid = threadIdx.x, wid = tid >> 5, lid = tid & 31;
    const uint32_t sbase = smem_u32(smem);

    float acc[2][8][4];
#pragma unroll
    for (int mt = 0; mt < 2; ++mt)
#pragma unroll
        for (int j = 0; j < 8; ++j)
#pragma unroll
            for (int e = 0; e < 4; ++e) acc[mt][j][e] = 0.f;

    const int apart = lid >> 4;
    const int brow0 = (lid & 7) + ((lid >> 4) << 3);
    const int bpart = (lid >> 3) & 1;
    int hra[2];
#pragma unroll
    for (int mt = 0; mt < 2; ++mt) {
        int m = wid * 32 + mt * 16 + (lid & 15);
        hra[mt] = ((m >> 5) + 1) * 34 + (m & 31) + 1;
    }

    auto prefetchB = [&](int tap, int bi) {
        uint32_t sb = sbase + DB + (uint32_t)bi * 8192u;
        const uint4* kp = (const uint4*)g_kt + (b * 9 + tap) * 512;
#pragma unroll
        for (int u = 0; u < 4; ++u) {
            int idx = tid + u * 128;
            int row = idx >> 3, c = idx & 7;
            uint32_t off = (uint32_t)row * 128u + (uint32_t)((c ^ (row & 7)) << 4);
            CP16(sb + off, kp + idx);
        }
    };

    // ---- one-time A halo fill (204 rows = 6y x 34x) + B tap0 ----
    for (int hr = tid; hr < 204; hr += 128) {
        int hy = hr / 34, hx = hr % 34;
        int y = y0 - 1 + hy, xg = x0 - 1 + hx;
        bool ok = ((unsigned)y < (unsigned)H_) && ((unsigned)xg < (unsigned)W_);
        long base = ((long)(b * 192 + y) * 192 + xg) * 8;
        const uint4* sh = (const uint4*)g_x_hi + base;
        const uint4 z = make_uint4(0, 0, 0, 0);
#pragma unroll
        for (int c = 0; c < 8; ++c) {
            uint32_t off = (uint32_t)hr * 128u + (uint32_t)((c ^ (hr & 7)) << 4);
            if (ok) {
                CP16(sbase + DA_HI + off, sh + c);
            } else {
                *(uint4*)(smem + DA_HI + off) = z;
            }
        }
    }
    prefetchB(0, 0);
    CP_COMMIT();
    CP_WAIT(0);
    __syncthreads();

    for (int tap = 0; tap < 9; ++tap) {
        if (tap < 8) {
            prefetchB(tap + 1, (tap + 1) & 1);
            CP_COMMIT();
        }

        const int dOff = (tap / 3 - 1) * 34 + (tap % 3 - 1);
        const uint32_t sbh = sbase + DB + (uint32_t)(tap & 1) * 8192u;

#pragma unroll
        for (int kc = 0; kc < 4; ++kc) {
            const int acol = kc * 2 + apart;
            const int bcol = kc * 2 + bpart;
            uint32_t bf[4][4], ah[2][4];
#pragma unroll
            for (int nt = 0; nt < 4; ++nt) {
                int row = brow0 + nt * 16;
                ldsm_x4(bf[nt], sbh + row * 128 + ((bcol ^ (row & 7)) << 4));
            }
#pragma unroll
            for (int mt = 0; mt < 2; ++mt) {
                int hr = hra[mt] + dOff;
                uint32_t off = (uint32_t)hr * 128u + (uint32_t)((acol ^ (hr & 7)) << 4);
                ldsm_x4(ah[mt], sbase + DA_HI + off);
            }
#pragma unroll
            for (int mt = 0; mt < 2; ++mt)
#pragma unroll
                for (int j = 0; j < 8; ++j)
                    mma_fp16(acc[mt][j], ah[mt], &bf[j >> 1][2 * (j & 1)]);
        }
        CP_WAIT(0);
        __syncthreads();
    }

    // epilogue: stage fp32 [m][oc] (stride 65, reuse A region), coalesced store
    float* st = (float*)smem;
#pragma unroll
    for (int mt = 0; mt < 2; ++mt)
#pragma unroll
        for (int j = 0; j < 8; ++j)
#pragma unroll
            for (int e = 0; e < 4; ++e) {
                int row = wid * 32 + mt * 16 + (lid >> 2) + ((e >> 1) << 3);
                int col = j * 8 + (lid & 3) * 2 + (e & 1);
                st[row * 65 + col] = acc[mt][j][e];
            }
    __syncthreads();

    for (int t = tid; t < 8192; t += 128) {
        int oc = t >> 7, m = t & 127;
        float v = fmaxf(st[m * 65 + oc], 0.f);
        out[((long)(b * 64 + oc) * 192 + (y0 + (m >> 5))) * 192 + x0 + (m & 31)] = v;
    }
}

// ---------------------------------------------------------------------------
// Launch
// ---------------------------------------------------------------------------
extern "C" void kernel_launch(void* const* d_in, const int* in_sizes, int n_in,
                              void* d_out, int out_size) {
    const float* x    = (const float*)d_in[0];  // (16,64,192,192)
    const float* w_qk = (const float*)d_in[1];  // (128,64,3,3)
    const float* wgt  = (const float*)d_in[2];  // (64,64,3,3)
    const float* temp = (const float*)d_in[3];  // (1,1,1)
    float* out = (float*)d_out;                 // (16,64,192,192)

    cudaFuncSetAttribute(qk_mma_kernel, cudaFuncAttributeMaxDynamicSharedMemorySize, QK_TOT);
    cudaFuncSetAttribute(attn_mma_kernel, cudaFuncAttributeMaxDynamicSharedMemorySize, AT_TOT);
    cudaFuncSetAttribute(final_mma_kernel, cudaFuncAttributeMaxDynamicSharedMemorySize, D_TOT);

    xcl_kernel<<<dim3(576, 17), 256>>>(x, w_qk);               // 0
    qk_mma_kernel<<<dim3(32, 2, 16), 128, QK_TOT>>>();         // 1
    attn_mma_kernel<<<dim3(25, 2, 16), 128, AT_TOT>>>();       // 2
    akconv_kernel<<<dim3(16, 16), 256>>>(wgt);                 // 3
    kern_kernel<<<dim3(64, 16), 64>>>(wgt, temp);              // 4
    final_mma_kernel<<<dim3(6, 48, 16), 128, D_TOT>>>(out);    // 5 (ncu slot)
}